// round 6
// baseline (speedup 1.0000x reference)
#include <cuda_runtime.h>
#include <cuda_bf16.h>
#include <cstdint>

// Problem constants
#define BB 4
#define SS 8192
#define DD 512
#define HH 8
#define HDIM 64
#define RR 64
#define BSROWS (BB * SS)      // 32768
#define NCHUNK 16

// -------- scratch (static device globals; no allocation) --------
__device__ float g_q[BSROWS * DD];
__device__ float g_k[BSROWS * DD];
__device__ float g_v[BSROWS * DD];
__device__ float g_phiq[BB * HH * SS * RR];
__device__ float g_phik[BB * HH * SS * RR];
__device__ float g_kvp[BB * HH * NCHUNK * RR * HDIM];
__device__ float g_ksp[BB * HH * NCHUNK * RR];
__device__ float g_kv[BB * HH * RR * HDIM];
__device__ float g_ks[BB * HH * RR];
__device__ __nv_bfloat16 g_xhi[BSROWS * DD];
__device__ __nv_bfloat16 g_xlo[BSROWS * DD];
__device__ __nv_bfloat16 g_ahi[BSROWS * DD];   // attn output hi
__device__ __nv_bfloat16 g_alo[BSROWS * DD];   // attn output lo
__device__ __nv_bfloat16 g_wthi[4 * DD * DD];  // [2048][512]: Wq^T,Wk^T,Wv^T,Wp^T
__device__ __nv_bfloat16 g_wtlo[4 * DD * DD];
__device__ float g_biasqkv[3 * DD];

// ============================================================
// helpers
// ============================================================
__device__ __forceinline__ uint32_t smem_to_u32(const void* p) {
    uint32_t a;
    asm("{ .reg .u64 t; cvta.to.shared.u64 t, %1; cvt.u32.u64 %0, t; }"
        : "=r"(a) : "l"(p));
    return a;
}
__device__ __forceinline__ void ldsm4(uint32_t& r0, uint32_t& r1,
                                      uint32_t& r2, uint32_t& r3,
                                      uint32_t addr) {
    asm volatile("ldmatrix.sync.aligned.m8n8.x4.shared.b16 {%0,%1,%2,%3}, [%4];"
                 : "=r"(r0), "=r"(r1), "=r"(r2), "=r"(r3) : "r"(addr));
}
__device__ __forceinline__ void mma16816(float* d, const uint32_t* a,
                                         const uint32_t* b) {
    asm volatile(
        "mma.sync.aligned.m16n8k16.row.col.f32.bf16.bf16.f32 "
        "{%0,%1,%2,%3}, {%4,%5,%6,%7}, {%8,%9}, {%0,%1,%2,%3};"
        : "+f"(d[0]), "+f"(d[1]), "+f"(d[2]), "+f"(d[3])
        : "r"(a[0]), "r"(a[1]), "r"(a[2]), "r"(a[3]), "r"(b[0]), "r"(b[1]));
}
#define CP_ASYNC16(dst, src) \
    asm volatile("cp.async.cg.shared.global [%0], [%1], 16;" :: "r"(dst), "l"(src))
#define CP_COMMIT() asm volatile("cp.async.commit_group;" ::: "memory")
#define CP_WAIT(n)  asm volatile("cp.async.wait_group %0;" :: "n"(n) : "memory")

__device__ __forceinline__ void split4(float4 v, uint2& hi, uint2& lo) {
    __nv_bfloat16 h0 = __float2bfloat16_rn(v.x), h1 = __float2bfloat16_rn(v.y);
    __nv_bfloat16 h2 = __float2bfloat16_rn(v.z), h3 = __float2bfloat16_rn(v.w);
    float r0 = v.x - __bfloat162float(h0), r1 = v.y - __bfloat162float(h1);
    float r2 = v.z - __bfloat162float(h2), r3 = v.w - __bfloat162float(h3);
    __nv_bfloat16 l0 = __float2bfloat16_rn(r0), l1 = __float2bfloat16_rn(r1);
    __nv_bfloat16 l2 = __float2bfloat16_rn(r2), l3 = __float2bfloat16_rn(r3);
    hi.x = ((uint32_t)__bfloat16_as_ushort(h1) << 16) | __bfloat16_as_ushort(h0);
    hi.y = ((uint32_t)__bfloat16_as_ushort(h3) << 16) | __bfloat16_as_ushort(h2);
    lo.x = ((uint32_t)__bfloat16_as_ushort(l1) << 16) | __bfloat16_as_ushort(l0);
    lo.y = ((uint32_t)__bfloat16_as_ushort(l3) << 16) | __bfloat16_as_ushort(l2);
}

// ============================================================
// prep kernels
// ============================================================
__global__ __launch_bounds__(256) void split_fp32(
    const float* __restrict__ X, __nv_bfloat16* __restrict__ Xh,
    __nv_bfloat16* __restrict__ Xl)
{
    int i = blockIdx.x * 256 + threadIdx.x;   // over float4s
    float4 v = ((const float4*)X)[i];
    uint2 hi, lo;
    split4(v, hi, lo);
    ((uint2*)Xh)[i] = hi;
    ((uint2*)Xl)[i] = lo;
}

// transpose + split: Th/Tl[rowoff + n][k] = split(W[k][n])
__global__ __launch_bounds__(256) void transpose_split(
    const float* __restrict__ W, __nv_bfloat16* __restrict__ Th,
    __nv_bfloat16* __restrict__ Tl, int rowoff)
{
    __shared__ float t[32][33];
    int bx = blockIdx.x * 32, by = blockIdx.y * 32;
    int x = threadIdx.x & 31, y = threadIdx.x >> 5;
    for (int i = y; i < 32; i += 8) t[i][x] = W[(size_t)(by + i) * DD + bx + x];
    __syncthreads();
    for (int i = y; i < 32; i += 8) {
        float v = t[x][i];
        __nv_bfloat16 h = __float2bfloat16_rn(v);
        __nv_bfloat16 l = __float2bfloat16_rn(v - __bfloat162float(h));
        size_t o = (size_t)(rowoff + bx + i) * DD + by + x;
        Th[o] = h;
        Tl[o] = l;
    }
}

__global__ void concat_bias(const float* bq, const float* bk, const float* bv,
                            float* bout)
{
    int i = blockIdx.x * 256 + threadIdx.x;
    if (i < DD) bout[i] = bq[i];
    else if (i < 2 * DD) bout[i] = bk[i - DD];
    else if (i < 3 * DD) bout[i] = bv[i - 2 * DD];
}

// ============================================================
// Tensor-core bf16 3-pass split GEMM, cp.async 3-stage pipeline.
// CTA tile 128x256, 8 warps (2m x 4n), warp tile 64x64.
// smem rows padded to 80B -> conflict-free ldmatrix.
// Output select: sel = bn>>1; column base = (bn&1)*256.
// ============================================================
#define BKC 32
#define NKCH (DD / BKC)          // 16
#define ROWB 80
#define TILE_A (128 * ROWB)      // 10240
#define TILE_B (256 * ROWB)      // 20480
#define ST_AHI 0
#define ST_ALO TILE_A
#define ST_BHI (2 * TILE_A)
#define ST_BLO (2 * TILE_A + TILE_B)
#define STAGEB (2 * TILE_A + 2 * TILE_B)   // 61440
#define PIPE 3
#define GEMM_SMEM (PIPE * STAGEB)          // 184320
#define OFF80(row, ch) ((uint32_t)((row) * ROWB + ((ch) << 4)))

__global__ __launch_bounds__(256, 1) void mma_gemm(
    const __nv_bfloat16* __restrict__ Ahi, const __nv_bfloat16* __restrict__ Alo,
    const __nv_bfloat16* __restrict__ Bhi, const __nv_bfloat16* __restrict__ Blo,
    const float* __restrict__ bias,
    float* __restrict__ o0, float* __restrict__ o1, float* __restrict__ o2)
{
    extern __shared__ char smem[];
    const uint32_t sb = smem_to_u32(smem);

    const int tid = threadIdx.x;
    const int wid = tid >> 5, lane = tid & 31;
    const int bn = blockIdx.x, bm = blockIdx.y;
    const int warp_m = wid & 1, warp_n = wid >> 1;

    const __nv_bfloat16* Ahi_b = Ahi + (size_t)bm * 128 * DD;
    const __nv_bfloat16* Alo_b = Alo + (size_t)bm * 128 * DD;
    const __nv_bfloat16* Bhi_b = Bhi + (size_t)bn * 256 * DD;
    const __nv_bfloat16* Blo_b = Blo + (size_t)bn * 256 * DD;

    // loader: row = tid>>2 (0..63), ch = tid&3
    const int lrow = tid >> 2;
    const int lch = tid & 3;

    auto load_chunk = [&](int c, int s) {
        const uint32_t stg = sb + s * STAGEB;
        const int k0 = c * BKC;
#pragma unroll
        for (int sw = 0; sw < 2; sw++) {
            const int row = sw * 64 + lrow;
            const size_t go = (size_t)row * DD + k0 + lch * 8;
            const uint32_t so = OFF80(row, lch);
            CP_ASYNC16(stg + ST_AHI + so, Ahi_b + go);
            CP_ASYNC16(stg + ST_ALO + so, Alo_b + go);
        }
#pragma unroll
        for (int sw = 0; sw < 4; sw++) {
            const int row = sw * 64 + lrow;
            const size_t go = (size_t)row * DD + k0 + lch * 8;
            const uint32_t so = OFF80(row, lch);
            CP_ASYNC16(stg + ST_BHI + so, Bhi_b + go);
            CP_ASYNC16(stg + ST_BLO + so, Blo_b + go);
        }
    };

    float acc[4][8][4];
#pragma unroll
    for (int i = 0; i < 4; i++)
#pragma unroll
        for (int j = 0; j < 8; j++)
#pragma unroll
            for (int e = 0; e < 4; e++) acc[i][j][e] = 0.f;

    // ldmatrix lane-address components
    const int mat = lane >> 3, mr = lane & 7;
    const int a_row_b = warp_m * 64 + (mat & 1) * 8 + mr;   // + im*16
    const int b_row_b = warp_n * 64 + (mat & 1) * 8 + mr;   // + j16*16
    const int mchunk = mat >> 1;                            // + kk*2

    load_chunk(0, 0);
    CP_COMMIT();
    load_chunk(1, 1);
    CP_COMMIT();

    for (int c = 0; c < NKCH; c++) {
        CP_WAIT(1);
        __syncthreads();
        if (c + 2 < NKCH) {
            load_chunk(c + 2, (c + 2) % PIPE);
            CP_COMMIT();
        }

        const uint32_t stg = sb + (c % PIPE) * STAGEB;
#pragma unroll
        for (int kk = 0; kk < 2; kk++) {
            const int ch = kk * 2 + mchunk;
            uint32_t ahi[4][4], alo[4][4];
#pragma unroll
            for (int im = 0; im < 4; im++) {
                const int row = a_row_b + im * 16;
                ldsm4(ahi[im][0], ahi[im][1], ahi[im][2], ahi[im][3],
                      stg + ST_AHI + OFF80(row, ch));
                ldsm4(alo[im][0], alo[im][1], alo[im][2], alo[im][3],
                      stg + ST_ALO + OFF80(row, ch));
            }
#pragma unroll
            for (int j16 = 0; j16 < 4; j16++) {
                const int row = b_row_b + j16 * 16;
                uint32_t h0, h1, h2, h3, l0, l1, l2, l3;
                ldsm4(h0, h1, h2, h3, stg + ST_BHI + OFF80(row, ch));
                ldsm4(l0, l1, l2, l3, stg + ST_BLO + OFF80(row, ch));
                uint32_t bh0[2] = {h0, h2}, bh1[2] = {h1, h3};
                uint32_t bl0[2] = {l0, l2}, bl1[2] = {l1, l3};
#pragma unroll
                for (int im = 0; im < 4; im++) {
                    mma16816(acc[im][j16 * 2], ahi[im], bh0);
                    mma16816(acc[im][j16 * 2], ahi[im], bl0);
                    mma16816(acc[im][j16 * 2], alo[im], bh0);
                    mma16816(acc[im][j16 * 2 + 1], ahi[im], bh1);
                    mma16816(acc[im][j16 * 2 + 1], ahi[im], bl1);
                    mma16816(acc[im][j16 * 2 + 1], alo[im], bh1);
                }
            }
        }
    }

    // ---- epilogue ----
    const int sel = bn >> 1;
    float* C = sel == 0 ? o0 : (sel == 1 ? o1 : o2);
    const int colbase = (bn & 1) * 256;
    const int erow = lane >> 2, ecol = (lane & 3) * 2;
#pragma unroll
    for (int im = 0; im < 4; im++) {
        const size_t row0 = (size_t)bm * 128 + warp_m * 64 + im * 16 + erow;
#pragma unroll
        for (int t = 0; t < 8; t++) {
            const int cofs = warp_n * 64 + t * 8 + ecol;
            float2 b2 = *(const float2*)&bias[bn * 256 + cofs];
            float2 q0 = make_float2(acc[im][t][0] + b2.x, acc[im][t][1] + b2.y);
            float2 q1 = make_float2(acc[im][t][2] + b2.x, acc[im][t][3] + b2.y);
            *(float2*)&C[row0 * DD + colbase + cofs] = q0;
            *(float2*)&C[(row0 + 8) * DD + colbase + cofs] = q1;
        }
    }
}

// ============================================================
// Sketch: z = gamma*Z + beta; u=z@G1, w=z@G2, phi=((1/8)u*w)^2
// ============================================================
__global__ __launch_bounds__(256) void sketch_kernel(
    const float* __restrict__ Z,
    const float* __restrict__ G1, const float* __restrict__ G2,
    const float* __restrict__ gamma, const float* __restrict__ beta,
    float* __restrict__ phi)
{
    __shared__ float Zs[64][64];
    __shared__ float G1s[64 * 64];
    __shared__ float G2s[64 * 64];

    const int tid = threadIdx.x;
    const int h = blockIdx.y;
    const int row0 = blockIdx.x * 64;

    for (int i = tid; i < 1024; i += 256) {
        ((float4*)G1s)[i] = ((const float4*)G1)[i];
        ((float4*)G2s)[i] = ((const float4*)G2)[i];
    }
    const float g0 = gamma[0], b0 = beta[0];
    for (int i = tid; i < 1024; i += 256) {
        int r = i >> 4;
        int c4 = (i & 15) * 4;
        float4 z = *(const float4*)&Z[(size_t)(row0 + r) * DD + h * HDIM + c4];
        z.x = g0 * z.x + b0;
        z.y = g0 * z.y + b0;
        z.z = g0 * z.z + b0;
        z.w = g0 * z.w + b0;
        *(float4*)&Zs[r][c4] = z;
    }
    __syncthreads();

    const int tr = tid >> 4, tc = tid & 15;
    const int r0 = tr * 4, c0 = tc * 4;
    float au[4][4], aw[4][4];
#pragma unroll
    for (int i = 0; i < 4; i++)
#pragma unroll
        for (int j = 0; j < 4; j++) { au[i][j] = 0.f; aw[i][j] = 0.f; }

#pragma unroll 8
    for (int hd = 0; hd < 64; hd++) {
        float4 g1 = *(float4*)&G1s[hd * 64 + c0];
        float4 g2 = *(float4*)&G2s[hd * 64 + c0];
#pragma unroll
        for (int i = 0; i < 4; i++) {
            float z = Zs[r0 + i][hd];
            au[i][0] += z * g1.x; au[i][1] += z * g1.y;
            au[i][2] += z * g1.z; au[i][3] += z * g1.w;
            aw[i][0] += z * g2.x; aw[i][1] += z * g2.y;
            aw[i][2] += z * g2.z; aw[i][3] += z * g2.w;
        }
    }

    const int b = row0 / SS;
    const int sbase = row0 % SS;
    const float inv = 0.125f;
#pragma unroll
    for (int i = 0; i < 4; i++) {
        int s = sbase + r0 + i;
        float h0 = inv * au[i][0] * aw[i][0];
        float h1 = inv * au[i][1] * aw[i][1];
        float h2 = inv * au[i][2] * aw[i][2];
        float h3 = inv * au[i][3] * aw[i][3];
        float4 o = make_float4(h0 * h0, h1 * h1, h2 * h2, h3 * h3);
        *(float4*)&phi[(((size_t)b * HH + h) * SS + s) * RR + c0] = o;
    }
}

// ============================================================
// kv partial sums over S chunks
// ============================================================
__global__ __launch_bounds__(256) void kvsum_kernel(
    const float* __restrict__ phik, const float* __restrict__ v,
    float* __restrict__ kvp, float* __restrict__ ksp)
{
    const int bh = blockIdx.y;
    const int chunk = blockIdx.x;
    const int b = bh >> 3, h = bh & 7;
    const int CS = SS / NCHUNK;

    __shared__ float Ps[32][64];
    __shared__ float Vs[32][64];

    const int tid = threadIdx.x;
    const int tr = tid >> 4, tc = tid & 15;
    const int r0 = tr * 4, d0 = tc * 4;

    float acc[4][4];
#pragma unroll
    for (int i = 0; i < 4; i++)
#pragma unroll
        for (int j = 0; j < 4; j++) acc[i][j] = 0.f;
    float ks = 0.f;

    const int s0 = chunk * CS;
    for (int st = 0; st < CS; st += 32) {
        for (int i = tid; i < 512; i += 256) {
            int row = i >> 4;
            int c4 = (i & 15) * 4;
            *(float4*)&Ps[row][c4] =
                *(const float4*)&phik[((size_t)bh * SS + s0 + st + row) * RR + c4];
            *(float4*)&Vs[row][c4] =
                *(const float4*)&v[((size_t)b * SS + s0 + st + row) * DD + h * HDIM + c4];
        }
        __syncthreads();
#pragma unroll 8
        for (int ss = 0; ss < 32; ss++) {
            float4 p = *(float4*)&Ps[ss][r0];
            float4 vv = *(float4*)&Vs[ss][d0];
            acc[0][0] += p.x * vv.x; acc[0][1] += p.x * vv.y;
            acc[0][2] += p.x * vv.z; acc[0][3] += p.x * vv.w;
            acc[1][0] += p.y * vv.x; acc[1][1] += p.y * vv.y;
            acc[1][2] += p.y * vv.z; acc[1][3] += p.y * vv.w;
            acc[2][0] += p.z * vv.x; acc[2][1] += p.z * vv.y;
            acc[2][2] += p.z * vv.z; acc[2][3] += p.z * vv.w;
            acc[3][0] += p.w * vv.x; acc[3][1] += p.w * vv.y;
            acc[3][2] += p.w * vv.z; acc[3][3] += p.w * vv.w;
        }
        if (tid < 64) {
#pragma unroll
            for (int ss = 0; ss < 32; ss++) ks += Ps[ss][tid];
        }
        __syncthreads();
    }

    float* kvout = kvp + ((size_t)bh * NCHUNK + chunk) * (RR * HDIM);
#pragma unroll
    for (int i = 0; i < 4; i++)
        *(float4*)&kvout[(r0 + i) * HDIM + d0] =
            make_float4(acc[i][0], acc[i][1], acc[i][2], acc[i][3]);
    if (tid < 64) ksp[((size_t)bh * NCHUNK + chunk) * RR + tid] = ks;
}

__global__ void reduce_kernel(const float* __restrict__ kvp,
                              const float* __restrict__ ksp,
                              float* __restrict__ kv, float* __restrict__ ks)
{
    const int idx = blockIdx.x * 256 + threadIdx.x;
    const int total_kv = BB * HH * RR * HDIM;
    if (idx < total_kv) {
        int bh = idx >> 12, e = idx & 4095;
        float s = 0.f;
#pragma unroll
        for (int c = 0; c < NCHUNK; c++)
            s += kvp[((size_t)bh * NCHUNK + c) * 4096 + e];
        kv[idx] = s;
    } else if (idx < total_kv + BB * HH * RR) {
        int j = idx - total_kv;
        int bh = j >> 6, r = j & 63;
        float s = 0.f;
#pragma unroll
        for (int c = 0; c < NCHUNK; c++)
            s += ksp[((size_t)bh * NCHUNK + c) * RR + r];
        ks[j] = s;
    }
}

// ============================================================
// attn output -> split bf16 hi/lo (feeds final GEMM directly)
// ============================================================
__global__ __launch_bounds__(256) void attn_out_kernel(
    const float* __restrict__ phiq, const float* __restrict__ kv,
    const float* __restrict__ ks,
    __nv_bfloat16* __restrict__ ahi, __nv_bfloat16* __restrict__ alo)
{
    const int bh = blockIdx.y;
    const int stile = blockIdx.x;
    const int b = bh >> 3, h = bh & 7;

    __shared__ float KVs[4096];
    __shared__ float KSs[64];
    __shared__ float Ps[32 * 65];
    __shared__ float Dens[32];

    const int tid = threadIdx.x;
    const int s0 = stile * 32;

    for (int i = tid; i < 1024; i += 256)
        ((float4*)KVs)[i] = ((const float4*)(kv + (size_t)bh * 4096))[i];
    if (tid < 64) KSs[tid] = ks[bh * RR + tid];
    for (int i = tid; i < 2048; i += 256) {
        int row = i >> 6, c = i & 63;
        Ps[row * 65 + c] = phiq[((size_t)bh * SS + s0 + row) * RR + c];
    }
    __syncthreads();

    if (tid < 32) {
        float dsum = 0.f;
#pragma unroll
        for (int r = 0; r < 64; r++) dsum += Ps[tid * 65 + r] * KSs[r];
        Dens[tid] = dsum + 1e-6f;
    }
    __syncthreads();

    const int d = tid & 63, g = tid >> 6;
    for (int rr = g; rr < 32; rr += 4) {
        float num = 0.f;
#pragma unroll
        for (int r = 0; r < 64; r++) num += Ps[rr * 65 + r] * KVs[r * 64 + d];
        float o = num / Dens[rr];
        __nv_bfloat16 hi = __float2bfloat16_rn(o);
        __nv_bfloat16 lo = __float2bfloat16_rn(o - __bfloat162float(hi));
        size_t idx = ((size_t)b * SS + s0 + rr) * DD + h * HDIM + d;
        ahi[idx] = hi;
        alo[idx] = lo;
    }
}

// ============================================================
// launch
// ============================================================
extern "C" void kernel_launch(void* const* d_in, const int* in_sizes, int n_in,
                              void* d_out, int out_size)
{
    const float* x       = (const float*)d_in[0];
    const float* Wq      = (const float*)d_in[1];
    const float* bq      = (const float*)d_in[2];
    const float* Wk      = (const float*)d_in[3];
    const float* bk      = (const float*)d_in[4];
    const float* Wv      = (const float*)d_in[5];
    const float* bv      = (const float*)d_in[6];
    const float* Wp      = (const float*)d_in[7];
    const float* bp      = (const float*)d_in[8];
    const float* gamma_q = (const float*)d_in[9];
    const float* beta_q  = (const float*)d_in[10];
    const float* gamma_k = (const float*)d_in[11];
    const float* beta_k  = (const float*)d_in[12];
    const float* qG1     = (const float*)d_in[13];
    const float* qG2     = (const float*)d_in[14];
    const float* kG1     = (const float*)d_in[15];
    const float* kG2     = (const float*)d_in[16];
    float* out = (float*)d_out;

    float *p_q, *p_k, *p_v, *p_phiq, *p_phik, *p_kvp, *p_ksp, *p_kv, *p_ks, *p_bqkv;
    __nv_bfloat16 *p_xhi, *p_xlo, *p_ahi, *p_alo, *p_wthi, *p_wtlo;
    cudaGetSymbolAddress((void**)&p_q, g_q);
    cudaGetSymbolAddress((void**)&p_k, g_k);
    cudaGetSymbolAddress((void**)&p_v, g_v);
    cudaGetSymbolAddress((void**)&p_phiq, g_phiq);
    cudaGetSymbolAddress((void**)&p_phik, g_phik);
    cudaGetSymbolAddress((void**)&p_kvp, g_kvp);
    cudaGetSymbolAddress((void**)&p_ksp, g_ksp);
    cudaGetSymbolAddress((void**)&p_kv, g_kv);
    cudaGetSymbolAddress((void**)&p_ks, g_ks);
    cudaGetSymbolAddress((void**)&p_bqkv, g_biasqkv);
    cudaGetSymbolAddress((void**)&p_xhi, g_xhi);
    cudaGetSymbolAddress((void**)&p_xlo, g_xlo);
    cudaGetSymbolAddress((void**)&p_ahi, g_ahi);
    cudaGetSymbolAddress((void**)&p_alo, g_alo);
    cudaGetSymbolAddress((void**)&p_wthi, g_wthi);
    cudaGetSymbolAddress((void**)&p_wtlo, g_wtlo);

    cudaFuncSetAttribute(mma_gemm, cudaFuncAttributeMaxDynamicSharedMemorySize,
                         GEMM_SMEM);

    // ---- prep: split x; transpose+split weights; concat bias ----
    split_fp32<<<BSROWS * DD / 4 / 256, 256>>>(x, p_xhi, p_xlo);
    dim3 tg(16, 16);
    transpose_split<<<tg, 256>>>(Wq, p_wthi, p_wtlo, 0);
    transpose_split<<<tg, 256>>>(Wk, p_wthi, p_wtlo, 512);
    transpose_split<<<tg, 256>>>(Wv, p_wthi, p_wtlo, 1024);
    transpose_split<<<tg, 256>>>(Wp, p_wthi, p_wtlo, 1536);
    concat_bias<<<6, 256>>>(bq, bk, bv, p_bqkv);

    // ---- fused QKV GEMM: grid (6, 256), each CTA does 128x256 ----
    dim3 gq(6, BSROWS / 128);
    mma_gemm<<<gq, 256, GEMM_SMEM>>>(p_xhi, p_xlo, p_wthi, p_wtlo, p_bqkv,
                                     p_q, p_k, p_v);

    dim3 sk_grid(BSROWS / 64, HH);
    sketch_kernel<<<sk_grid, 256>>>(p_q, qG1, qG2, gamma_q, beta_q, p_phiq);
    sketch_kernel<<<sk_grid, 256>>>(p_k, kG1, kG2, gamma_k, beta_k, p_phik);

    kvsum_kernel<<<dim3(NCHUNK, BB * HH), 256>>>(p_phik, p_v, p_kvp, p_ksp);

    int red_total = BB * HH * RR * HDIM + BB * HH * RR;
    reduce_kernel<<<(red_total + 255) / 256, 256>>>(p_kvp, p_ksp, p_kv, p_ks);

    attn_out_kernel<<<dim3(SS / 32, BB * HH), 256>>>(p_phiq, p_kv, p_ks,
                                                     p_ahi, p_alo);

    // ---- output projection: grid (2, 256) ----
    dim3 go(2, BSROWS / 128);
    mma_gemm<<<go, 256, GEMM_SMEM>>>(p_ahi, p_alo,
                                     p_wthi + 1536 * DD, p_wtlo + 1536 * DD,
                                     bp, out, out, out);
}

// round 7
// speedup vs baseline: 1.0922x; 1.0922x over previous
#include <cuda_runtime.h>
#include <cuda_bf16.h>
#include <cstdint>

// Problem constants
#define BB 4
#define SS 8192
#define DD 512
#define HH 8
#define HDIM 64
#define RR 64
#define BSROWS (BB * SS)      // 32768
#define NCHUNK 16

// -------- scratch (static device globals; no allocation) --------
__device__ float g_q[BSROWS * DD];
__device__ float g_k[BSROWS * DD];
__device__ float g_v[BSROWS * DD];
__device__ float g_phiq[BB * HH * SS * RR];
__device__ float g_phik[BB * HH * SS * RR];
__device__ float g_kvp[BB * HH * NCHUNK * RR * HDIM];
__device__ float g_ksp[BB * HH * NCHUNK * RR];
__device__ float g_kv[BB * HH * RR * HDIM];
__device__ float g_ks[BB * HH * RR];
__device__ __nv_bfloat16 g_xhi[BSROWS * DD];
__device__ __nv_bfloat16 g_xlo[BSROWS * DD];
__device__ __nv_bfloat16 g_ahi[BSROWS * DD];
__device__ __nv_bfloat16 g_alo[BSROWS * DD];
__device__ __nv_bfloat16 g_wthi[4 * DD * DD];
__device__ __nv_bfloat16 g_wtlo[4 * DD * DD];
__device__ float g_biasqkv[3 * DD];
// interleaved transposed sketch matrices: [0]=q (G1/G2), [1]=k
__device__ __nv_bfloat16 g_gint_hi[2][128 * 64];
__device__ __nv_bfloat16 g_gint_lo[2][128 * 64];

// ============================================================
// helpers
// ============================================================
__device__ __forceinline__ uint32_t smem_to_u32(const void* p) {
    uint32_t a;
    asm("{ .reg .u64 t; cvta.to.shared.u64 t, %1; cvt.u32.u64 %0, t; }"
        : "=r"(a) : "l"(p));
    return a;
}
__device__ __forceinline__ void ldsm4(uint32_t& r0, uint32_t& r1,
                                      uint32_t& r2, uint32_t& r3,
                                      uint32_t addr) {
    asm volatile("ldmatrix.sync.aligned.m8n8.x4.shared.b16 {%0,%1,%2,%3}, [%4];"
                 : "=r"(r0), "=r"(r1), "=r"(r2), "=r"(r3) : "r"(addr));
}
__device__ __forceinline__ void mma16816(float* d, const uint32_t* a,
                                         const uint32_t* b) {
    asm volatile(
        "mma.sync.aligned.m16n8k16.row.col.f32.bf16.bf16.f32 "
        "{%0,%1,%2,%3}, {%4,%5,%6,%7}, {%8,%9}, {%0,%1,%2,%3};"
        : "+f"(d[0]), "+f"(d[1]), "+f"(d[2]), "+f"(d[3])
        : "r"(a[0]), "r"(a[1]), "r"(a[2]), "r"(a[3]), "r"(b[0]), "r"(b[1]));
}
#define CP_ASYNC16(dst, src) \
    asm volatile("cp.async.cg.shared.global [%0], [%1], 16;" :: "r"(dst), "l"(src))
#define CP_COMMIT() asm volatile("cp.async.commit_group;" ::: "memory")
#define CP_WAIT(n)  asm volatile("cp.async.wait_group %0;" :: "n"(n) : "memory")

__device__ __forceinline__ void split4(float4 v, uint2& hi, uint2& lo) {
    __nv_bfloat16 h0 = __float2bfloat16_rn(v.x), h1 = __float2bfloat16_rn(v.y);
    __nv_bfloat16 h2 = __float2bfloat16_rn(v.z), h3 = __float2bfloat16_rn(v.w);
    float r0 = v.x - __bfloat162float(h0), r1 = v.y - __bfloat162float(h1);
    float r2 = v.z - __bfloat162float(h2), r3 = v.w - __bfloat162float(h3);
    __nv_bfloat16 l0 = __float2bfloat16_rn(r0), l1 = __float2bfloat16_rn(r1);
    __nv_bfloat16 l2 = __float2bfloat16_rn(r2), l3 = __float2bfloat16_rn(r3);
    hi.x = ((uint32_t)__bfloat16_as_ushort(h1) << 16) | __bfloat16_as_ushort(h0);
    hi.y = ((uint32_t)__bfloat16_as_ushort(h3) << 16) | __bfloat16_as_ushort(h2);
    lo.x = ((uint32_t)__bfloat16_as_ushort(l1) << 16) | __bfloat16_as_ushort(l0);
    lo.y = ((uint32_t)__bfloat16_as_ushort(l3) << 16) | __bfloat16_as_ushort(l2);
}

// ============================================================
// prep kernels
// ============================================================
__global__ __launch_bounds__(256) void split_fp32(
    const float* __restrict__ X, __nv_bfloat16* __restrict__ Xh,
    __nv_bfloat16* __restrict__ Xl)
{
    int i = blockIdx.x * 256 + threadIdx.x;
    float4 v = ((const float4*)X)[i];
    uint2 hi, lo;
    split4(v, hi, lo);
    ((uint2*)Xh)[i] = hi;
    ((uint2*)Xl)[i] = lo;
}

// transpose + split one weight matrix
__global__ __launch_bounds__(256) void transpose_split(
    const float* __restrict__ W, __nv_bfloat16* __restrict__ Th,
    __nv_bfloat16* __restrict__ Tl, int rowoff)
{
    __shared__ float t[32][33];
    int bx = blockIdx.x * 32, by = blockIdx.y * 32;
    int x = threadIdx.x & 31, y = threadIdx.x >> 5;
    for (int i = y; i < 32; i += 8) t[i][x] = W[(size_t)(by + i) * DD + bx + x];
    __syncthreads();
    for (int i = y; i < 32; i += 8) {
        float v = t[x][i];
        __nv_bfloat16 h = __float2bfloat16_rn(v);
        __nv_bfloat16 l = __float2bfloat16_rn(v - __bfloat162float(h));
        size_t o = (size_t)(rowoff + bx + i) * DD + by + x;
        Th[o] = h;
        Tl[o] = l;
    }
}

// two weight matrices in one launch (z selects)
__global__ __launch_bounds__(256) void transpose_split2(
    const float* __restrict__ W0, const float* __restrict__ W1,
    __nv_bfloat16* __restrict__ Th, __nv_bfloat16* __restrict__ Tl,
    int rowoff0, int rowoff1)
{
    __shared__ float t[32][33];
    const float* W = blockIdx.z ? W1 : W0;
    const int rowoff = blockIdx.z ? rowoff1 : rowoff0;
    int bx = blockIdx.x * 32, by = blockIdx.y * 32;
    int x = threadIdx.x & 31, y = threadIdx.x >> 5;
    for (int i = y; i < 32; i += 8) t[i][x] = W[(size_t)(by + i) * DD + bx + x];
    __syncthreads();
    for (int i = y; i < 32; i += 8) {
        float v = t[x][i];
        __nv_bfloat16 h = __float2bfloat16_rn(v);
        __nv_bfloat16 l = __float2bfloat16_rn(v - __bfloat162float(h));
        size_t o = (size_t)(rowoff + bx + i) * DD + by + x;
        Th[o] = h;
        Tl[o] = l;
    }
}

__global__ void concat_bias(const float* bq, const float* bk, const float* bv,
                            float* bout)
{
    int i = blockIdx.x * 256 + threadIdx.x;
    if (i < DD) bout[i] = bq[i];
    else if (i < 2 * DD) bout[i] = bk[i - DD];
    else if (i < 3 * DD) bout[i] = bv[i - 2 * DD];
}

// Build interleaved transposed sketch matrices:
// Gint[set][n][k] = (n odd ? G2 : G1)[k][n>>1], split to bf16 hi/lo.
// blockIdx.x selects set (0=q, 1=k).
__global__ __launch_bounds__(256) void g_prep(
    const float* __restrict__ qG1, const float* __restrict__ qG2,
    const float* __restrict__ kG1, const float* __restrict__ kG2)
{
    const int set = blockIdx.x;
    const float* G1 = set ? kG1 : qG1;
    const float* G2 = set ? kG2 : qG2;
    __nv_bfloat16* Oh = g_gint_hi[set];
    __nv_bfloat16* Ol = g_gint_lo[set];
    for (int it = 0; it < 32; it++) {
        int idx = it * 256 + threadIdx.x;     // 8192 elems
        int n = idx >> 6, k = idx & 63;
        float v = ((n & 1) ? G2 : G1)[k * 64 + (n >> 1)];
        __nv_bfloat16 h = __float2bfloat16_rn(v);
        Oh[idx] = h;
        Ol[idx] = __float2bfloat16_rn(v - __bfloat162float(h));
    }
}

// ============================================================
// Tensor-core bf16 3-pass split GEMM, cp.async 3-stage pipeline.
// CTA tile 128x256, 8 warps (2m x 4n), warp tile 64x64.
// ============================================================
#define BKC 32
#define NKCH (DD / BKC)          // 16
#define ROWB 80
#define TILE_A (128 * ROWB)
#define TILE_B (256 * ROWB)
#define ST_AHI 0
#define ST_ALO TILE_A
#define ST_BHI (2 * TILE_A)
#define ST_BLO (2 * TILE_A + TILE_B)
#define STAGEB (2 * TILE_A + 2 * TILE_B)   // 61440
#define PIPE 3
#define GEMM_SMEM (PIPE * STAGEB)          // 184320
#define OFF80(row, ch) ((uint32_t)((row) * ROWB + ((ch) << 4)))

__global__ __launch_bounds__(256, 1) void mma_gemm(
    const __nv_bfloat16* __restrict__ Ahi, const __nv_bfloat16* __restrict__ Alo,
    const __nv_bfloat16* __restrict__ Bhi, const __nv_bfloat16* __restrict__ Blo,
    const float* __restrict__ bias,
    float* __restrict__ o0, float* __restrict__ o1, float* __restrict__ o2)
{
    extern __shared__ char smem[];
    const uint32_t sb = smem_to_u32(smem);

    const int tid = threadIdx.x;
    const int wid = tid >> 5, lane = tid & 31;
    const int bn = blockIdx.x, bm = blockIdx.y;
    const int warp_m = wid & 1, warp_n = wid >> 1;

    const __nv_bfloat16* Ahi_b = Ahi + (size_t)bm * 128 * DD;
    const __nv_bfloat16* Alo_b = Alo + (size_t)bm * 128 * DD;
    const __nv_bfloat16* Bhi_b = Bhi + (size_t)bn * 256 * DD;
    const __nv_bfloat16* Blo_b = Blo + (size_t)bn * 256 * DD;

    const int lrow = tid >> 2;
    const int lch = tid & 3;

    auto load_chunk = [&](int c, int s) {
        const uint32_t stg = sb + s * STAGEB;
        const int k0 = c * BKC;
#pragma unroll
        for (int sw = 0; sw < 2; sw++) {
            const int row = sw * 64 + lrow;
            const size_t go = (size_t)row * DD + k0 + lch * 8;
            const uint32_t so = OFF80(row, lch);
            CP_ASYNC16(stg + ST_AHI + so, Ahi_b + go);
            CP_ASYNC16(stg + ST_ALO + so, Alo_b + go);
        }
#pragma unroll
        for (int sw = 0; sw < 4; sw++) {
            const int row = sw * 64 + lrow;
            const size_t go = (size_t)row * DD + k0 + lch * 8;
            const uint32_t so = OFF80(row, lch);
            CP_ASYNC16(stg + ST_BHI + so, Bhi_b + go);
            CP_ASYNC16(stg + ST_BLO + so, Blo_b + go);
        }
    };

    float acc[4][8][4];
#pragma unroll
    for (int i = 0; i < 4; i++)
#pragma unroll
        for (int j = 0; j < 8; j++)
#pragma unroll
            for (int e = 0; e < 4; e++) acc[i][j][e] = 0.f;

    const int mat = lane >> 3, mr = lane & 7;
    const int a_row_b = warp_m * 64 + (mat & 1) * 8 + mr;
    const int b_row_b = warp_n * 64 + (mat & 1) * 8 + mr;
    const int mchunk = mat >> 1;

    load_chunk(0, 0);
    CP_COMMIT();
    load_chunk(1, 1);
    CP_COMMIT();

    for (int c = 0; c < NKCH; c++) {
        CP_WAIT(1);
        __syncthreads();
        if (c + 2 < NKCH) {
            load_chunk(c + 2, (c + 2) % PIPE);
            CP_COMMIT();
        }

        const uint32_t stg = sb + (c % PIPE) * STAGEB;
#pragma unroll
        for (int kk = 0; kk < 2; kk++) {
            const int ch = kk * 2 + mchunk;
            uint32_t ahi[4][4], alo[4][4];
#pragma unroll
            for (int im = 0; im < 4; im++) {
                const int row = a_row_b + im * 16;
                ldsm4(ahi[im][0], ahi[im][1], ahi[im][2], ahi[im][3],
                      stg + ST_AHI + OFF80(row, ch));
                ldsm4(alo[im][0], alo[im][1], alo[im][2], alo[im][3],
                      stg + ST_ALO + OFF80(row, ch));
            }
#pragma unroll
            for (int j16 = 0; j16 < 4; j16++) {
                const int row = b_row_b + j16 * 16;
                uint32_t h0, h1, h2, h3, l0, l1, l2, l3;
                ldsm4(h0, h1, h2, h3, stg + ST_BHI + OFF80(row, ch));
                ldsm4(l0, l1, l2, l3, stg + ST_BLO + OFF80(row, ch));
                uint32_t bh0[2] = {h0, h2}, bh1[2] = {h1, h3};
                uint32_t bl0[2] = {l0, l2}, bl1[2] = {l1, l3};
#pragma unroll
                for (int im = 0; im < 4; im++) {
                    mma16816(acc[im][j16 * 2], ahi[im], bh0);
                    mma16816(acc[im][j16 * 2], ahi[im], bl0);
                    mma16816(acc[im][j16 * 2], alo[im], bh0);
                    mma16816(acc[im][j16 * 2 + 1], ahi[im], bh1);
                    mma16816(acc[im][j16 * 2 + 1], ahi[im], bl1);
                    mma16816(acc[im][j16 * 2 + 1], alo[im], bh1);
                }
            }
        }
    }

    const int sel = bn >> 1;
    float* C = sel == 0 ? o0 : (sel == 1 ? o1 : o2);
    const int colbase = (bn & 1) * 256;
    const int erow = lane >> 2, ecol = (lane & 3) * 2;
#pragma unroll
    for (int im = 0; im < 4; im++) {
        const size_t row0 = (size_t)bm * 128 + warp_m * 64 + im * 16 + erow;
#pragma unroll
        for (int t = 0; t < 8; t++) {
            const int cofs = warp_n * 64 + t * 8 + ecol;
            float2 b2 = *(const float2*)&bias[bn * 256 + cofs];
            float2 q0 = make_float2(acc[im][t][0] + b2.x, acc[im][t][1] + b2.y);
            float2 q1 = make_float2(acc[im][t][2] + b2.x, acc[im][t][3] + b2.y);
            *(float2*)&C[row0 * DD + colbase + cofs] = q0;
            *(float2*)&C[(row0 + 8) * DD + colbase + cofs] = q1;
        }
    }
}

// ============================================================
// Tensor-core sketch: per CTA = 128 rows x one head.
// z = gamma*Z+beta (split bf16); B = interleaved [G1^T | G2^T] (n=2r,2r+1)
// -> acc cols (2t, 2t+1) = (u_r, w_r) in-thread; phi = (u*w/8)^2.
// 8 warps (2m x 4n), warp tile 64x32, K=64, no pipeline.
// ============================================================
#define SKROWB 144
#define SK_AHI 0
#define SK_ALO (128 * SKROWB)
#define SK_BHI (2 * 128 * SKROWB)
#define SK_BLO (3 * 128 * SKROWB)
#define SK_SMEM (4 * 128 * SKROWB)   // 73728
#define SOFF(row, ch) ((uint32_t)((row) * SKROWB + ((ch) << 4)))

__global__ __launch_bounds__(256, 2) void sketch_tc(
    const float* __restrict__ Z, const __nv_bfloat16* __restrict__ Gh,
    const __nv_bfloat16* __restrict__ Gl,
    const float* __restrict__ gamma, const float* __restrict__ beta,
    float* __restrict__ phi)
{
    extern __shared__ char smem[];
    const uint32_t sb = smem_to_u32(smem);
    const int tid = threadIdx.x;
    const int wid = tid >> 5, lane = tid & 31;
    const int bm = blockIdx.x, h = blockIdx.y;
    const int warp_m = wid & 1, warp_n = wid >> 1;

    // load z tile [128 x 64] fp32, affine, split -> smem
    const float g0 = gamma[0], b0 = beta[0];
    {
        const int zrow = tid >> 4, zc4 = (tid & 15) * 4;
#pragma unroll
        for (int sw = 0; sw < 8; sw++) {
            const int row = sw * 16 + zrow;
            float4 v = *(const float4*)&Z[(size_t)(bm * 128 + row) * DD +
                                          h * HDIM + zc4];
            v.x = g0 * v.x + b0; v.y = g0 * v.y + b0;
            v.z = g0 * v.z + b0; v.w = g0 * v.w + b0;
            uint2 hi, lo;
            split4(v, hi, lo);
            *(uint2*)(smem + SK_AHI + row * SKROWB + zc4 * 2) = hi;
            *(uint2*)(smem + SK_ALO + row * SKROWB + zc4 * 2) = lo;
        }
    }
    // load Gint [128 x 64] bf16 hi/lo -> smem (padded rows)
    {
#pragma unroll
        for (int it = 0; it < 4; it++) {
            const int cidx = it * 256 + tid;     // 1024 16B-chunks
            const int n = cidx >> 3, ch = cidx & 7;
            *(uint4*)(smem + SK_BHI + SOFF(n, ch)) =
                *(const uint4*)((const char*)Gh + n * 128 + ch * 16);
            *(uint4*)(smem + SK_BLO + SOFF(n, ch)) =
                *(const uint4*)((const char*)Gl + n * 128 + ch * 16);
        }
    }
    __syncthreads();

    float acc[4][4][4];
#pragma unroll
    for (int i = 0; i < 4; i++)
#pragma unroll
        for (int j = 0; j < 4; j++)
#pragma unroll
            for (int e = 0; e < 4; e++) acc[i][j][e] = 0.f;

    const int mat = lane >> 3, mr = lane & 7;
    const int a_row_b = warp_m * 64 + (mat & 1) * 8 + mr;
    const int b_row_b = warp_n * 32 + (mat & 1) * 8 + mr;
    const int mchunk = mat >> 1;

#pragma unroll
    for (int kk = 0; kk < 4; kk++) {
        const int ch = kk * 2 + mchunk;
        uint32_t ahi[4][4], alo[4][4];
#pragma unroll
        for (int im = 0; im < 4; im++) {
            const int row = a_row_b + im * 16;
            ldsm4(ahi[im][0], ahi[im][1], ahi[im][2], ahi[im][3],
                  sb + SK_AHI + SOFF(row, ch));
            ldsm4(alo[im][0], alo[im][1], alo[im][2], alo[im][3],
                  sb + SK_ALO + SOFF(row, ch));
        }
#pragma unroll
        for (int j16 = 0; j16 < 2; j16++) {
            const int row = b_row_b + j16 * 16;
            uint32_t h0, h1, h2, h3, l0, l1, l2, l3;
            ldsm4(h0, h1, h2, h3, sb + SK_BHI + SOFF(row, ch));
            ldsm4(l0, l1, l2, l3, sb + SK_BLO + SOFF(row, ch));
            uint32_t bh0[2] = {h0, h2}, bh1[2] = {h1, h3};
            uint32_t bl0[2] = {l0, l2}, bl1[2] = {l1, l3};
#pragma unroll
            for (int im = 0; im < 4; im++) {
                mma16816(acc[im][j16 * 2], ahi[im], bh0);
                mma16816(acc[im][j16 * 2], ahi[im], bl0);
                mma16816(acc[im][j16 * 2], alo[im], bh0);
                mma16816(acc[im][j16 * 2 + 1], ahi[im], bh1);
                mma16816(acc[im][j16 * 2 + 1], ahi[im], bl1);
                mma16816(acc[im][j16 * 2 + 1], alo[im], bh1);
            }
        }
    }

    // epilogue: phi = ((1/8) * u * w)^2
    const int b = bm >> 6;               // 8192/128 = 64 tiles per batch
    const int sbase = (bm & 63) * 128;
    const int g = lane >> 2, t = lane & 3;
    const float inv = 0.125f;
    float* phib = phi + ((size_t)b * HH + h) * SS * RR;
#pragma unroll
    for (int im = 0; im < 4; im++) {
        const int s0 = sbase + warp_m * 64 + im * 16 + g;
#pragma unroll
        for (int jn = 0; jn < 4; jn++) {
            const int r = warp_n * 16 + jn * 4 + t;
            float h0 = inv * acc[im][jn][0] * acc[im][jn][1];
            float h1 = inv * acc[im][jn][2] * acc[im][jn][3];
            phib[(size_t)s0 * RR + r] = h0 * h0;
            phib[(size_t)(s0 + 8) * RR + r] = h1 * h1;
        }
    }
}

// ============================================================
// kv partial sums over S chunks
// ============================================================
__global__ __launch_bounds__(256) void kvsum_kernel(
    const float* __restrict__ phik, const float* __restrict__ v,
    float* __restrict__ kvp, float* __restrict__ ksp)
{
    const int bh = blockIdx.y;
    const int chunk = blockIdx.x;
    const int b = bh >> 3, h = bh & 7;
    const int CS = SS / NCHUNK;

    __shared__ float Ps[32][64];
    __shared__ float Vs[32][64];

    const int tid = threadIdx.x;
    const int tr = tid >> 4, tc = tid & 15;
    const int r0 = tr * 4, d0 = tc * 4;

    float acc[4][4];
#pragma unroll
    for (int i = 0; i < 4; i++)
#pragma unroll
        for (int j = 0; j < 4; j++) acc[i][j] = 0.f;
    float ks = 0.f;

    const int s0 = chunk * CS;
    for (int st = 0; st < CS; st += 32) {
        for (int i = tid; i < 512; i += 256) {
            int row = i >> 4;
            int c4 = (i & 15) * 4;
            *(float4*)&Ps[row][c4] =
                *(const float4*)&phik[((size_t)bh * SS + s0 + st + row) * RR + c4];
            *(float4*)&Vs[row][c4] =
                *(const float4*)&v[((size_t)b * SS + s0 + st + row) * DD + h * HDIM + c4];
        }
        __syncthreads();
#pragma unroll 8
        for (int ss = 0; ss < 32; ss++) {
            float4 p = *(float4*)&Ps[ss][r0];
            float4 vv = *(float4*)&Vs[ss][d0];
            acc[0][0] += p.x * vv.x; acc[0][1] += p.x * vv.y;
            acc[0][2] += p.x * vv.z; acc[0][3] += p.x * vv.w;
            acc[1][0] += p.y * vv.x; acc[1][1] += p.y * vv.y;
            acc[1][2] += p.y * vv.z; acc[1][3] += p.y * vv.w;
            acc[2][0] += p.z * vv.x; acc[2][1] += p.z * vv.y;
            acc[2][2] += p.z * vv.z; acc[2][3] += p.z * vv.w;
            acc[3][0] += p.w * vv.x; acc[3][1] += p.w * vv.y;
            acc[3][2] += p.w * vv.z; acc[3][3] += p.w * vv.w;
        }
        if (tid < 64) {
#pragma unroll
            for (int ss = 0; ss < 32; ss++) ks += Ps[ss][tid];
        }
        __syncthreads();
    }

    float* kvout = kvp + ((size_t)bh * NCHUNK + chunk) * (RR * HDIM);
#pragma unroll
    for (int i = 0; i < 4; i++)
        *(float4*)&kvout[(r0 + i) * HDIM + d0] =
            make_float4(acc[i][0], acc[i][1], acc[i][2], acc[i][3]);
    if (tid < 64) ksp[((size_t)bh * NCHUNK + chunk) * RR + tid] = ks;
}

__global__ void reduce_kernel(const float* __restrict__ kvp,
                              const float* __restrict__ ksp,
                              float* __restrict__ kv, float* __restrict__ ks)
{
    const int idx = blockIdx.x * 256 + threadIdx.x;
    const int total_kv = BB * HH * RR * HDIM;
    if (idx < total_kv) {
        int bh = idx >> 12, e = idx & 4095;
        float s = 0.f;
#pragma unroll
        for (int c = 0; c < NCHUNK; c++)
            s += kvp[((size_t)bh * NCHUNK + c) * 4096 + e];
        kv[idx] = s;
    } else if (idx < total_kv + BB * HH * RR) {
        int j = idx - total_kv;
        int bh = j >> 6, r = j & 63;
        float s = 0.f;
#pragma unroll
        for (int c = 0; c < NCHUNK; c++)
            s += ksp[((size_t)bh * NCHUNK + c) * RR + r];
        ks[j] = s;
    }
}

// ============================================================
// attn output -> split bf16 hi/lo
// ============================================================
__global__ __launch_bounds__(256) void attn_out_kernel(
    const float* __restrict__ phiq, const float* __restrict__ kv,
    const float* __restrict__ ks,
    __nv_bfloat16* __restrict__ ahi, __nv_bfloat16* __restrict__ alo)
{
    const int bh = blockIdx.y;
    const int stile = blockIdx.x;
    const int b = bh >> 3, h = bh & 7;

    __shared__ float KVs[4096];
    __shared__ float KSs[64];
    __shared__ float Ps[32 * 65];
    __shared__ float Dens[32];

    const int tid = threadIdx.x;
    const int s0 = stile * 32;

    for (int i = tid; i < 1024; i += 256)
        ((float4*)KVs)[i] = ((const float4*)(kv + (size_t)bh * 4096))[i];
    if (tid < 64) KSs[tid] = ks[bh * RR + tid];
    for (int i = tid; i < 2048; i += 256) {
        int row = i >> 6, c = i & 63;
        Ps[row * 65 + c] = phiq[((size_t)bh * SS + s0 + row) * RR + c];
    }
    __syncthreads();

    if (tid < 32) {
        float dsum = 0.f;
#pragma unroll
        for (int r = 0; r < 64; r++) dsum += Ps[tid * 65 + r] * KSs[r];
        Dens[tid] = dsum + 1e-6f;
    }
    __syncthreads();

    const int d = tid & 63, g = tid >> 6;
    for (int rr = g; rr < 32; rr += 4) {
        float num = 0.f;
#pragma unroll
        for (int r = 0; r < 64; r++) num += Ps[rr * 65 + r] * KVs[r * 64 + d];
        float o = num / Dens[rr];
        __nv_bfloat16 hi = __float2bfloat16_rn(o);
        __nv_bfloat16 lo = __float2bfloat16_rn(o - __bfloat162float(hi));
        size_t idx = ((size_t)b * SS + s0 + rr) * DD + h * HDIM + d;
        ahi[idx] = hi;
        alo[idx] = lo;
    }
}

// ============================================================
// launch
// ============================================================
extern "C" void kernel_launch(void* const* d_in, const int* in_sizes, int n_in,
                              void* d_out, int out_size)
{
    const float* x       = (const float*)d_in[0];
    const float* Wq      = (const float*)d_in[1];
    const float* bq      = (const float*)d_in[2];
    const float* Wk      = (const float*)d_in[3];
    const float* bk      = (const float*)d_in[4];
    const float* Wv      = (const float*)d_in[5];
    const float* bv      = (const float*)d_in[6];
    const float* Wp      = (const float*)d_in[7];
    const float* bp      = (const float*)d_in[8];
    const float* gamma_q = (const float*)d_in[9];
    const float* beta_q  = (const float*)d_in[10];
    const float* gamma_k = (const float*)d_in[11];
    const float* beta_k  = (const float*)d_in[12];
    const float* qG1     = (const float*)d_in[13];
    const float* qG2     = (const float*)d_in[14];
    const float* kG1     = (const float*)d_in[15];
    const float* kG2     = (const float*)d_in[16];
    float* out = (float*)d_out;

    float *p_q, *p_k, *p_v, *p_phiq, *p_phik, *p_kvp, *p_ksp, *p_kv, *p_ks, *p_bqkv;
    __nv_bfloat16 *p_xhi, *p_xlo, *p_ahi, *p_alo, *p_wthi, *p_wtlo;
    __nv_bfloat16 *p_ginth, *p_gintl;
    cudaGetSymbolAddress((void**)&p_q, g_q);
    cudaGetSymbolAddress((void**)&p_k, g_k);
    cudaGetSymbolAddress((void**)&p_v, g_v);
    cudaGetSymbolAddress((void**)&p_phiq, g_phiq);
    cudaGetSymbolAddress((void**)&p_phik, g_phik);
    cudaGetSymbolAddress((void**)&p_kvp, g_kvp);
    cudaGetSymbolAddress((void**)&p_ksp, g_ksp);
    cudaGetSymbolAddress((void**)&p_kv, g_kv);
    cudaGetSymbolAddress((void**)&p_ks, g_ks);
    cudaGetSymbolAddress((void**)&p_bqkv, g_biasqkv);
    cudaGetSymbolAddress((void**)&p_xhi, g_xhi);
    cudaGetSymbolAddress((void**)&p_xlo, g_xlo);
    cudaGetSymbolAddress((void**)&p_ahi, g_ahi);
    cudaGetSymbolAddress((void**)&p_alo, g_alo);
    cudaGetSymbolAddress((void**)&p_wthi, g_wthi);
    cudaGetSymbolAddress((void**)&p_wtlo, g_wtlo);
    cudaGetSymbolAddress((void**)&p_ginth, g_gint_hi);
    cudaGetSymbolAddress((void**)&p_gintl, g_gint_lo);

    cudaFuncSetAttribute(mma_gemm, cudaFuncAttributeMaxDynamicSharedMemorySize,
                         GEMM_SMEM);
    cudaFuncSetAttribute(sketch_tc, cudaFuncAttributeMaxDynamicSharedMemorySize,
                         SK_SMEM);

    // ---- prep (5 launches, so ncu -s 5 captures the QKV GEMM) ----
    split_fp32<<<BSROWS * DD / 4 / 256, 256>>>(x, p_xhi, p_xlo);           // 1
    concat_bias<<<6, 256>>>(bq, bk, bv, p_bqkv);                           // 2
    g_prep<<<2, 256>>>(qG1, qG2, kG1, kG2);                                // 3
    dim3 tg(16, 16);
    transpose_split<<<tg, 256>>>(Wq, p_wthi, p_wtlo, 0);                   // 4
    transpose_split2<<<dim3(16, 16, 2), 256>>>(Wk, Wv, p_wthi, p_wtlo,
                                               512, 1024);                 // 5

    // ---- fused QKV GEMM ----
    dim3 gq(6, BSROWS / 128);
    mma_gemm<<<gq, 256, GEMM_SMEM>>>(p_xhi, p_xlo, p_wthi, p_wtlo, p_bqkv,
                                     p_q, p_k, p_v);                       // 6

    // ---- tensor-core sketch ----
    dim3 skg(BSROWS / 128, HH);
    sketch_tc<<<skg, 256, SK_SMEM>>>(p_q, p_ginth, p_gintl,
                                     gamma_q, beta_q, p_phiq);
    sketch_tc<<<skg, 256, SK_SMEM>>>(p_k, p_ginth + 128 * 64,
                                     p_gintl + 128 * 64,
                                     gamma_k, beta_k, p_phik);

    kvsum_kernel<<<dim3(NCHUNK, BB * HH), 256>>>(p_phik, p_v, p_kvp, p_ksp);

    int red_total = BB * HH * RR * HDIM + BB * HH * RR;
    reduce_kernel<<<(red_total + 255) / 256, 256>>>(p_kvp, p_ksp, p_kv, p_ks);

    attn_out_kernel<<<dim3(SS / 32, BB * HH), 256>>>(p_phiq, p_kv, p_ks,
                                                     p_ahi, p_alo);

    transpose_split<<<tg, 256>>>(Wp, p_wthi, p_wtlo, 1536);

    dim3 go(2, BSROWS / 128);
    mma_gemm<<<go, 256, GEMM_SMEM>>>(p_ahi, p_alo,
                                     p_wthi + 1536 * DD, p_wtlo + 1536 * DD,
                                     bp, out, out, out);
}

// round 8
// speedup vs baseline: 1.2661x; 1.1593x over previous
#include <cuda_runtime.h>
#include <cuda_bf16.h>
#include <cstdint>

// Problem constants
#define BB 4
#define SS 8192
#define DD 512
#define HH 8
#define HDIM 64
#define RR 64
#define BSROWS (BB * SS)      // 32768
#define BH (BB * HH)          // 32
#define NCHUNK 16

// -------- scratch (static device globals; no allocation) --------
__device__ float g_q[BSROWS * DD];
__device__ float g_k[BSROWS * DD];
__device__ __nv_bfloat16 g_vh[BSROWS * DD];
__device__ __nv_bfloat16 g_vl[BSROWS * DD];
__device__ __nv_bfloat16 g_xhi[BSROWS * DD];
__device__ __nv_bfloat16 g_xlo[BSROWS * DD];
__device__ __nv_bfloat16 g_ahi[BSROWS * DD];
__device__ __nv_bfloat16 g_alo[BSROWS * DD];
__device__ __nv_bfloat16 g_wthi[4 * DD * DD];
__device__ __nv_bfloat16 g_wtlo[4 * DD * DD];
__device__ float g_biasqkv[3 * DD];
__device__ __nv_bfloat16 g_gint_hi[2][128 * 64];
__device__ __nv_bfloat16 g_gint_lo[2][128 * 64];
// phi buffers: phiq [bh][s][r]; phik transposed [bh][r][s]
__device__ __nv_bfloat16 g_pqh[BH * SS * RR];
__device__ __nv_bfloat16 g_pql[BH * SS * RR];
__device__ __nv_bfloat16 g_pkth[BH * RR * SS];
__device__ __nv_bfloat16 g_pktl[BH * RR * SS];
// kvT partials [bh][chunk][d][r], ksum partials
__device__ float g_kvtp[BH * NCHUNK * HDIM * RR];
__device__ float g_ksp[BH * NCHUNK * RR];
__device__ __nv_bfloat16 g_kvth[BH * HDIM * RR];
__device__ __nv_bfloat16 g_kvtl[BH * HDIM * RR];
__device__ float g_ks[BH * RR];

// ============================================================
// helpers
// ============================================================
__device__ __forceinline__ uint32_t smem_to_u32(const void* p) {
    uint32_t a;
    asm("{ .reg .u64 t; cvta.to.shared.u64 t, %1; cvt.u32.u64 %0, t; }"
        : "=r"(a) : "l"(p));
    return a;
}
__device__ __forceinline__ void ldsm4(uint32_t& r0, uint32_t& r1,
                                      uint32_t& r2, uint32_t& r3,
                                      uint32_t addr) {
    asm volatile("ldmatrix.sync.aligned.m8n8.x4.shared.b16 {%0,%1,%2,%3}, [%4];"
                 : "=r"(r0), "=r"(r1), "=r"(r2), "=r"(r3) : "r"(addr));
}
__device__ __forceinline__ void ldsm4t(uint32_t& r0, uint32_t& r1,
                                       uint32_t& r2, uint32_t& r3,
                                       uint32_t addr) {
    asm volatile("ldmatrix.sync.aligned.m8n8.x4.trans.shared.b16 {%0,%1,%2,%3}, [%4];"
                 : "=r"(r0), "=r"(r1), "=r"(r2), "=r"(r3) : "r"(addr));
}
__device__ __forceinline__ void mma16816(float* d, const uint32_t* a,
                                         const uint32_t* b) {
    asm volatile(
        "mma.sync.aligned.m16n8k16.row.col.f32.bf16.bf16.f32 "
        "{%0,%1,%2,%3}, {%4,%5,%6,%7}, {%8,%9}, {%0,%1,%2,%3};"
        : "+f"(d[0]), "+f"(d[1]), "+f"(d[2]), "+f"(d[3])
        : "r"(a[0]), "r"(a[1]), "r"(a[2]), "r"(a[3]), "r"(b[0]), "r"(b[1]));
}
#define CP_ASYNC16(dst, src) \
    asm volatile("cp.async.cg.shared.global [%0], [%1], 16;" :: "r"(dst), "l"(src))
#define CP_COMMIT() asm volatile("cp.async.commit_group;" ::: "memory")
#define CP_WAIT(n)  asm volatile("cp.async.wait_group %0;" :: "n"(n) : "memory")

__device__ __forceinline__ void split4(float4 v, uint2& hi, uint2& lo) {
    __nv_bfloat16 h0 = __float2bfloat16_rn(v.x), h1 = __float2bfloat16_rn(v.y);
    __nv_bfloat16 h2 = __float2bfloat16_rn(v.z), h3 = __float2bfloat16_rn(v.w);
    float r0 = v.x - __bfloat162float(h0), r1 = v.y - __bfloat162float(h1);
    float r2 = v.z - __bfloat162float(h2), r3 = v.w - __bfloat162float(h3);
    __nv_bfloat16 l0 = __float2bfloat16_rn(r0), l1 = __float2bfloat16_rn(r1);
    __nv_bfloat16 l2 = __float2bfloat16_rn(r2), l3 = __float2bfloat16_rn(r3);
    hi.x = ((uint32_t)__bfloat16_as_ushort(h1) << 16) | __bfloat16_as_ushort(h0);
    hi.y = ((uint32_t)__bfloat16_as_ushort(h3) << 16) | __bfloat16_as_ushort(h2);
    lo.x = ((uint32_t)__bfloat16_as_ushort(l1) << 16) | __bfloat16_as_ushort(l0);
    lo.y = ((uint32_t)__bfloat16_as_ushort(l3) << 16) | __bfloat16_as_ushort(l2);
}
// pack 2 floats -> bf16x2 hi word + lo word
__device__ __forceinline__ void split2(float a, float b, uint32_t& hp, uint32_t& lp) {
    __nv_bfloat16 h0 = __float2bfloat16_rn(a), h1 = __float2bfloat16_rn(b);
    float l0 = a - __bfloat162float(h0), l1 = b - __bfloat162float(h1);
    __nv_bfloat16 e0 = __float2bfloat16_rn(l0), e1 = __float2bfloat16_rn(l1);
    hp = ((uint32_t)__bfloat16_as_ushort(h1) << 16) | __bfloat16_as_ushort(h0);
    lp = ((uint32_t)__bfloat16_as_ushort(e1) << 16) | __bfloat16_as_ushort(e0);
}

// ============================================================
// prep kernels
// ============================================================
__global__ __launch_bounds__(256) void split_fp32(
    const float* __restrict__ X, __nv_bfloat16* __restrict__ Xh,
    __nv_bfloat16* __restrict__ Xl)
{
    int i = blockIdx.x * 256 + threadIdx.x;
    float4 v = ((const float4*)X)[i];
    uint2 hi, lo;
    split4(v, hi, lo);
    ((uint2*)Xh)[i] = hi;
    ((uint2*)Xl)[i] = lo;
}

__global__ __launch_bounds__(256) void transpose_split(
    const float* __restrict__ W, __nv_bfloat16* __restrict__ Th,
    __nv_bfloat16* __restrict__ Tl, int rowoff)
{
    __shared__ float t[32][33];
    int bx = blockIdx.x * 32, by = blockIdx.y * 32;
    int x = threadIdx.x & 31, y = threadIdx.x >> 5;
    for (int i = y; i < 32; i += 8) t[i][x] = W[(size_t)(by + i) * DD + bx + x];
    __syncthreads();
    for (int i = y; i < 32; i += 8) {
        float v = t[x][i];
        __nv_bfloat16 h = __float2bfloat16_rn(v);
        __nv_bfloat16 l = __float2bfloat16_rn(v - __bfloat162float(h));
        size_t o = (size_t)(rowoff + bx + i) * DD + by + x;
        Th[o] = h;
        Tl[o] = l;
    }
}

__global__ __launch_bounds__(256) void transpose_split2(
    const float* __restrict__ W0, const float* __restrict__ W1,
    __nv_bfloat16* __restrict__ Th, __nv_bfloat16* __restrict__ Tl,
    int rowoff0, int rowoff1)
{
    __shared__ float t[32][33];
    const float* W = blockIdx.z ? W1 : W0;
    const int rowoff = blockIdx.z ? rowoff1 : rowoff0;
    int bx = blockIdx.x * 32, by = blockIdx.y * 32;
    int x = threadIdx.x & 31, y = threadIdx.x >> 5;
    for (int i = y; i < 32; i += 8) t[i][x] = W[(size_t)(by + i) * DD + bx + x];
    __syncthreads();
    for (int i = y; i < 32; i += 8) {
        float v = t[x][i];
        __nv_bfloat16 h = __float2bfloat16_rn(v);
        __nv_bfloat16 l = __float2bfloat16_rn(v - __bfloat162float(h));
        size_t o = (size_t)(rowoff + bx + i) * DD + by + x;
        Th[o] = h;
        Tl[o] = l;
    }
}

__global__ void concat_bias(const float* bq, const float* bk, const float* bv,
                            float* bout)
{
    int i = blockIdx.x * 256 + threadIdx.x;
    if (i < DD) bout[i] = bq[i];
    else if (i < 2 * DD) bout[i] = bk[i - DD];
    else if (i < 3 * DD) bout[i] = bv[i - 2 * DD];
}

__global__ __launch_bounds__(256) void g_prep(
    const float* __restrict__ qG1, const float* __restrict__ qG2,
    const float* __restrict__ kG1, const float* __restrict__ kG2)
{
    const int set = blockIdx.x;
    const float* G1 = set ? kG1 : qG1;
    const float* G2 = set ? kG2 : qG2;
    __nv_bfloat16* Oh = g_gint_hi[set];
    __nv_bfloat16* Ol = g_gint_lo[set];
    for (int it = 0; it < 32; it++) {
        int idx = it * 256 + threadIdx.x;
        int n = idx >> 6, k = idx & 63;
        float v = ((n & 1) ? G2 : G1)[k * 64 + (n >> 1)];
        __nv_bfloat16 h = __float2bfloat16_rn(v);
        Oh[idx] = h;
        Ol[idx] = __float2bfloat16_rn(v - __bfloat162float(h));
    }
}

// ============================================================
// Tensor-core bf16 3-pass split GEMM (as R7), v output -> bf16 hi/lo
// ============================================================
#define BKC 32
#define NKCH (DD / BKC)
#define ROWB 80
#define TILE_A (128 * ROWB)
#define TILE_B (256 * ROWB)
#define ST_AHI 0
#define ST_ALO TILE_A
#define ST_BHI (2 * TILE_A)
#define ST_BLO (2 * TILE_A + TILE_B)
#define STAGEB (2 * TILE_A + 2 * TILE_B)
#define PIPE 3
#define GEMM_SMEM (PIPE * STAGEB)
#define OFF80(row, ch) ((uint32_t)((row) * ROWB + ((ch) << 4)))

__global__ __launch_bounds__(256, 1) void mma_gemm(
    const __nv_bfloat16* __restrict__ Ahi, const __nv_bfloat16* __restrict__ Alo,
    const __nv_bfloat16* __restrict__ Bhi, const __nv_bfloat16* __restrict__ Blo,
    const float* __restrict__ bias,
    float* __restrict__ o0, float* __restrict__ o1,
    __nv_bfloat16* __restrict__ o2h, __nv_bfloat16* __restrict__ o2l)
{
    extern __shared__ char smem[];
    const uint32_t sb = smem_to_u32(smem);

    const int tid = threadIdx.x;
    const int wid = tid >> 5, lane = tid & 31;
    const int bn = blockIdx.x, bm = blockIdx.y;
    const int warp_m = wid & 1, warp_n = wid >> 1;

    const __nv_bfloat16* Ahi_b = Ahi + (size_t)bm * 128 * DD;
    const __nv_bfloat16* Alo_b = Alo + (size_t)bm * 128 * DD;
    const __nv_bfloat16* Bhi_b = Bhi + (size_t)bn * 256 * DD;
    const __nv_bfloat16* Blo_b = Blo + (size_t)bn * 256 * DD;

    const int lrow = tid >> 2;
    const int lch = tid & 3;

    auto load_chunk = [&](int c, int s) {
        const uint32_t stg = sb + s * STAGEB;
        const int k0 = c * BKC;
#pragma unroll
        for (int sw = 0; sw < 2; sw++) {
            const int row = sw * 64 + lrow;
            const size_t go = (size_t)row * DD + k0 + lch * 8;
            const uint32_t so = OFF80(row, lch);
            CP_ASYNC16(stg + ST_AHI + so, Ahi_b + go);
            CP_ASYNC16(stg + ST_ALO + so, Alo_b + go);
        }
#pragma unroll
        for (int sw = 0; sw < 4; sw++) {
            const int row = sw * 64 + lrow;
            const size_t go = (size_t)row * DD + k0 + lch * 8;
            const uint32_t so = OFF80(row, lch);
            CP_ASYNC16(stg + ST_BHI + so, Bhi_b + go);
            CP_ASYNC16(stg + ST_BLO + so, Blo_b + go);
        }
    };

    float acc[4][8][4];
#pragma unroll
    for (int i = 0; i < 4; i++)
#pragma unroll
        for (int j = 0; j < 8; j++)
#pragma unroll
            for (int e = 0; e < 4; e++) acc[i][j][e] = 0.f;

    const int mat = lane >> 3, mr = lane & 7;
    const int a_row_b = warp_m * 64 + (mat & 1) * 8 + mr;
    const int b_row_b = warp_n * 64 + (mat & 1) * 8 + mr;
    const int mchunk = mat >> 1;

    load_chunk(0, 0);
    CP_COMMIT();
    load_chunk(1, 1);
    CP_COMMIT();

    for (int c = 0; c < NKCH; c++) {
        CP_WAIT(1);
        __syncthreads();
        if (c + 2 < NKCH) {
            load_chunk(c + 2, (c + 2) % PIPE);
            CP_COMMIT();
        }

        const uint32_t stg = sb + (c % PIPE) * STAGEB;
#pragma unroll
        for (int kk = 0; kk < 2; kk++) {
            const int ch = kk * 2 + mchunk;
            uint32_t ahi[4][4], alo[4][4];
#pragma unroll
            for (int im = 0; im < 4; im++) {
                const int row = a_row_b + im * 16;
                ldsm4(ahi[im][0], ahi[im][1], ahi[im][2], ahi[im][3],
                      stg + ST_AHI + OFF80(row, ch));
                ldsm4(alo[im][0], alo[im][1], alo[im][2], alo[im][3],
                      stg + ST_ALO + OFF80(row, ch));
            }
#pragma unroll
            for (int j16 = 0; j16 < 4; j16++) {
                const int row = b_row_b + j16 * 16;
                uint32_t h0, h1, h2, h3, l0, l1, l2, l3;
                ldsm4(h0, h1, h2, h3, stg + ST_BHI + OFF80(row, ch));
                ldsm4(l0, l1, l2, l3, stg + ST_BLO + OFF80(row, ch));
                uint32_t bh0[2] = {h0, h2}, bh1[2] = {h1, h3};
                uint32_t bl0[2] = {l0, l2}, bl1[2] = {l1, l3};
#pragma unroll
                for (int im = 0; im < 4; im++) {
                    mma16816(acc[im][j16 * 2], ahi[im], bh0);
                    mma16816(acc[im][j16 * 2], ahi[im], bl0);
                    mma16816(acc[im][j16 * 2], alo[im], bh0);
                    mma16816(acc[im][j16 * 2 + 1], ahi[im], bh1);
                    mma16816(acc[im][j16 * 2 + 1], ahi[im], bl1);
                    mma16816(acc[im][j16 * 2 + 1], alo[im], bh1);
                }
            }
        }
    }

    const int sel = bn >> 1;
    const int colbase = (bn & 1) * 256;
    const int erow = lane >> 2, ecol = (lane & 3) * 2;
    if (sel < 2) {
        float* C = sel == 0 ? o0 : o1;
#pragma unroll
        for (int im = 0; im < 4; im++) {
            const size_t row0 = (size_t)bm * 128 + warp_m * 64 + im * 16 + erow;
#pragma unroll
            for (int t = 0; t < 8; t++) {
                const int cofs = warp_n * 64 + t * 8 + ecol;
                float2 b2 = *(const float2*)&bias[bn * 256 + cofs];
                float2 q0 = make_float2(acc[im][t][0] + b2.x, acc[im][t][1] + b2.y);
                float2 q1 = make_float2(acc[im][t][2] + b2.x, acc[im][t][3] + b2.y);
                *(float2*)&C[row0 * DD + colbase + cofs] = q0;
                *(float2*)&C[(row0 + 8) * DD + colbase + cofs] = q1;
            }
        }
    } else {
        // v output: split to bf16 hi/lo
#pragma unroll
        for (int im = 0; im < 4; im++) {
            const size_t row0 = (size_t)bm * 128 + warp_m * 64 + im * 16 + erow;
#pragma unroll
            for (int t = 0; t < 8; t++) {
                const int cofs = warp_n * 64 + t * 8 + ecol;
                float2 b2 = *(const float2*)&bias[bn * 256 + cofs];
                uint32_t hp, lp;
                split2(acc[im][t][0] + b2.x, acc[im][t][1] + b2.y, hp, lp);
                *(uint32_t*)(o2h + row0 * DD + colbase + cofs) = hp;
                *(uint32_t*)(o2l + row0 * DD + colbase + cofs) = lp;
                split2(acc[im][t][2] + b2.x, acc[im][t][3] + b2.y, hp, lp);
                *(uint32_t*)(o2h + (row0 + 8) * DD + colbase + cofs) = hp;
                *(uint32_t*)(o2l + (row0 + 8) * DD + colbase + cofs) = lp;
            }
        }
    }
}

// ============================================================
// Fused TC sketch (q & k via blockIdx.z):
// phi = ((u*w)/8)^2, split bf16.
// set 0 (q): phiq [bh][s][r]; set 1 (k): phikT [bh][r][s].
// Both staged through smem for coalesced global writes.
// ============================================================
#define SKROWB 144
#define SK_AHI 0
#define SK_ALO (128 * SKROWB)
#define SK_BHI (2 * 128 * SKROWB)
#define SK_BLO (3 * 128 * SKROWB)
#define SK_SMEM (4 * 128 * SKROWB)   // 73728
#define SOFF(row, ch) ((uint32_t)((row) * SKROWB + ((ch) << 4)))

__global__ __launch_bounds__(256, 2) void sketch_tc2(
    const float* __restrict__ Q, const float* __restrict__ K,
    const float* __restrict__ gq, const float* __restrict__ betq,
    const float* __restrict__ gk, const float* __restrict__ betk,
    __nv_bfloat16* __restrict__ pqh, __nv_bfloat16* __restrict__ pql,
    __nv_bfloat16* __restrict__ pkth, __nv_bfloat16* __restrict__ pktl)
{
    extern __shared__ char smem[];
    const uint32_t sb = smem_to_u32(smem);
    const int tid = threadIdx.x;
    const int wid = tid >> 5, lane = tid & 31;
    const int bm = blockIdx.x, h = blockIdx.y, set = blockIdx.z;
    const int warp_m = wid & 1, warp_n = wid >> 1;

    const float* Z = set ? K : Q;
    const float g0 = set ? gk[0] : gq[0];
    const float b0 = set ? betk[0] : betq[0];
    const __nv_bfloat16* Gh = &g_gint_hi[set][0];
    const __nv_bfloat16* Gl = &g_gint_lo[set][0];

    // load z tile [128 x 64] fp32, affine, split -> smem
    {
        const int zrow = tid >> 4, zc4 = (tid & 15) * 4;
#pragma unroll
        for (int sw = 0; sw < 8; sw++) {
            const int row = sw * 16 + zrow;
            float4 v = *(const float4*)&Z[(size_t)(bm * 128 + row) * DD +
                                          h * HDIM + zc4];
            v.x = g0 * v.x + b0; v.y = g0 * v.y + b0;
            v.z = g0 * v.z + b0; v.w = g0 * v.w + b0;
            uint2 hi, lo;
            split4(v, hi, lo);
            *(uint2*)(smem + SK_AHI + row * SKROWB + zc4 * 2) = hi;
            *(uint2*)(smem + SK_ALO + row * SKROWB + zc4 * 2) = lo;
        }
    }
    // load Gint [128 x 64] bf16 hi/lo -> smem
    {
#pragma unroll
        for (int it = 0; it < 4; it++) {
            const int cidx = it * 256 + tid;
            const int n = cidx >> 3, ch = cidx & 7;
            *(uint4*)(smem + SK_BHI + SOFF(n, ch)) =
                *(const uint4*)((const char*)Gh + n * 128 + ch * 16);
            *(uint4*)(smem + SK_BLO + SOFF(n, ch)) =
                *(const uint4*)((const char*)Gl + n * 128 + ch * 16);
        }
    }
    __syncthreads();

    float acc[4][4][4];
#pragma unroll
    for (int i = 0; i < 4; i++)
#pragma unroll
        for (int j = 0; j < 4; j++)
#pragma unroll
            for (int e = 0; e < 4; e++) acc[i][j][e] = 0.f;

    const int mat = lane >> 3, mr = lane & 7;
    const int a_row_b = warp_m * 64 + (mat & 1) * 8 + mr;
    const int b_row_b = warp_n * 32 + (mat & 1) * 8 + mr;
    const int mchunk = mat >> 1;

#pragma unroll
    for (int kk = 0; kk < 4; kk++) {
        const int ch = kk * 2 + mchunk;
        uint32_t ahi[4][4], alo[4][4];
#pragma unroll
        for (int im = 0; im < 4; im++) {
            const int row = a_row_b + im * 16;
            ldsm4(ahi[im][0], ahi[im][1], ahi[im][2], ahi[im][3],
                  sb + SK_AHI + SOFF(row, ch));
            ldsm4(alo[im][0], alo[im][1], alo[im][2], alo[im][3],
                  sb + SK_ALO + SOFF(row, ch));
        }
#pragma unroll
        for (int j16 = 0; j16 < 2; j16++) {
            const int row = b_row_b + j16 * 16;
            uint32_t h0, h1, h2, h3, l0, l1, l2, l3;
            ldsm4(h0, h1, h2, h3, sb + SK_BHI + SOFF(row, ch));
            ldsm4(l0, l1, l2, l3, sb + SK_BLO + SOFF(row, ch));
            uint32_t bh0[2] = {h0, h2}, bh1[2] = {h1, h3};
            uint32_t bl0[2] = {l0, l2}, bl1[2] = {l1, l3};
#pragma unroll
            for (int im = 0; im < 4; im++) {
                mma16816(acc[im][j16 * 2], ahi[im], bh0);
                mma16816(acc[im][j16 * 2], ahi[im], bl0);
                mma16816(acc[im][j16 * 2], alo[im], bh0);
                mma16816(acc[im][j16 * 2 + 1], ahi[im], bh1);
                mma16816(acc[im][j16 * 2 + 1], ahi[im], bl1);
                mma16816(acc[im][j16 * 2 + 1], alo[im], bh1);
            }
        }
    }

    const int b = bm >> 6;
    const int sbase = (bm & 63) * 128;
    const int bh = b * HH + h;
    const int g = lane >> 2, t = lane & 3;
    const float inv = 0.125f;

    __syncthreads();   // done reading mma smem; reuse for staging

    __nv_bfloat16* SH = (__nv_bfloat16*)smem;
    if (set == 0) {
        // stage [128][72] hi + lo (lo at +128*144 bytes)
        __nv_bfloat16* SL = (__nv_bfloat16*)(smem + 128 * 144);
#pragma unroll
        for (int im = 0; im < 4; im++) {
            const int s0 = warp_m * 64 + im * 16 + g;
#pragma unroll
            for (int jn = 0; jn < 4; jn++) {
                const int r = warp_n * 16 + jn * 4 + t;
                float h0 = inv * acc[im][jn][0] * acc[im][jn][1];
                float h1 = inv * acc[im][jn][2] * acc[im][jn][3];
                float p0 = h0 * h0, p1 = h1 * h1;
                __nv_bfloat16 x0 = __float2bfloat16_rn(p0);
                __nv_bfloat16 x1 = __float2bfloat16_rn(p1);
                SH[s0 * 72 + r] = x0;
                SH[(s0 + 8) * 72 + r] = x1;
                SL[s0 * 72 + r] = __float2bfloat16_rn(p0 - __bfloat162float(x0));
                SL[(s0 + 8) * 72 + r] = __float2bfloat16_rn(p1 - __bfloat162float(x1));
            }
        }
        __syncthreads();
        const int row = tid >> 1, half = tid & 1;
        size_t gbase = ((size_t)bh * SS + sbase + row) * RR + half * 32;
        const uint4* srcH = (const uint4*)(smem + row * 144 + half * 64);
        const uint4* srcL = (const uint4*)(smem + 128 * 144 + row * 144 + half * 64);
#pragma unroll
        for (int i = 0; i < 4; i++) ((uint4*)(pqh + gbase))[i] = srcH[i];
#pragma unroll
        for (int i = 0; i < 4; i++) ((uint4*)(pql + gbase))[i] = srcL[i];
    } else {
        // stage transposed [64 r][136 s] hi + lo (lo at +64*272 bytes)
        __nv_bfloat16* SL = (__nv_bfloat16*)(smem + 64 * 272);
#pragma unroll
        for (int im = 0; im < 4; im++) {
            const int s0 = warp_m * 64 + im * 16 + g;
#pragma unroll
            for (int jn = 0; jn < 4; jn++) {
                const int r = warp_n * 16 + jn * 4 + t;
                float h0 = inv * acc[im][jn][0] * acc[im][jn][1];
                float h1 = inv * acc[im][jn][2] * acc[im][jn][3];
                float p0 = h0 * h0, p1 = h1 * h1;
                __nv_bfloat16 x0 = __float2bfloat16_rn(p0);
                __nv_bfloat16 x1 = __float2bfloat16_rn(p1);
                SH[r * 136 + s0] = x0;
                SH[r * 136 + s0 + 8] = x1;
                SL[r * 136 + s0] = __float2bfloat16_rn(p0 - __bfloat162float(x0));
                SL[r * 136 + s0 + 8] = __float2bfloat16_rn(p1 - __bfloat162float(x1));
            }
        }
        __syncthreads();
        const int r = tid >> 2, q4 = tid & 3;
        size_t gbase = ((size_t)bh * RR + r) * SS + sbase + q4 * 32;
        const uint4* srcH = (const uint4*)(smem + r * 272 + q4 * 64);
        const uint4* srcL = (const uint4*)(smem + 64 * 272 + r * 272 + q4 * 64);
#pragma unroll
        for (int i = 0; i < 4; i++) ((uint4*)(pkth + gbase))[i] = srcH[i];
#pragma unroll
        for (int i = 0; i < 4; i++) ((uint4*)(pktl + gbase))[i] = srcL[i];
    }
}

// ============================================================
// TC kvsum: kvT[d][r] = sum_s v[s,d]*phik[s,r], per (bh, chunk).
// A = v^T via ldmatrix.trans; B = phikT rows (standard).
// ksum partial computed scalar from phikT smem tiles.
// ============================================================
__global__ __launch_bounds__(256) void kvsum_tc(
    const __nv_bfloat16* __restrict__ pkth, const __nv_bfloat16* __restrict__ pktl,
    const __nv_bfloat16* __restrict__ vh, const __nv_bfloat16* __restrict__ vl,
    float* __restrict__ kvtp, float* __restrict__ ksp)
{
    __shared__ __align__(16) char sm[4 * 64 * 144];   // 36864
    const uint32_t sb = smem_to_u32(sm);
    const uint32_t VHI = 0, VLO = 9216, PKH = 18432, PKL = 27648;

    const int tid = threadIdx.x;
    const int wid = tid >> 5, lane = tid & 31;
    const int chunk = blockIdx.x, bh = blockIdx.y;
    const int b = bh >> 3, h = bh & 7;
    const int warp_m = wid & 1, warp_n = wid >> 1;
    const int mat = lane >> 3, mr = lane & 7;
    const int g = lane >> 2, t = lane & 3;

    float acc[2][2][4];
#pragma unroll
    for (int i = 0; i < 2; i++)
#pragma unroll
        for (int j = 0; j < 2; j++)
#pragma unroll
            for (int e = 0; e < 4; e++) acc[i][j][e] = 0.f;
    float kacc = 0.f;

    const int lr = tid >> 2, lq = tid & 3;
    const int kr = tid & 63, kg = tid >> 6;

    for (int step = 0; step < 8; step++) {
        const int s0 = chunk * 512 + step * 64;
        {
            const size_t vo = (size_t)(b * SS + s0 + lr) * DD + h * HDIM + lq * 16;
            *(uint4*)(sm + VHI + lr * 144 + lq * 32) = *(const uint4*)(vh + vo);
            *(uint4*)(sm + VHI + lr * 144 + lq * 32 + 16) = *(const uint4*)(vh + vo + 8);
            *(uint4*)(sm + VLO + lr * 144 + lq * 32) = *(const uint4*)(vl + vo);
            *(uint4*)(sm + VLO + lr * 144 + lq * 32 + 16) = *(const uint4*)(vl + vo + 8);
            const size_t po = ((size_t)bh * RR + lr) * SS + s0 + lq * 16;
            *(uint4*)(sm + PKH + lr * 144 + lq * 32) = *(const uint4*)(pkth + po);
            *(uint4*)(sm + PKH + lr * 144 + lq * 32 + 16) = *(const uint4*)(pkth + po + 8);
            *(uint4*)(sm + PKL + lr * 144 + lq * 32) = *(const uint4*)(pktl + po);
            *(uint4*)(sm + PKL + lr * 144 + lq * 32 + 16) = *(const uint4*)(pktl + po + 8);
        }
        __syncthreads();

        // ksum partial: row kr, cols kg*16..+15
#pragma unroll
        for (int c = 0; c < 16; c++) {
            int sc = kg * 16 + c;
            kacc += __bfloat162float(*(__nv_bfloat16*)(sm + PKH + kr * 144 + sc * 2))
                  + __bfloat162float(*(__nv_bfloat16*)(sm + PKL + kr * 144 + sc * 2));
        }

#pragma unroll
        for (int kk = 0; kk < 4; kk++) {
            // A = v^T (trans ldmatrix): tiles (d, s)
            uint32_t ah[2][4], al[2][4];
#pragma unroll
            for (int im = 0; im < 2; im++) {
                const int d0 = warp_m * 32 + im * 16 + (mat & 1) * 8;
                const int srow = kk * 16 + ((mat >> 1) & 1) * 8 + mr;
                ldsm4t(ah[im][0], ah[im][1], ah[im][2], ah[im][3],
                       sb + VHI + srow * 144 + d0 * 2);
                ldsm4t(al[im][0], al[im][1], al[im][2], al[im][3],
                       sb + VLO + srow * 144 + d0 * 2);
            }
            // B = phikT rows r (standard)
            const int rrow = warp_n * 16 + (mat & 1) * 8 + mr;
            const int chb = kk * 2 + (mat >> 1);
            uint32_t h0, h1, h2, h3, l0, l1, l2, l3;
            ldsm4(h0, h1, h2, h3, sb + PKH + rrow * 144 + chb * 16);
            ldsm4(l0, l1, l2, l3, sb + PKL + rrow * 144 + chb * 16);
            uint32_t bh0[2] = {h0, h2}, bh1[2] = {h1, h3};
            uint32_t bl0[2] = {l0, l2}, bl1[2] = {l1, l3};
#pragma unroll
            for (int im = 0; im < 2; im++) {
                mma16816(acc[im][0], ah[im], bh0);
                mma16816(acc[im][0], ah[im], bl0);
                mma16816(acc[im][0], al[im], bh0);
                mma16816(acc[im][1], ah[im], bh1);
                mma16816(acc[im][1], ah[im], bl1);
                mma16816(acc[im][1], al[im], bh1);
            }
        }
        __syncthreads();
    }

    // write kvT partials [bh][chunk][d][r]
    float* outp = kvtp + ((size_t)bh * NCHUNK + chunk) * (HDIM * RR);
#pragma unroll
    for (int im = 0; im < 2; im++) {
        const int d = warp_m * 32 + im * 16 + g;
#pragma unroll
        for (int nb = 0; nb < 2; nb++) {
            const int r = warp_n * 16 + nb * 8 + t * 2;
            *(float2*)&outp[d * RR + r] =
                make_float2(acc[im][nb][0], acc[im][nb][1]);
            *(float2*)&outp[(d + 8) * RR + r] =
                make_float2(acc[im][nb][2], acc[im][nb][3]);
        }
    }
    // ksum reduce across 4 groups
    __syncthreads();
    float* red = (float*)sm;
    red[kg * 64 + kr] = kacc;
    __syncthreads();
    if (tid < 64)
        ksp[((size_t)bh * NCHUNK + chunk) * RR + tid] =
            red[tid] + red[64 + tid] + red[128 + tid] + red[192 + tid];
}

// reduce partials -> kvT bf16 hi/lo + ksum fp32
__global__ void reduce2(const float* __restrict__ kvtp,
                        const float* __restrict__ ksp,
                        __nv_bfloat16* __restrict__ kvth,
                        __nv_bfloat16* __restrict__ kvtl,
                        float* __restrict__ ks)
{
    const int idx = blockIdx.x * 256 + threadIdx.x;
    const int total = BH * HDIM * RR;   // 131072
    if (idx < total) {
        int bh = idx >> 12, e = idx & 4095;
        float s = 0.f;
#pragma unroll
        for (int c = 0; c < NCHUNK; c++)
            s += kvtp[((size_t)bh * NCHUNK + c) * 4096 + e];
        __nv_bfloat16 hi = __float2bfloat16_rn(s);
        kvth[idx] = hi;
        kvtl[idx] = __float2bfloat16_rn(s - __bfloat162float(hi));
    } else if (idx < total + BH * RR) {
        int j = idx - total;
        int bh = j >> 6, r = j & 63;
        float s = 0.f;
#pragma unroll
        for (int c = 0; c < NCHUNK; c++)
            s += ksp[((size_t)bh * NCHUNK + c) * RR + r];
        ks[j] = s;
    }
}

// ============================================================
// TC attn: num[s][d] = phiq[s,:] @ kvT[d,:]; out = num * (1/den);
// den = phiq . ksum + eps  (scalar, reciprocal cached).
// CTA = (s-tile 128, bh). Output written as bf16 hi/lo.
// ============================================================
#define AT_PQH 0
#define AT_PQL (128 * 144)
#define AT_KVH (2 * 128 * 144)
#define AT_KVL (AT_KVH + 64 * 144)
#define AT_KS  (AT_KVL + 64 * 144)
#define AT_DEN (AT_KS + 256)
#define AT_SMEM (AT_DEN + 512 + 256)

__global__ __launch_bounds__(256) void attn_tc(
    const __nv_bfloat16* __restrict__ pqh, const __nv_bfloat16* __restrict__ pql,
    const __nv_bfloat16* __restrict__ kvth, const __nv_bfloat16* __restrict__ kvtl,
    const float* __restrict__ ks,
    __nv_bfloat16* __restrict__ ahi, __nv_bfloat16* __restrict__ alo)
{
    extern __shared__ char sm[];
    const uint32_t sb = smem_to_u32(sm);
    const int tid = threadIdx.x;
    const int wid = tid >> 5, lane = tid & 31;
    const int stile = blockIdx.x, bh = blockIdx.y;
    const int b = bh >> 3, h = bh & 7;
    const int sbase = stile * 128;
    const int warp_m = wid >> 1, warp_n = wid & 1;

    // load phiq tiles [128][64] hi/lo
    {
        const int row = tid >> 1, half = tid & 1;
        size_t gbase = ((size_t)bh * SS + sbase + row) * RR + half * 32;
        uint4* dstH = (uint4*)(sm + AT_PQH + row * 144 + half * 64);
        uint4* dstL = (uint4*)(sm + AT_PQL + row * 144 + half * 64);
#pragma unroll
        for (int i = 0; i < 4; i++) dstH[i] = ((const uint4*)(pqh + gbase))[i];
#pragma unroll
        for (int i = 0; i < 4; i++) dstL[i] = ((const uint4*)(pql + gbase))[i];
    }
    // load kvT [64][64] hi/lo
    {
        const int row = tid >> 2, q4 = tid & 3;
        size_t gbase = (size_t)bh * (HDIM * RR) + row * RR + q4 * 16;
        *(uint4*)(sm + AT_KVH + row * 144 + q4 * 32) = *(const uint4*)(kvth + gbase);
        *(uint4*)(sm + AT_KVH + row * 144 + q4 * 32 + 16) = *(const uint4*)(kvth + gbase + 8);
        *(uint4*)(sm + AT_KVL + row * 144 + q4 * 32) = *(const uint4*)(kvtl + gbase);
        *(uint4*)(sm + AT_KVL + row * 144 + q4 * 32 + 16) = *(const uint4*)(kvtl + gbase + 8);
    }
    if (tid < 64) ((float*)(sm + AT_KS))[tid] = ks[bh * RR + tid];
    __syncthreads();

    // den reciprocal per s row
    if (tid < 128) {
        float d = 1e-6f;
        const float* kss = (const float*)(sm + AT_KS);
#pragma unroll 16
        for (int r = 0; r < 64; r++) {
            float p = __bfloat162float(*(__nv_bfloat16*)(sm + AT_PQH + tid * 144 + r * 2))
                    + __bfloat162float(*(__nv_bfloat16*)(sm + AT_PQL + tid * 144 + r * 2));
            d += p * kss[r];
        }
        ((float*)(sm + AT_DEN))[tid] = 1.0f / d;
    }
    __syncthreads();

    float acc[2][4][4];
#pragma unroll
    for (int i = 0; i < 2; i++)
#pragma unroll
        for (int j = 0; j < 4; j++)
#pragma unroll
            for (int e = 0; e < 4; e++) acc[i][j][e] = 0.f;

    const int mat = lane >> 3, mr = lane & 7;
    const int a_row_b = warp_m * 32 + (mat & 1) * 8 + mr;
    const int b_row_b = warp_n * 32 + (mat & 1) * 8 + mr;
    const int mchunk = mat >> 1;

#pragma unroll
    for (int kk = 0; kk < 4; kk++) {
        const int ch = kk * 2 + mchunk;
        uint32_t ah[2][4], al[2][4];
#pragma unroll
        for (int im = 0; im < 2; im++) {
            const int row = a_row_b + im * 16;
            ldsm4(ah[im][0], ah[im][1], ah[im][2], ah[im][3],
                  sb + AT_PQH + row * 144 + ch * 16);
            ldsm4(al[im][0], al[im][1], al[im][2], al[im][3],
                  sb + AT_PQL + row * 144 + ch * 16);
        }
#pragma unroll
        for (int nt = 0; nt < 2; nt++) {
            const int row = b_row_b + nt * 16;
            uint32_t h0, h1, h2, h3, l0, l1, l2, l3;
            ldsm4(h0, h1, h2, h3, sb + AT_KVH + row * 144 + ch * 16);
            ldsm4(l0, l1, l2, l3, sb + AT_KVL + row * 144 + ch * 16);
            uint32_t bh0[2] = {h0, h2}, bh1[2] = {h1, h3};
            uint32_t bl0[2] = {l0, l2}, bl1[2] = {l1, l3};
#pragma unroll
            for (int im = 0; im < 2; im++) {
                mma16816(acc[im][nt * 2], ah[im], bh0);
                mma16816(acc[im][nt * 2], ah[im], bl0);
                mma16816(acc[im][nt * 2], al[im], bh0);
                mma16816(acc[im][nt * 2 + 1], ah[im], bh1);
                mma16816(acc[im][nt * 2 + 1], ah[im], bl1);
                mma16816(acc[im][nt * 2 + 1], al[im], bh1);
            }
        }
    }

    // epilogue
    const int g = lane >> 2, t = lane & 3;
    const float* rden = (const float*)(sm + AT_DEN);
#pragma unroll
    for (int im = 0; im < 2; im++) {
        const int s0 = warp_m * 32 + im * 16 + g;
        const float rd0 = rden[s0], rd1 = rden[s0 + 8];
        const size_t row0 = ((size_t)b * SS + sbase + s0) * DD + h * HDIM;
        const size_t row1 = row0 + 8 * DD;
#pragma unroll
        for (int j8 = 0; j8 < 4; j8++) {
            const int d = warp_n * 32 + j8 * 8 + t * 2;
            uint32_t hp, lp;
            split2(acc[im][j8][0] * rd0, acc[im][j8][1] * rd0, hp, lp);
            *(uint32_t*)(ahi + row0 + d) = hp;
            *(uint32_t*)(alo + row0 + d) = lp;
            split2(acc[im][j8][2] * rd1, acc[im][j8][3] * rd1, hp, lp);
            *(uint32_t*)(ahi + row1 + d) = hp;
            *(uint32_t*)(alo + row1 + d) = lp;
        }
    }
}

// ============================================================
// launch
// ============================================================
extern "C" void kernel_launch(void* const* d_in, const int* in_sizes, int n_in,
                              void* d_out, int out_size)
{
    const float* x       = (const float*)d_in[0];
    const float* Wq      = (const float*)d_in[1];
    const float* bq      = (const float*)d_in[2];
    const float* Wk      = (const float*)d_in[3];
    const float* bk      = (const float*)d_in[4];
    const float* Wv      = (const float*)d_in[5];
    const float* bv      = (const float*)d_in[6];
    const float* Wp      = (const float*)d_in[7];
    const float* bp      = (const float*)d_in[8];
    const float* gamma_q = (const float*)d_in[9];
    const float* beta_q  = (const float*)d_in[10];
    const float* gamma_k = (const float*)d_in[11];
    const float* beta_k  = (const float*)d_in[12];
    const float* qG1     = (const float*)d_in[13];
    const float* qG2     = (const float*)d_in[14];
    const float* kG1     = (const float*)d_in[15];
    const float* kG2     = (const float*)d_in[16];
    float* out = (float*)d_out;

    float *p_q, *p_k, *p_bqkv, *p_kvtp, *p_ksp, *p_ks;
    __nv_bfloat16 *p_xhi, *p_xlo, *p_ahi, *p_alo, *p_wthi, *p_wtlo;
    __nv_bfloat16 *p_vh, *p_vl, *p_pqh, *p_pql, *p_pkth, *p_pktl, *p_kvth, *p_kvtl;
    cudaGetSymbolAddress((void**)&p_q, g_q);
    cudaGetSymbolAddress((void**)&p_k, g_k);
    cudaGetSymbolAddress((void**)&p_vh, g_vh);
    cudaGetSymbolAddress((void**)&p_vl, g_vl);
    cudaGetSymbolAddress((void**)&p_bqkv, g_biasqkv);
    cudaGetSymbolAddress((void**)&p_xhi, g_xhi);
    cudaGetSymbolAddress((void**)&p_xlo, g_xlo);
    cudaGetSymbolAddress((void**)&p_ahi, g_ahi);
    cudaGetSymbolAddress((void**)&p_alo, g_alo);
    cudaGetSymbolAddress((void**)&p_wthi, g_wthi);
    cudaGetSymbolAddress((void**)&p_wtlo, g_wtlo);
    cudaGetSymbolAddress((void**)&p_pqh, g_pqh);
    cudaGetSymbolAddress((void**)&p_pql, g_pql);
    cudaGetSymbolAddress((void**)&p_pkth, g_pkth);
    cudaGetSymbolAddress((void**)&p_pktl, g_pktl);
    cudaGetSymbolAddress((void**)&p_kvtp, g_kvtp);
    cudaGetSymbolAddress((void**)&p_ksp, g_ksp);
    cudaGetSymbolAddress((void**)&p_kvth, g_kvth);
    cudaGetSymbolAddress((void**)&p_kvtl, g_kvtl);
    cudaGetSymbolAddress((void**)&p_ks, g_ks);

    cudaFuncSetAttribute(mma_gemm, cudaFuncAttributeMaxDynamicSharedMemorySize,
                         GEMM_SMEM);
    cudaFuncSetAttribute(sketch_tc2, cudaFuncAttributeMaxDynamicSharedMemorySize,
                         SK_SMEM);
    cudaFuncSetAttribute(attn_tc, cudaFuncAttributeMaxDynamicSharedMemorySize,
                         AT_SMEM);

    // ---- prep ----
    split_fp32<<<BSROWS * DD / 4 / 256, 256>>>(x, p_xhi, p_xlo);
    concat_bias<<<6, 256>>>(bq, bk, bv, p_bqkv);
    g_prep<<<2, 256>>>(qG1, qG2, kG1, kG2);
    dim3 tg(16, 16);
    transpose_split<<<tg, 256>>>(Wq, p_wthi, p_wtlo, 0);
    transpose_split2<<<dim3(16, 16, 2), 256>>>(Wk, Wv, p_wthi, p_wtlo,
                                               512, 1024);

    // ---- fused QKV GEMM ----
    dim3 gq(6, BSROWS / 128);
    mma_gemm<<<gq, 256, GEMM_SMEM>>>(p_xhi, p_xlo, p_wthi, p_wtlo, p_bqkv,
                                     p_q, p_k, p_vh, p_vl);

    // ---- fused TC sketch (q & k) ----
    dim3 skg(BSROWS / 128, HH, 2);
    sketch_tc2<<<skg, 256, SK_SMEM>>>(p_q, p_k, gamma_q, beta_q,
                                      gamma_k, beta_k,
                                      p_pqh, p_pql, p_pkth, p_pktl);

    // ---- TC kvsum + reduce ----
    kvsum_tc<<<dim3(NCHUNK, BH), 256>>>(p_pkth, p_pktl, p_vh, p_vl,
                                        p_kvtp, p_ksp);
    int red_total = BH * HDIM * RR + BH * RR;
    reduce2<<<(red_total + 255) / 256, 256>>>(p_kvtp, p_ksp,
                                              p_kvth, p_kvtl, p_ks);

    // ---- TC attention output ----
    attn_tc<<<dim3(SS / 128, BH), 256, AT_SMEM>>>(p_pqh, p_pql,
                                                  p_kvth, p_kvtl, p_ks,
                                                  p_ahi, p_alo);

    transpose_split<<<tg, 256>>>(Wp, p_wthi, p_wtlo, 1536);

    // ---- output projection ----
    dim3 go(2, BSROWS / 128);
    mma_gemm<<<go, 256, GEMM_SMEM>>>(p_ahi, p_alo,
                                     p_wthi + 1536 * DD, p_wtlo + 1536 * DD,
                                     bp, out, out, p_vh, p_vl);
}

// round 9
// speedup vs baseline: 1.6040x; 1.2668x over previous
#include <cuda_runtime.h>
#include <cuda_fp16.h>
#include <cstdint>

// Problem constants
#define BB 4
#define SS 8192
#define DD 512
#define HH 8
#define HDIM 64
#define RR 64
#define BSROWS (BB * SS)      // 32768
#define BH (BB * HH)          // 32
#define NCHUNK 16

// -------- scratch (static device globals; no allocation) --------
__device__ __half g_xhi[BSROWS * DD];
__device__ __half g_xlo[BSROWS * DD];
__device__ __half g_qh[BSROWS * DD];
__device__ __half g_ql[BSROWS * DD];
__device__ __half g_kh[BSROWS * DD];
__device__ __half g_kl[BSROWS * DD];
__device__ __half g_vh[BSROWS * DD];
__device__ __half g_vl[BSROWS * DD];
__device__ __half g_ahi[BSROWS * DD];
__device__ __half g_alo[BSROWS * DD];
__device__ __half g_wth[4 * DD * DD];     // fp16 transposed weights (hi only)
__device__ float g_biasqkv[3 * DD];
__device__ __half g_gint_hi[2][128 * 64];
__device__ __half g_gint_lo[2][128 * 64];
__device__ __half g_pqh[BH * SS * RR];
__device__ __half g_pql[BH * SS * RR];
__device__ __half g_pkth[BH * RR * SS];
__device__ __half g_pktl[BH * RR * SS];
__device__ float g_kvtp[BH * NCHUNK * HDIM * RR];
__device__ float g_ksp[BH * NCHUNK * RR];
__device__ __half g_kvth[BH * HDIM * RR];
__device__ __half g_kvtl[BH * HDIM * RR];
__device__ float g_ks[BH * RR];

// ============================================================
// helpers
// ============================================================
__device__ __forceinline__ uint32_t smem_to_u32(const void* p) {
    uint32_t a;
    asm("{ .reg .u64 t; cvta.to.shared.u64 t, %1; cvt.u32.u64 %0, t; }"
        : "=r"(a) : "l"(p));
    return a;
}
__device__ __forceinline__ void ldsm4(uint32_t& r0, uint32_t& r1,
                                      uint32_t& r2, uint32_t& r3,
                                      uint32_t addr) {
    asm volatile("ldmatrix.sync.aligned.m8n8.x4.shared.b16 {%0,%1,%2,%3}, [%4];"
                 : "=r"(r0), "=r"(r1), "=r"(r2), "=r"(r3) : "r"(addr));
}
__device__ __forceinline__ void ldsm4t(uint32_t& r0, uint32_t& r1,
                                       uint32_t& r2, uint32_t& r3,
                                       uint32_t addr) {
    asm volatile("ldmatrix.sync.aligned.m8n8.x4.trans.shared.b16 {%0,%1,%2,%3}, [%4];"
                 : "=r"(r0), "=r"(r1), "=r"(r2), "=r"(r3) : "r"(addr));
}
__device__ __forceinline__ void mma16816(float* d, const uint32_t* a,
                                         const uint32_t* b) {
    asm volatile(
        "mma.sync.aligned.m16n8k16.row.col.f32.f16.f16.f32 "
        "{%0,%1,%2,%3}, {%4,%5,%6,%7}, {%8,%9}, {%0,%1,%2,%3};"
        : "+f"(d[0]), "+f"(d[1]), "+f"(d[2]), "+f"(d[3])
        : "r"(a[0]), "r"(a[1]), "r"(a[2]), "r"(a[3]), "r"(b[0]), "r"(b[1]));
}
#define CP_ASYNC16(dst, src) \
    asm volatile("cp.async.cg.shared.global [%0], [%1], 16;" :: "r"(dst), "l"(src))
#define CP_COMMIT() asm volatile("cp.async.commit_group;" ::: "memory")
#define CP_WAIT(n)  asm volatile("cp.async.wait_group %0;" :: "n"(n) : "memory")

__device__ __forceinline__ void split4h(float4 v, uint2& hi, uint2& lo) {
    __half h0 = __float2half_rn(v.x), h1 = __float2half_rn(v.y);
    __half h2 = __float2half_rn(v.z), h3 = __float2half_rn(v.w);
    float r0 = v.x - __half2float(h0), r1 = v.y - __half2float(h1);
    float r2 = v.z - __half2float(h2), r3 = v.w - __half2float(h3);
    __half l0 = __float2half_rn(r0), l1 = __float2half_rn(r1);
    __half l2 = __float2half_rn(r2), l3 = __float2half_rn(r3);
    hi.x = ((uint32_t)__half_as_ushort(h1) << 16) | __half_as_ushort(h0);
    hi.y = ((uint32_t)__half_as_ushort(h3) << 16) | __half_as_ushort(h2);
    lo.x = ((uint32_t)__half_as_ushort(l1) << 16) | __half_as_ushort(l0);
    lo.y = ((uint32_t)__half_as_ushort(l3) << 16) | __half_as_ushort(l2);
}
__device__ __forceinline__ void split2h(float a, float b, uint32_t& hp, uint32_t& lp) {
    __half h0 = __float2half_rn(a), h1 = __float2half_rn(b);
    float l0 = a - __half2float(h0), l1 = b - __half2float(h1);
    __half e0 = __float2half_rn(l0), e1 = __float2half_rn(l1);
    hp = ((uint32_t)__half_as_ushort(h1) << 16) | __half_as_ushort(h0);
    lp = ((uint32_t)__half_as_ushort(e1) << 16) | __half_as_ushort(e0);
}

// ============================================================
// prep kernels
// ============================================================
__global__ __launch_bounds__(256) void split_fp32(
    const float* __restrict__ X, __half* __restrict__ Xh,
    __half* __restrict__ Xl)
{
    int i = blockIdx.x * 256 + threadIdx.x;
    float4 v = ((const float4*)X)[i];
    uint2 hi, lo;
    split4h(v, hi, lo);
    ((uint2*)Xh)[i] = hi;
    ((uint2*)Xl)[i] = lo;
}

// transpose two weight matrices (z selects), optional gamma scaling
__global__ __launch_bounds__(256) void transpose_h2(
    const float* __restrict__ W0, const float* __restrict__ W1,
    const float* __restrict__ g0, const float* __restrict__ g1,
    __half* __restrict__ Th, int rowoff0, int rowoff1)
{
    __shared__ float t[32][33];
    const float* W = blockIdx.z ? W1 : W0;
    const float* gp = blockIdx.z ? g1 : g0;
    const float scale = gp ? gp[0] : 1.0f;
    const int rowoff = blockIdx.z ? rowoff1 : rowoff0;
    int bx = blockIdx.x * 32, by = blockIdx.y * 32;
    int x = threadIdx.x & 31, y = threadIdx.x >> 5;
    for (int i = y; i < 32; i += 8) t[i][x] = W[(size_t)(by + i) * DD + bx + x];
    __syncthreads();
    for (int i = y; i < 32; i += 8)
        Th[(size_t)(rowoff + bx + i) * DD + by + x] = __float2half_rn(t[x][i] * scale);
}

// biases: fold affine (gamma*b + beta) for q,k
__global__ void concat_bias(const float* bq, const float* bk, const float* bv,
                            const float* gq, const float* betq,
                            const float* gk, const float* betk,
                            float* bout)
{
    int i = blockIdx.x * 256 + threadIdx.x;
    if (i < DD) bout[i] = gq[0] * bq[i] + betq[0];
    else if (i < 2 * DD) bout[i] = gk[0] * bk[i - DD] + betk[0];
    else if (i < 3 * DD) bout[i] = bv[i - 2 * DD];
}

__global__ __launch_bounds__(256) void g_prep(
    const float* __restrict__ qG1, const float* __restrict__ qG2,
    const float* __restrict__ kG1, const float* __restrict__ kG2)
{
    const int set = blockIdx.x;
    const float* G1 = set ? kG1 : qG1;
    const float* G2 = set ? kG2 : qG2;
    __half* Oh = g_gint_hi[set];
    __half* Ol = g_gint_lo[set];
    for (int it = 0; it < 32; it++) {
        int idx = it * 256 + threadIdx.x;
        int n = idx >> 6, k = idx & 63;
        float v = ((n & 1) ? G2 : G1)[k * 64 + (n >> 1)];
        __half h = __float2half_rn(v);
        Oh[idx] = h;
        Ol[idx] = __float2half_rn(v - __half2float(h));
    }
}

// ============================================================
// fp16 2-pass split GEMM: C = (Ahi+Alo) @ Bh^T + bias.
// CTA tile 128x256, 8 warps (2m x 4n), warp tile 64x64.
// cp.async 4-stage pipeline, unconditional commits.
// QKV mode (ofp32==null): outputs fp16 hi/lo, sel = bn>>1.
// Proj mode (ofp32 set): fp32 output.
// ============================================================
#define BKC 32
#define NKCH (DD / BKC)          // 16
#define ROWB 80
#define TILE_A (128 * ROWB)      // 10240
#define TILE_B (256 * ROWB)      // 20480
#define ST_AHI 0
#define ST_ALO TILE_A
#define ST_BH (2 * TILE_A)
#define STAGEB (2 * TILE_A + TILE_B)   // 40960
#define PIPE 4
#define GEMM_SMEM (PIPE * STAGEB)      // 163840
#define OFF80(row, ch) ((uint32_t)((row) * ROWB + ((ch) << 4)))

__global__ __launch_bounds__(256, 1) void mma_gemm(
    const __half* __restrict__ Ahi, const __half* __restrict__ Alo,
    const __half* __restrict__ Bh, const float* __restrict__ bias,
    __half* __restrict__ o0h, __half* __restrict__ o0l,
    __half* __restrict__ o1h, __half* __restrict__ o1l,
    __half* __restrict__ o2h, __half* __restrict__ o2l,
    float* __restrict__ ofp32)
{
    extern __shared__ char smem[];
    const uint32_t sb = smem_to_u32(smem);

    const int tid = threadIdx.x;
    const int wid = tid >> 5, lane = tid & 31;
    const int bn = blockIdx.x, bm = blockIdx.y;
    const int warp_m = wid & 1, warp_n = wid >> 1;

    const __half* Ahi_b = Ahi + (size_t)bm * 128 * DD;
    const __half* Alo_b = Alo + (size_t)bm * 128 * DD;
    const __half* Bh_b = Bh + (size_t)bn * 256 * DD;

    const int lrow = tid >> 2;
    const int lch = tid & 3;

    auto load_chunk = [&](int c, int s) {
        const uint32_t stg = sb + s * STAGEB;
        const int k0 = c * BKC;
#pragma unroll
        for (int sw = 0; sw < 2; sw++) {
            const int row = sw * 64 + lrow;
            const size_t go = (size_t)row * DD + k0 + lch * 8;
            const uint32_t so = OFF80(row, lch);
            CP_ASYNC16(stg + ST_AHI + so, Ahi_b + go);
            CP_ASYNC16(stg + ST_ALO + so, Alo_b + go);
        }
#pragma unroll
        for (int sw = 0; sw < 4; sw++) {
            const int row = sw * 64 + lrow;
            const size_t go = (size_t)row * DD + k0 + lch * 8;
            CP_ASYNC16(stg + ST_BH + OFF80(row, lch), Bh_b + go);
        }
    };

    float acc[4][8][4];
#pragma unroll
    for (int i = 0; i < 4; i++)
#pragma unroll
        for (int j = 0; j < 8; j++)
#pragma unroll
            for (int e = 0; e < 4; e++) acc[i][j][e] = 0.f;

    const int mat = lane >> 3, mr = lane & 7;
    const int a_row_b = warp_m * 64 + (mat & 1) * 8 + mr;
    const int b_row_b = warp_n * 64 + (mat & 1) * 8 + mr;
    const int mchunk = mat >> 1;

    load_chunk(0, 0); CP_COMMIT();
    load_chunk(1, 1); CP_COMMIT();
    load_chunk(2, 2); CP_COMMIT();

    for (int c = 0; c < NKCH; c++) {
        CP_WAIT(2);
        __syncthreads();
        if (c + 3 < NKCH) load_chunk(c + 3, (c + 3) % PIPE);
        CP_COMMIT();

        const uint32_t stg = sb + (c % PIPE) * STAGEB;
#pragma unroll
        for (int kk = 0; kk < 2; kk++) {
            const int ch = kk * 2 + mchunk;
            uint32_t ahi[4][4], alo[4][4];
#pragma unroll
            for (int im = 0; im < 4; im++) {
                const int row = a_row_b + im * 16;
                ldsm4(ahi[im][0], ahi[im][1], ahi[im][2], ahi[im][3],
                      stg + ST_AHI + OFF80(row, ch));
                ldsm4(alo[im][0], alo[im][1], alo[im][2], alo[im][3],
                      stg + ST_ALO + OFF80(row, ch));
            }
#pragma unroll
            for (int j16 = 0; j16 < 4; j16++) {
                const int row = b_row_b + j16 * 16;
                uint32_t h0, h1, h2, h3;
                ldsm4(h0, h1, h2, h3, stg + ST_BH + OFF80(row, ch));
                uint32_t bh0[2] = {h0, h2}, bh1[2] = {h1, h3};
#pragma unroll
                for (int im = 0; im < 4; im++) {
                    mma16816(acc[im][j16 * 2], ahi[im], bh0);
                    mma16816(acc[im][j16 * 2], alo[im], bh0);
                    mma16816(acc[im][j16 * 2 + 1], ahi[im], bh1);
                    mma16816(acc[im][j16 * 2 + 1], alo[im], bh1);
                }
            }
        }
    }

    const int erow = lane >> 2, ecol = (lane & 3) * 2;
    if (ofp32) {
        const int colbase = bn * 256;
#pragma unroll
        for (int im = 0; im < 4; im++) {
            const size_t row0 = (size_t)bm * 128 + warp_m * 64 + im * 16 + erow;
#pragma unroll
            for (int t = 0; t < 8; t++) {
                const int cofs = warp_n * 64 + t * 8 + ecol;
                float2 b2 = *(const float2*)&bias[colbase + cofs];
                float2 q0 = make_float2(acc[im][t][0] + b2.x, acc[im][t][1] + b2.y);
                float2 q1 = make_float2(acc[im][t][2] + b2.x, acc[im][t][3] + b2.y);
                *(float2*)&ofp32[row0 * DD + colbase + cofs] = q0;
                *(float2*)&ofp32[(row0 + 8) * DD + colbase + cofs] = q1;
            }
        }
    } else {
        const int sel = bn >> 1;
        const int colbase = (bn & 1) * 256;
        __half* oh = sel == 0 ? o0h : (sel == 1 ? o1h : o2h);
        __half* ol = sel == 0 ? o0l : (sel == 1 ? o1l : o2l);
#pragma unroll
        for (int im = 0; im < 4; im++) {
            const size_t row0 = (size_t)bm * 128 + warp_m * 64 + im * 16 + erow;
#pragma unroll
            for (int t = 0; t < 8; t++) {
                const int cofs = warp_n * 64 + t * 8 + ecol;
                float2 b2 = *(const float2*)&bias[bn * 256 + cofs];
                uint32_t hp, lp;
                split2h(acc[im][t][0] + b2.x, acc[im][t][1] + b2.y, hp, lp);
                *(uint32_t*)(oh + row0 * DD + colbase + cofs) = hp;
                *(uint32_t*)(ol + row0 * DD + colbase + cofs) = lp;
                split2h(acc[im][t][2] + b2.x, acc[im][t][3] + b2.y, hp, lp);
                *(uint32_t*)(oh + (row0 + 8) * DD + colbase + cofs) = hp;
                *(uint32_t*)(ol + (row0 + 8) * DD + colbase + cofs) = lp;
            }
        }
    }
}

// ============================================================
// TC sketch (3-pass fp16, q & k via blockIdx.z):
// A = z (fp16 hi/lo, affine pre-folded); B = interleaved [G1^T|G2^T] hi/lo.
// phi = ((u*w)/8)^2, split fp16. set0: phiq [s][r]; set1: phikT [r][s].
// ============================================================
#define SKROWB 144
#define SK_AHI 0
#define SK_ALO (128 * SKROWB)
#define SK_BHI (2 * 128 * SKROWB)
#define SK_BLO (3 * 128 * SKROWB)
#define SK_SMEM (4 * 128 * SKROWB)   // 73728
#define SOFF(row, ch) ((uint32_t)((row) * SKROWB + ((ch) << 4)))

__global__ __launch_bounds__(256, 2) void sketch_tc2(
    const __half* __restrict__ Qh, const __half* __restrict__ Ql,
    const __half* __restrict__ Kh, const __half* __restrict__ Kl,
    __half* __restrict__ pqh, __half* __restrict__ pql,
    __half* __restrict__ pkth, __half* __restrict__ pktl)
{
    extern __shared__ char smem[];
    const uint32_t sb = smem_to_u32(smem);
    const int tid = threadIdx.x;
    const int wid = tid >> 5, lane = tid & 31;
    const int bm = blockIdx.x, h = blockIdx.y, set = blockIdx.z;
    const int warp_m = wid & 1, warp_n = wid >> 1;

    const __half* Zh = set ? Kh : Qh;
    const __half* Zl = set ? Kl : Ql;
    const __half* Gh = &g_gint_hi[set][0];
    const __half* Gl = &g_gint_lo[set][0];

    // load z tile [128 x 64] fp16 hi/lo (pure copies, no conversion)
#pragma unroll
    for (int it = 0; it < 4; it++) {
        const int cidx = it * 256 + tid;     // 1024 chunks of 16B per tile
        const int row = cidx >> 3, ch = cidx & 7;
        const size_t go = ((size_t)(bm * 128 + row) * DD + h * HDIM) * 2 + ch * 16;
        *(uint4*)(smem + SK_AHI + SOFF(row, ch)) = *(const uint4*)((const char*)Zh + go);
        *(uint4*)(smem + SK_ALO + SOFF(row, ch)) = *(const uint4*)((const char*)Zl + go);
        *(uint4*)(smem + SK_BHI + SOFF(row, ch)) = *(const uint4*)((const char*)Gh + row * 128 + ch * 16);
        *(uint4*)(smem + SK_BLO + SOFF(row, ch)) = *(const uint4*)((const char*)Gl + row * 128 + ch * 16);
    }
    __syncthreads();

    float acc[4][4][4];
#pragma unroll
    for (int i = 0; i < 4; i++)
#pragma unroll
        for (int j = 0; j < 4; j++)
#pragma unroll
            for (int e = 0; e < 4; e++) acc[i][j][e] = 0.f;

    const int mat = lane >> 3, mr = lane & 7;
    const int a_row_b = warp_m * 64 + (mat & 1) * 8 + mr;
    const int b_row_b = warp_n * 32 + (mat & 1) * 8 + mr;
    const int mchunk = mat >> 1;

#pragma unroll
    for (int kk = 0; kk < 4; kk++) {
        const int ch = kk * 2 + mchunk;
        uint32_t ahi[4][4], alo[4][4];
#pragma unroll
        for (int im = 0; im < 4; im++) {
            const int row = a_row_b + im * 16;
            ldsm4(ahi[im][0], ahi[im][1], ahi[im][2], ahi[im][3],
                  sb + SK_AHI + SOFF(row, ch));
            ldsm4(alo[im][0], alo[im][1], alo[im][2], alo[im][3],
                  sb + SK_ALO + SOFF(row, ch));
        }
#pragma unroll
        for (int j16 = 0; j16 < 2; j16++) {
            const int row = b_row_b + j16 * 16;
            uint32_t h0, h1, h2, h3, l0, l1, l2, l3;
            ldsm4(h0, h1, h2, h3, sb + SK_BHI + SOFF(row, ch));
            ldsm4(l0, l1, l2, l3, sb + SK_BLO + SOFF(row, ch));
            uint32_t bh0[2] = {h0, h2}, bh1[2] = {h1, h3};
            uint32_t bl0[2] = {l0, l2}, bl1[2] = {l1, l3};
#pragma unroll
            for (int im = 0; im < 4; im++) {
                mma16816(acc[im][j16 * 2], ahi[im], bh0);
                mma16816(acc[im][j16 * 2], ahi[im], bl0);
                mma16816(acc[im][j16 * 2], alo[im], bh0);
                mma16816(acc[im][j16 * 2 + 1], ahi[im], bh1);
                mma16816(acc[im][j16 * 2 + 1], ahi[im], bl1);
                mma16816(acc[im][j16 * 2 + 1], alo[im], bh1);
            }
        }
    }

    const int b = bm >> 6;
    const int sbase = (bm & 63) * 128;
    const int bh = b * HH + h;
    const int g = lane >> 2, t = lane & 3;
    const float inv = 0.125f;

    __syncthreads();

    __half* SH = (__half*)smem;
    if (set == 0) {
        __half* SL = (__half*)(smem + 128 * 144);
#pragma unroll
        for (int im = 0; im < 4; im++) {
            const int s0 = warp_m * 64 + im * 16 + g;
#pragma unroll
            for (int jn = 0; jn < 4; jn++) {
                const int r = warp_n * 16 + jn * 4 + t;
                float h0 = inv * acc[im][jn][0] * acc[im][jn][1];
                float h1 = inv * acc[im][jn][2] * acc[im][jn][3];
                float p0 = h0 * h0, p1 = h1 * h1;
                __half x0 = __float2half_rn(p0);
                __half x1 = __float2half_rn(p1);
                SH[s0 * 72 + r] = x0;
                SH[(s0 + 8) * 72 + r] = x1;
                SL[s0 * 72 + r] = __float2half_rn(p0 - __half2float(x0));
                SL[(s0 + 8) * 72 + r] = __float2half_rn(p1 - __half2float(x1));
            }
        }
        __syncthreads();
        const int row = tid >> 1, half = tid & 1;
        size_t gbase = ((size_t)bh * SS + sbase + row) * RR + half * 32;
        const uint4* srcH = (const uint4*)(smem + row * 144 + half * 64);
        const uint4* srcL = (const uint4*)(smem + 128 * 144 + row * 144 + half * 64);
#pragma unroll
        for (int i = 0; i < 4; i++) ((uint4*)(pqh + gbase))[i] = srcH[i];
#pragma unroll
        for (int i = 0; i < 4; i++) ((uint4*)(pql + gbase))[i] = srcL[i];
    } else {
        __half* SL = (__half*)(smem + 64 * 272);
#pragma unroll
        for (int im = 0; im < 4; im++) {
            const int s0 = warp_m * 64 + im * 16 + g;
#pragma unroll
            for (int jn = 0; jn < 4; jn++) {
                const int r = warp_n * 16 + jn * 4 + t;
                float h0 = inv * acc[im][jn][0] * acc[im][jn][1];
                float h1 = inv * acc[im][jn][2] * acc[im][jn][3];
                float p0 = h0 * h0, p1 = h1 * h1;
                __half x0 = __float2half_rn(p0);
                __half x1 = __float2half_rn(p1);
                SH[r * 136 + s0] = x0;
                SH[r * 136 + s0 + 8] = x1;
                SL[r * 136 + s0] = __float2half_rn(p0 - __half2float(x0));
                SL[r * 136 + s0 + 8] = __float2half_rn(p1 - __half2float(x1));
            }
        }
        __syncthreads();
        const int r = tid >> 2, q4 = tid & 3;
        size_t gbase = ((size_t)bh * RR + r) * SS + sbase + q4 * 32;
        const uint4* srcH = (const uint4*)(smem + r * 272 + q4 * 64);
        const uint4* srcL = (const uint4*)(smem + 64 * 272 + r * 272 + q4 * 64);
#pragma unroll
        for (int i = 0; i < 4; i++) ((uint4*)(pkth + gbase))[i] = srcH[i];
#pragma unroll
        for (int i = 0; i < 4; i++) ((uint4*)(pktl + gbase))[i] = srcL[i];
    }
}

// ============================================================
// TC kvsum (3-pass fp16): kvT[d][r] = sum_s v[s,d]*phik[s,r]
// ============================================================
__global__ __launch_bounds__(256) void kvsum_tc(
    const __half* __restrict__ pkth, const __half* __restrict__ pktl,
    const __half* __restrict__ vh, const __half* __restrict__ vl,
    float* __restrict__ kvtp, float* __restrict__ ksp)
{
    __shared__ __align__(16) char sm[4 * 64 * 144];
    const uint32_t sb = smem_to_u32(sm);
    const uint32_t VHI = 0, VLO = 9216, PKH = 18432, PKL = 27648;

    const int tid = threadIdx.x;
    const int wid = tid >> 5, lane = tid & 31;
    const int chunk = blockIdx.x, bh = blockIdx.y;
    const int b = bh >> 3, h = bh & 7;
    const int warp_m = wid & 1, warp_n = wid >> 1;
    const int mat = lane >> 3, mr = lane & 7;
    const int g = lane >> 2, t = lane & 3;

    float acc[2][2][4];
#pragma unroll
    for (int i = 0; i < 2; i++)
#pragma unroll
        for (int j = 0; j < 2; j++)
#pragma unroll
            for (int e = 0; e < 4; e++) acc[i][j][e] = 0.f;
    float kacc = 0.f;

    const int lr = tid >> 2, lq = tid & 3;
    const int kr = tid & 63, kg = tid >> 6;

    for (int step = 0; step < 8; step++) {
        const int s0 = chunk * 512 + step * 64;
        {
            const size_t vo = (size_t)(b * SS + s0 + lr) * DD + h * HDIM + lq * 16;
            *(uint4*)(sm + VHI + lr * 144 + lq * 32) = *(const uint4*)(vh + vo);
            *(uint4*)(sm + VHI + lr * 144 + lq * 32 + 16) = *(const uint4*)(vh + vo + 8);
            *(uint4*)(sm + VLO + lr * 144 + lq * 32) = *(const uint4*)(vl + vo);
            *(uint4*)(sm + VLO + lr * 144 + lq * 32 + 16) = *(const uint4*)(vl + vo + 8);
            const size_t po = ((size_t)bh * RR + lr) * SS + s0 + lq * 16;
            *(uint4*)(sm + PKH + lr * 144 + lq * 32) = *(const uint4*)(pkth + po);
            *(uint4*)(sm + PKH + lr * 144 + lq * 32 + 16) = *(const uint4*)(pkth + po + 8);
            *(uint4*)(sm + PKL + lr * 144 + lq * 32) = *(const uint4*)(pktl + po);
            *(uint4*)(sm + PKL + lr * 144 + lq * 32 + 16) = *(const uint4*)(pktl + po + 8);
        }
        __syncthreads();

#pragma unroll
        for (int c = 0; c < 16; c++) {
            int sc = kg * 16 + c;
            kacc += __half2float(*(__half*)(sm + PKH + kr * 144 + sc * 2))
                  + __half2float(*(__half*)(sm + PKL + kr * 144 + sc * 2));
        }

#pragma unroll
        for (int kk = 0; kk < 4; kk++) {
            uint32_t ah[2][4], al[2][4];
#pragma unroll
            for (int im = 0; im < 2; im++) {
                const int d0 = warp_m * 32 + im * 16 + (mat & 1) * 8;
                const int srow = kk * 16 + ((mat >> 1) & 1) * 8 + mr;
                ldsm4t(ah[im][0], ah[im][1], ah[im][2], ah[im][3],
                       sb + VHI + srow * 144 + d0 * 2);
                ldsm4t(al[im][0], al[im][1], al[im][2], al[im][3],
                       sb + VLO + srow * 144 + d0 * 2);
            }
            const int rrow = warp_n * 16 + (mat & 1) * 8 + mr;
            const int chb = kk * 2 + (mat >> 1);
            uint32_t h0, h1, h2, h3, l0, l1, l2, l3;
            ldsm4(h0, h1, h2, h3, sb + PKH + rrow * 144 + chb * 16);
            ldsm4(l0, l1, l2, l3, sb + PKL + rrow * 144 + chb * 16);
            uint32_t bh0[2] = {h0, h2}, bh1[2] = {h1, h3};
            uint32_t bl0[2] = {l0, l2}, bl1[2] = {l1, l3};
#pragma unroll
            for (int im = 0; im < 2; im++) {
                mma16816(acc[im][0], ah[im], bh0);
                mma16816(acc[im][0], ah[im], bl0);
                mma16816(acc[im][0], al[im], bh0);
                mma16816(acc[im][1], ah[im], bh1);
                mma16816(acc[im][1], ah[im], bl1);
                mma16816(acc[im][1], al[im], bh1);
            }
        }
        __syncthreads();
    }

    float* outp = kvtp + ((size_t)bh * NCHUNK + chunk) * (HDIM * RR);
#pragma unroll
    for (int im = 0; im < 2; im++) {
        const int d = warp_m * 32 + im * 16 + g;
#pragma unroll
        for (int nb = 0; nb < 2; nb++) {
            const int r = warp_n * 16 + nb * 8 + t * 2;
            *(float2*)&outp[d * RR + r] =
                make_float2(acc[im][nb][0], acc[im][nb][1]);
            *(float2*)&outp[(d + 8) * RR + r] =
                make_float2(acc[im][nb][2], acc[im][nb][3]);
        }
    }
    __syncthreads();
    float* red = (float*)sm;
    red[kg * 64 + kr] = kacc;
    __syncthreads();
    if (tid < 64)
        ksp[((size_t)bh * NCHUNK + chunk) * RR + tid] =
            red[tid] + red[64 + tid] + red[128 + tid] + red[192 + tid];
}

__global__ void reduce2(const float* __restrict__ kvtp,
                        const float* __restrict__ ksp,
                        __half* __restrict__ kvth, __half* __restrict__ kvtl,
                        float* __restrict__ ks)
{
    const int idx = blockIdx.x * 256 + threadIdx.x;
    const int total = BH * HDIM * RR;
    if (idx < total) {
        int bh = idx >> 12, e = idx & 4095;
        float s = 0.f;
#pragma unroll
        for (int c = 0; c < NCHUNK; c++)
            s += kvtp[((size_t)bh * NCHUNK + c) * 4096 + e];
        __half hi = __float2half_rn(s);
        kvth[idx] = hi;
        kvtl[idx] = __float2half_rn(s - __half2float(hi));
    } else if (idx < total + BH * RR) {
        int j = idx - total;
        int bh = j >> 6, r = j & 63;
        float s = 0.f;
#pragma unroll
        for (int c = 0; c < NCHUNK; c++)
            s += ksp[((size_t)bh * NCHUNK + c) * RR + r];
        ks[j] = s;
    }
}

// ============================================================
// TC attn (3-pass fp16): out = (phiq @ kvT) / (phiq.ks + eps), split fp16
// ============================================================
#define AT_PQH 0
#define AT_PQL (128 * 144)
#define AT_KVH (2 * 128 * 144)
#define AT_KVL (AT_KVH + 64 * 144)
#define AT_KS  (AT_KVL + 64 * 144)
#define AT_DEN (AT_KS + 256)
#define AT_SMEM (AT_DEN + 512 + 256)

__global__ __launch_bounds__(256) void attn_tc(
    const __half* __restrict__ pqh, const __half* __restrict__ pql,
    const __half* __restrict__ kvth, const __half* __restrict__ kvtl,
    const float* __restrict__ ks,
    __half* __restrict__ ahi, __half* __restrict__ alo)
{
    extern __shared__ char sm[];
    const uint32_t sb = smem_to_u32(sm);
    const int tid = threadIdx.x;
    const int wid = tid >> 5, lane = tid & 31;
    const int stile = blockIdx.x, bh = blockIdx.y;
    const int b = bh >> 3, h = bh & 7;
    const int sbase = stile * 128;
    const int warp_m = wid >> 1, warp_n = wid & 1;

    {
        const int row = tid >> 1, half = tid & 1;
        size_t gbase = ((size_t)bh * SS + sbase + row) * RR + half * 32;
        uint4* dstH = (uint4*)(sm + AT_PQH + row * 144 + half * 64);
        uint4* dstL = (uint4*)(sm + AT_PQL + row * 144 + half * 64);
#pragma unroll
        for (int i = 0; i < 4; i++) dstH[i] = ((const uint4*)(pqh + gbase))[i];
#pragma unroll
        for (int i = 0; i < 4; i++) dstL[i] = ((const uint4*)(pql + gbase))[i];
    }
    {
        const int row = tid >> 2, q4 = tid & 3;
        size_t gbase = (size_t)bh * (HDIM * RR) + row * RR + q4 * 16;
        *(uint4*)(sm + AT_KVH + row * 144 + q4 * 32) = *(const uint4*)(kvth + gbase);
        *(uint4*)(sm + AT_KVH + row * 144 + q4 * 32 + 16) = *(const uint4*)(kvth + gbase + 8);
        *(uint4*)(sm + AT_KVL + row * 144 + q4 * 32) = *(const uint4*)(kvtl + gbase);
        *(uint4*)(sm + AT_KVL + row * 144 + q4 * 32 + 16) = *(const uint4*)(kvtl + gbase + 8);
    }
    if (tid < 64) ((float*)(sm + AT_KS))[tid] = ks[bh * RR + tid];
    __syncthreads();

    if (tid < 128) {
        float d = 1e-6f;
        const float* kss = (const float*)(sm + AT_KS);
#pragma unroll 16
        for (int r = 0; r < 64; r++) {
            float p = __half2float(*(__half*)(sm + AT_PQH + tid * 144 + r * 2))
                    + __half2float(*(__half*)(sm + AT_PQL + tid * 144 + r * 2));
            d += p * kss[r];
        }
        ((float*)(sm + AT_DEN))[tid] = 1.0f / d;
    }
    __syncthreads();

    float acc[2][4][4];
#pragma unroll
    for (int i = 0; i < 2; i++)
#pragma unroll
        for (int j = 0; j < 4; j++)
#pragma unroll
            for (int e = 0; e < 4; e++) acc[i][j][e] = 0.f;

    const int mat = lane >> 3, mr = lane & 7;
    const int a_row_b = warp_m * 32 + (mat & 1) * 8 + mr;
    const int b_row_b = warp_n * 32 + (mat & 1) * 8 + mr;
    const int mchunk = mat >> 1;

#pragma unroll
    for (int kk = 0; kk < 4; kk++) {
        const int ch = kk * 2 + mchunk;
        uint32_t ah[2][4], al[2][4];
#pragma unroll
        for (int im = 0; im < 2; im++) {
            const int row = a_row_b + im * 16;
            ldsm4(ah[im][0], ah[im][1], ah[im][2], ah[im][3],
                  sb + AT_PQH + row * 144 + ch * 16);
            ldsm4(al[im][0], al[im][1], al[im][2], al[im][3],
                  sb + AT_PQL + row * 144 + ch * 16);
        }
#pragma unroll
        for (int nt = 0; nt < 2; nt++) {
            const int row = b_row_b + nt * 16;
            uint32_t h0, h1, h2, h3, l0, l1, l2, l3;
            ldsm4(h0, h1, h2, h3, sb + AT_KVH + row * 144 + ch * 16);
            ldsm4(l0, l1, l2, l3, sb + AT_KVL + row * 144 + ch * 16);
            uint32_t bh0[2] = {h0, h2}, bh1[2] = {h1, h3};
            uint32_t bl0[2] = {l0, l2}, bl1[2] = {l1, l3};
#pragma unroll
            for (int im = 0; im < 2; im++) {
                mma16816(acc[im][nt * 2], ah[im], bh0);
                mma16816(acc[im][nt * 2], ah[im], bl0);
                mma16816(acc[im][nt * 2], al[im], bh0);
                mma16816(acc[im][nt * 2 + 1], ah[im], bh1);
                mma16816(acc[im][nt * 2 + 1], ah[im], bl1);
                mma16816(acc[im][nt * 2 + 1], al[im], bh1);
            }
        }
    }

    const int g = lane >> 2, t = lane & 3;
    const float* rden = (const float*)(sm + AT_DEN);
#pragma unroll
    for (int im = 0; im < 2; im++) {
        const int s0 = warp_m * 32 + im * 16 + g;
        const float rd0 = rden[s0], rd1 = rden[s0 + 8];
        const size_t row0 = ((size_t)b * SS + sbase + s0) * DD + h * HDIM;
        const size_t row1 = row0 + 8 * DD;
#pragma unroll
        for (int j8 = 0; j8 < 4; j8++) {
            const int d = warp_n * 32 + j8 * 8 + t * 2;
            uint32_t hp, lp;
            split2h(acc[im][j8][0] * rd0, acc[im][j8][1] * rd0, hp, lp);
            *(uint32_t*)(ahi + row0 + d) = hp;
            *(uint32_t*)(alo + row0 + d) = lp;
            split2h(acc[im][j8][2] * rd1, acc[im][j8][3] * rd1, hp, lp);
            *(uint32_t*)(ahi + row1 + d) = hp;
            *(uint32_t*)(alo + row1 + d) = lp;
        }
    }
}

// ============================================================
// launch
// ============================================================
extern "C" void kernel_launch(void* const* d_in, const int* in_sizes, int n_in,
                              void* d_out, int out_size)
{
    const float* x       = (const float*)d_in[0];
    const float* Wq      = (const float*)d_in[1];
    const float* bq      = (const float*)d_in[2];
    const float* Wk      = (const float*)d_in[3];
    const float* bk      = (const float*)d_in[4];
    const float* Wv      = (const float*)d_in[5];
    const float* bv      = (const float*)d_in[6];
    const float* Wp      = (const float*)d_in[7];
    const float* bp      = (const float*)d_in[8];
    const float* gamma_q = (const float*)d_in[9];
    const float* beta_q  = (const float*)d_in[10];
    const float* gamma_k = (const float*)d_in[11];
    const float* beta_k  = (const float*)d_in[12];
    const float* qG1     = (const float*)d_in[13];
    const float* qG2     = (const float*)d_in[14];
    const float* kG1     = (const float*)d_in[15];
    const float* kG2     = (const float*)d_in[16];
    float* out = (float*)d_out;

    float *p_bqkv, *p_kvtp, *p_ksp, *p_ks;
    __half *p_xhi, *p_xlo, *p_qh, *p_ql, *p_kh, *p_kl, *p_vh, *p_vl;
    __half *p_ahi, *p_alo, *p_wth, *p_pqh, *p_pql, *p_pkth, *p_pktl, *p_kvth, *p_kvtl;
    cudaGetSymbolAddress((void**)&p_xhi, g_xhi);
    cudaGetSymbolAddress((void**)&p_xlo, g_xlo);
    cudaGetSymbolAddress((void**)&p_qh, g_qh);
    cudaGetSymbolAddress((void**)&p_ql, g_ql);
    cudaGetSymbolAddress((void**)&p_kh, g_kh);
    cudaGetSymbolAddress((void**)&p_kl, g_kl);
    cudaGetSymbolAddress((void**)&p_vh, g_vh);
    cudaGetSymbolAddress((void**)&p_vl, g_vl);
    cudaGetSymbolAddress((void**)&p_ahi, g_ahi);
    cudaGetSymbolAddress((void**)&p_alo, g_alo);
    cudaGetSymbolAddress((void**)&p_wth, g_wth);
    cudaGetSymbolAddress((void**)&p_bqkv, g_biasqkv);
    cudaGetSymbolAddress((void**)&p_pqh, g_pqh);
    cudaGetSymbolAddress((void**)&p_pql, g_pql);
    cudaGetSymbolAddress((void**)&p_pkth, g_pkth);
    cudaGetSymbolAddress((void**)&p_pktl, g_pktl);
    cudaGetSymbolAddress((void**)&p_kvtp, g_kvtp);
    cudaGetSymbolAddress((void**)&p_ksp, g_ksp);
    cudaGetSymbolAddress((void**)&p_kvth, g_kvth);
    cudaGetSymbolAddress((void**)&p_kvtl, g_kvtl);
    cudaGetSymbolAddress((void**)&p_ks, g_ks);

    cudaFuncSetAttribute(mma_gemm, cudaFuncAttributeMaxDynamicSharedMemorySize,
                         GEMM_SMEM);
    cudaFuncSetAttribute(sketch_tc2, cudaFuncAttributeMaxDynamicSharedMemorySize,
                         SK_SMEM);
    cudaFuncSetAttribute(attn_tc, cudaFuncAttributeMaxDynamicSharedMemorySize,
                         AT_SMEM);

    // ---- prep (5 launches so ncu -s 5 -c 1 profiles the QKV GEMM) ----
    split_fp32<<<BSROWS * DD / 4 / 256, 256>>>(x, p_xhi, p_xlo);               // 1
    concat_bias<<<6, 256>>>(bq, bk, bv, gamma_q, beta_q, gamma_k, beta_k,
                            p_bqkv);                                           // 2
    g_prep<<<2, 256>>>(qG1, qG2, kG1, kG2);                                    // 3
    transpose_h2<<<dim3(16, 16, 2), 256>>>(Wq, Wk, gamma_q, gamma_k,
                                           p_wth, 0, 512);                     // 4
    transpose_h2<<<dim3(16, 16, 2), 256>>>(Wv, Wp, nullptr, nullptr,
                                           p_wth, 1024, 1536);                 // 5

    // ---- fused QKV GEMM (2-pass fp16) ----
    dim3 gq(6, BSROWS / 128);
    mma_gemm<<<gq, 256, GEMM_SMEM>>>(p_xhi, p_xlo, p_wth, p_bqkv,
                                     p_qh, p_ql, p_kh, p_kl, p_vh, p_vl,
                                     nullptr);                                 // 6

    // ---- TC sketch (3-pass fp16, q & k) ----
    dim3 skg(BSROWS / 128, HH, 2);
    sketch_tc2<<<skg, 256, SK_SMEM>>>(p_qh, p_ql, p_kh, p_kl,
                                      p_pqh, p_pql, p_pkth, p_pktl);

    // ---- TC kvsum + reduce ----
    kvsum_tc<<<dim3(NCHUNK, BH), 256>>>(p_pkth, p_pktl, p_vh, p_vl,
                                        p_kvtp, p_ksp);
    int red_total = BH * HDIM * RR + BH * RR;
    reduce2<<<(red_total + 255) / 256, 256>>>(p_kvtp, p_ksp,
                                              p_kvth, p_kvtl, p_ks);

    // ---- TC attention output ----
    attn_tc<<<dim3(SS / 128, BH), 256, AT_SMEM>>>(p_pqh, p_pql,
                                                  p_kvth, p_kvtl, p_ks,
                                                  p_ahi, p_alo);

    // ---- output projection (2-pass fp16, fp32 out) ----
    dim3 go(2, BSROWS / 128);
    mma_gemm<<<go, 256, GEMM_SMEM>>>(p_ahi, p_alo, p_wth + 1536 * DD, bp,
                                     nullptr, nullptr, nullptr, nullptr,
                                     nullptr, nullptr, out);
}

// round 10
// speedup vs baseline: 1.7729x; 1.1053x over previous
#include <cuda_runtime.h>
#include <cuda_fp16.h>
#include <cstdint>

// Problem constants
#define BB 4
#define SS 8192
#define DD 512
#define HH 8
#define HDIM 64
#define RR 64
#define BSROWS (BB * SS)      // 32768
#define BH (BB * HH)          // 32
#define NCHUNK 16

// -------- scratch (static device globals; no allocation) --------
__device__ __half g_xhi[BSROWS * DD];
__device__ __half g_xlo[BSROWS * DD];
__device__ __half g_vh[BSROWS * DD];
__device__ __half g_vl[BSROWS * DD];
__device__ __half g_ahi[BSROWS * DD];
__device__ __half g_wth[4 * DD * DD];     // fp16 transposed weights
__device__ float g_biasqkv[3 * DD];
__device__ __half g_gint_hi[2][128 * 64];
__device__ __half g_gint_lo[2][128 * 64];
__device__ __half g_pqh[BH * SS * RR];
__device__ __half g_pql[BH * SS * RR];
__device__ __half g_pkth[BH * RR * SS];
__device__ __half g_pktl[BH * RR * SS];
__device__ float g_kvtp[BH * NCHUNK * HDIM * RR];
__device__ float g_ksp[BH * NCHUNK * RR];
__device__ __half g_kvth[BH * HDIM * RR];
__device__ __half g_kvtl[BH * HDIM * RR];
__device__ float g_ks[BH * RR];

// ============================================================
// helpers
// ============================================================
__device__ __forceinline__ uint32_t smem_to_u32(const void* p) {
    uint32_t a;
    asm("{ .reg .u64 t; cvta.to.shared.u64 t, %1; cvt.u32.u64 %0, t; }"
        : "=r"(a) : "l"(p));
    return a;
}
__device__ __forceinline__ void ldsm4(uint32_t& r0, uint32_t& r1,
                                      uint32_t& r2, uint32_t& r3,
                                      uint32_t addr) {
    asm volatile("ldmatrix.sync.aligned.m8n8.x4.shared.b16 {%0,%1,%2,%3}, [%4];"
                 : "=r"(r0), "=r"(r1), "=r"(r2), "=r"(r3) : "r"(addr));
}
__device__ __forceinline__ void ldsm4t(uint32_t& r0, uint32_t& r1,
                                       uint32_t& r2, uint32_t& r3,
                                       uint32_t addr) {
    asm volatile("ldmatrix.sync.aligned.m8n8.x4.trans.shared.b16 {%0,%1,%2,%3}, [%4];"
                 : "=r"(r0), "=r"(r1), "=r"(r2), "=r"(r3) : "r"(addr));
}
__device__ __forceinline__ void mma16816(float* d, const uint32_t* a,
                                         const uint32_t* b) {
    asm volatile(
        "mma.sync.aligned.m16n8k16.row.col.f32.f16.f16.f32 "
        "{%0,%1,%2,%3}, {%4,%5,%6,%7}, {%8,%9}, {%0,%1,%2,%3};"
        : "+f"(d[0]), "+f"(d[1]), "+f"(d[2]), "+f"(d[3])
        : "r"(a[0]), "r"(a[1]), "r"(a[2]), "r"(a[3]), "r"(b[0]), "r"(b[1]));
}
#define CP_ASYNC16(dst, src) \
    asm volatile("cp.async.cg.shared.global [%0], [%1], 16;" :: "r"(dst), "l"(src))
#define CP_COMMIT() asm volatile("cp.async.commit_group;" ::: "memory")
#define CP_WAIT(n)  asm volatile("cp.async.wait_group %0;" :: "n"(n) : "memory")

__device__ __forceinline__ void split4h(float4 v, uint2& hi, uint2& lo) {
    __half h0 = __float2half_rn(v.x), h1 = __float2half_rn(v.y);
    __half h2 = __float2half_rn(v.z), h3 = __float2half_rn(v.w);
    float r0 = v.x - __half2float(h0), r1 = v.y - __half2float(h1);
    float r2 = v.z - __half2float(h2), r3 = v.w - __half2float(h3);
    __half l0 = __float2half_rn(r0), l1 = __float2half_rn(r1);
    __half l2 = __float2half_rn(r2), l3 = __float2half_rn(r3);
    hi.x = ((uint32_t)__half_as_ushort(h1) << 16) | __half_as_ushort(h0);
    hi.y = ((uint32_t)__half_as_ushort(h3) << 16) | __half_as_ushort(h2);
    lo.x = ((uint32_t)__half_as_ushort(l1) << 16) | __half_as_ushort(l0);
    lo.y = ((uint32_t)__half_as_ushort(l3) << 16) | __half_as_ushort(l2);
}
__device__ __forceinline__ void split2h(float a, float b, uint32_t& hp, uint32_t& lp) {
    __half h0 = __float2half_rn(a), h1 = __float2half_rn(b);
    float l0 = a - __half2float(h0), l1 = b - __half2float(h1);
    __half e0 = __float2half_rn(l0), e1 = __float2half_rn(l1);
    hp = ((uint32_t)__half_as_ushort(h1) << 16) | __half_as_ushort(h0);
    lp = ((uint32_t)__half_as_ushort(e1) << 16) | __half_as_ushort(e0);
}
__device__ __forceinline__ uint32_t pack2h(float a, float b) {
    __half h0 = __float2half_rn(a), h1 = __float2half_rn(b);
    return ((uint32_t)__half_as_ushort(h1) << 16) | __half_as_ushort(h0);
}

// ============================================================
// prep kernels
// ============================================================
__global__ __launch_bounds__(256) void split_fp32(
    const float* __restrict__ X, __half* __restrict__ Xh,
    __half* __restrict__ Xl)
{
    int i = blockIdx.x * 256 + threadIdx.x;
    float4 v = ((const float4*)X)[i];
    uint2 hi, lo;
    split4h(v, hi, lo);
    ((uint2*)Xh)[i] = hi;
    ((uint2*)Xl)[i] = lo;
}

__global__ __launch_bounds__(256) void transpose_h2(
    const float* __restrict__ W0, const float* __restrict__ W1,
    const float* __restrict__ g0, const float* __restrict__ g1,
    __half* __restrict__ Th, int rowoff0, int rowoff1)
{
    __shared__ float t[32][33];
    const float* W = blockIdx.z ? W1 : W0;
    const float* gp = blockIdx.z ? g1 : g0;
    const float scale = gp ? gp[0] : 1.0f;
    const int rowoff = blockIdx.z ? rowoff1 : rowoff0;
    int bx = blockIdx.x * 32, by = blockIdx.y * 32;
    int x = threadIdx.x & 31, y = threadIdx.x >> 5;
    for (int i = y; i < 32; i += 8) t[i][x] = W[(size_t)(by + i) * DD + bx + x];
    __syncthreads();
    for (int i = y; i < 32; i += 8)
        Th[(size_t)(rowoff + bx + i) * DD + by + x] = __float2half_rn(t[x][i] * scale);
}

__global__ void concat_bias(const float* bq, const float* bk, const float* bv,
                            const float* gq, const float* betq,
                            const float* gk, const float* betk,
                            float* bout)
{
    int i = blockIdx.x * 256 + threadIdx.x;
    if (i < DD) bout[i] = gq[0] * bq[i] + betq[0];
    else if (i < 2 * DD) bout[i] = gk[0] * bk[i - DD] + betk[0];
    else if (i < 3 * DD) bout[i] = bv[i - 2 * DD];
}

__global__ __launch_bounds__(256) void g_prep(
    const float* __restrict__ qG1, const float* __restrict__ qG2,
    const float* __restrict__ kG1, const float* __restrict__ kG2)
{
    const int set = blockIdx.x;
    const float* G1 = set ? kG1 : qG1;
    const float* G2 = set ? kG2 : qG2;
    __half* Oh = g_gint_hi[set];
    __half* Ol = g_gint_lo[set];
    for (int it = 0; it < 32; it++) {
        int idx = it * 256 + threadIdx.x;
        int n = idx >> 6, k = idx & 63;
        float v = ((n & 1) ? G2 : G1)[k * 64 + (n >> 1)];
        __half h = __float2half_rn(v);
        Oh[idx] = h;
        Ol[idx] = __float2half_rn(v - __half2float(h));
    }
}

// ============================================================
// fp16 split GEMM + fused sketch epilogue.
// CTA tile 128x256, 8 warps (2m x 4n), warp tile 64x64.
// Alo != null -> 2-pass (A split); Alo == null -> 1-pass.
// ofp32 set -> proj mode (fp32 out).
// Else QKV mode: sel = bn>>1: 0 -> q (fused sketch -> phiq),
//   1 -> k (fused sketch -> phikT), 2 -> v (fp16 hi/lo out).
// ============================================================
#define BKC 32
#define NKCH (DD / BKC)          // 16
#define ROWB 80
#define TILE_A (128 * ROWB)      // 10240
#define TILE_B (256 * ROWB)      // 20480
#define ST_AHI 0
#define ST_ALO TILE_A
#define ST_BH (2 * TILE_A)
#define STAGEB (2 * TILE_A + TILE_B)   // 40960
#define PIPE 4
#define OFF80(row, ch) ((uint32_t)((row) * ROWB + ((ch) << 4)))
// fused sketch regions (reuse smem after mainloop)
#define FZ_HEAD 36864            // per-head z region: hi 18432 + lo 18432
#define FZ_LO 18432
#define FG_OFF (4 * FZ_HEAD)     // 147456
#define FG_LO 18432
#define GEMM_SMEM (FG_OFF + 2 * FG_LO)   // 184320 (> PIPE*STAGEB=163840)
#define SOFF144(row, ch) ((uint32_t)((row) * 144 + ((ch) << 4)))

__global__ __launch_bounds__(256, 1) void mma_gemm(
    const __half* __restrict__ Ahi, const __half* __restrict__ Alo,
    const __half* __restrict__ Bh, const float* __restrict__ bias,
    __half* __restrict__ pqh, __half* __restrict__ pql,
    __half* __restrict__ pkth, __half* __restrict__ pktl,
    __half* __restrict__ vh, __half* __restrict__ vl,
    float* __restrict__ ofp32)
{
    extern __shared__ char smem[];
    const uint32_t sb = smem_to_u32(smem);

    const int tid = threadIdx.x;
    const int wid = tid >> 5, lane = tid & 31;
    const int bn = blockIdx.x, bm = blockIdx.y;
    const int warp_m = wid & 1, warp_n = wid >> 1;
    const bool twopass = (Alo != nullptr);

    const __half* Ahi_b = Ahi + (size_t)bm * 128 * DD;
    const __half* Alo_b = twopass ? Alo + (size_t)bm * 128 * DD : Ahi_b;
    const __half* Bh_b = Bh + (size_t)bn * 256 * DD;

    const int lrow = tid >> 2;
    const int lch = tid & 3;

    auto load_chunk = [&](int c, int s) {
        const uint32_t stg = sb + s * STAGEB;
        const int k0 = c * BKC;
#pragma unroll
        for (int sw = 0; sw < 2; sw++) {
            const int row = sw * 64 + lrow;
            const size_t go = (size_t)row * DD + k0 + lch * 8;
            const uint32_t so = OFF80(row, lch);
            CP_ASYNC16(stg + ST_AHI + so, Ahi_b + go);
            if (twopass) CP_ASYNC16(stg + ST_ALO + so, Alo_b + go);
        }
#pragma unroll
        for (int sw = 0; sw < 4; sw++) {
            const int row = sw * 64 + lrow;
            const size_t go = (size_t)row * DD + k0 + lch * 8;
            CP_ASYNC16(stg + ST_BH + OFF80(row, lch), Bh_b + go);
        }
    };

    float acc[4][8][4];
#pragma unroll
    for (int i = 0; i < 4; i++)
#pragma unroll
        for (int j = 0; j < 8; j++)
#pragma unroll
            for (int e = 0; e < 4; e++) acc[i][j][e] = 0.f;

    const int mat = lane >> 3, mr = lane & 7;
    const int a_row_b = warp_m * 64 + (mat & 1) * 8 + mr;
    const int b_row_b = warp_n * 64 + (mat & 1) * 8 + mr;
    const int mchunk = mat >> 1;

    load_chunk(0, 0); CP_COMMIT();
    load_chunk(1, 1); CP_COMMIT();
    load_chunk(2, 2); CP_COMMIT();

    for (int c = 0; c < NKCH; c++) {
        CP_WAIT(2);
        __syncthreads();
        if (c + 3 < NKCH) load_chunk(c + 3, (c + 3) % PIPE);
        CP_COMMIT();

        const uint32_t stg = sb + (c % PIPE) * STAGEB;
#pragma unroll
        for (int kk = 0; kk < 2; kk++) {
            const int ch = kk * 2 + mchunk;
            uint32_t ahi[4][4], alo[4][4];
#pragma unroll
            for (int im = 0; im < 4; im++) {
                const int row = a_row_b + im * 16;
                ldsm4(ahi[im][0], ahi[im][1], ahi[im][2], ahi[im][3],
                      stg + ST_AHI + OFF80(row, ch));
                if (twopass)
                    ldsm4(alo[im][0], alo[im][1], alo[im][2], alo[im][3],
                          stg + ST_ALO + OFF80(row, ch));
            }
#pragma unroll
            for (int j16 = 0; j16 < 4; j16++) {
                const int row = b_row_b + j16 * 16;
                uint32_t h0, h1, h2, h3;
                ldsm4(h0, h1, h2, h3, stg + ST_BH + OFF80(row, ch));
                uint32_t bh0[2] = {h0, h2}, bh1[2] = {h1, h3};
#pragma unroll
                for (int im = 0; im < 4; im++) {
                    mma16816(acc[im][j16 * 2], ahi[im], bh0);
                    mma16816(acc[im][j16 * 2 + 1], ahi[im], bh1);
                    if (twopass) {
                        mma16816(acc[im][j16 * 2], alo[im], bh0);
                        mma16816(acc[im][j16 * 2 + 1], alo[im], bh1);
                    }
                }
            }
        }
    }

    const int erow = lane >> 2, ecol = (lane & 3) * 2;

    if (ofp32) {
        // ---- projection epilogue: fp32 out ----
        const int colbase = bn * 256;
#pragma unroll
        for (int im = 0; im < 4; im++) {
            const size_t row0 = (size_t)bm * 128 + warp_m * 64 + im * 16 + erow;
#pragma unroll
            for (int t = 0; t < 8; t++) {
                const int cofs = warp_n * 64 + t * 8 + ecol;
                float2 b2 = *(const float2*)&bias[colbase + cofs];
                float2 q0 = make_float2(acc[im][t][0] + b2.x, acc[im][t][1] + b2.y);
                float2 q1 = make_float2(acc[im][t][2] + b2.x, acc[im][t][3] + b2.y);
                *(float2*)&ofp32[row0 * DD + colbase + cofs] = q0;
                *(float2*)&ofp32[(row0 + 8) * DD + colbase + cofs] = q1;
            }
        }
        return;
    }

    const int sel = bn >> 1;
    if (sel == 2) {
        // ---- v epilogue: fp16 hi/lo ----
        const int colbase = (bn & 1) * 256;
#pragma unroll
        for (int im = 0; im < 4; im++) {
            const size_t row0 = (size_t)bm * 128 + warp_m * 64 + im * 16 + erow;
#pragma unroll
            for (int t = 0; t < 8; t++) {
                const int cofs = warp_n * 64 + t * 8 + ecol;
                float2 b2 = *(const float2*)&bias[bn * 256 + cofs];
                uint32_t hp, lp;
                split2h(acc[im][t][0] + b2.x, acc[im][t][1] + b2.y, hp, lp);
                *(uint32_t*)(vh + row0 * DD + colbase + cofs) = hp;
                *(uint32_t*)(vl + row0 * DD + colbase + cofs) = lp;
                split2h(acc[im][t][2] + b2.x, acc[im][t][3] + b2.y, hp, lp);
                *(uint32_t*)(vh + (row0 + 8) * DD + colbase + cofs) = hp;
                *(uint32_t*)(vl + (row0 + 8) * DD + colbase + cofs) = lp;
            }
        }
        return;
    }

    // ================= fused sketch epilogue (sel 0 = q, 1 = k) ==========
    CP_WAIT(0);
    __syncthreads();   // mainloop smem no longer needed

    // stage z = acc + bias as fp16 hi/lo, per head (4 heads per CTA tile)
#pragma unroll
    for (int im = 0; im < 4; im++) {
        const int row = warp_m * 64 + im * 16 + erow;
#pragma unroll
        for (int t = 0; t < 8; t++) {
            const int cofs = warp_n * 64 + t * 8 + ecol;
            const int head = cofs >> 6, c = cofs & 63;
            float2 b2 = *(const float2*)&bias[bn * 256 + cofs];
            uint32_t hp, lp;
            split2h(acc[im][t][0] + b2.x, acc[im][t][1] + b2.y, hp, lp);
            *(uint32_t*)(smem + head * FZ_HEAD + row * 144 + c * 2) = hp;
            *(uint32_t*)(smem + head * FZ_HEAD + FZ_LO + row * 144 + c * 2) = lp;
            split2h(acc[im][t][2] + b2.x, acc[im][t][3] + b2.y, hp, lp);
            *(uint32_t*)(smem + head * FZ_HEAD + (row + 8) * 144 + c * 2) = hp;
            *(uint32_t*)(smem + head * FZ_HEAD + FZ_LO + (row + 8) * 144 + c * 2) = lp;
        }
    }
    // load G-int (hi/lo) for this set
    {
        const __half* Gh = &g_gint_hi[sel][0];
        const __half* Gl = &g_gint_lo[sel][0];
#pragma unroll
        for (int it = 0; it < 4; it++) {
            const int cidx = it * 256 + tid;
            const int row = cidx >> 3, ch = cidx & 7;
            *(uint4*)(smem + FG_OFF + SOFF144(row, ch)) =
                *(const uint4*)((const char*)Gh + row * 128 + ch * 16);
            *(uint4*)(smem + FG_OFF + FG_LO + SOFF144(row, ch)) =
                *(const uint4*)((const char*)Gl + row * 128 + ch * 16);
        }
    }
    __syncthreads();

    // sketch warp mapping
    const int swm = wid & 1, swn = wid >> 1;
    const int a_row_s = swm * 64 + (mat & 1) * 8 + mr;
    const int b_row_s = swn * 32 + (mat & 1) * 8 + mr;
    const int b = bm >> 6;
    const int sbase = (bm & 63) * 128;
    const int g = lane >> 2, t4 = lane & 3;
    const float inv = 0.125f;

    for (int hd = 0; hd < 4; hd++) {
        const uint32_t zb = sb + hd * FZ_HEAD;

        float sk[4][4][4];
#pragma unroll
        for (int i = 0; i < 4; i++)
#pragma unroll
            for (int j = 0; j < 4; j++)
#pragma unroll
                for (int e = 0; e < 4; e++) sk[i][j][e] = 0.f;

#pragma unroll
        for (int kk = 0; kk < 4; kk++) {
            const int ch = kk * 2 + mchunk;
            uint32_t zhi[4][4], zlo[4][4];
#pragma unroll
            for (int im = 0; im < 4; im++) {
                const int row = a_row_s + im * 16;
                ldsm4(zhi[im][0], zhi[im][1], zhi[im][2], zhi[im][3],
                      zb + SOFF144(row, ch));
                ldsm4(zlo[im][0], zlo[im][1], zlo[im][2], zlo[im][3],
                      zb + FZ_LO + SOFF144(row, ch));
            }
#pragma unroll
            for (int j16 = 0; j16 < 2; j16++) {
                const int row = b_row_s + j16 * 16;
                uint32_t h0, h1, h2, h3, l0, l1, l2, l3;
                ldsm4(h0, h1, h2, h3, sb + FG_OFF + SOFF144(row, ch));
                ldsm4(l0, l1, l2, l3, sb + FG_OFF + FG_LO + SOFF144(row, ch));
                uint32_t gh0[2] = {h0, h2}, gh1[2] = {h1, h3};
                uint32_t gl0[2] = {l0, l2}, gl1[2] = {l1, l3};
#pragma unroll
                for (int im = 0; im < 4; im++) {
                    mma16816(sk[im][j16 * 2], zhi[im], gh0);
                    mma16816(sk[im][j16 * 2], zhi[im], gl0);
                    mma16816(sk[im][j16 * 2], zlo[im], gh0);
                    mma16816(sk[im][j16 * 2 + 1], zhi[im], gh1);
                    mma16816(sk[im][j16 * 2 + 1], zhi[im], gl1);
                    mma16816(sk[im][j16 * 2 + 1], zlo[im], gh1);
                }
            }
        }

        const int h = (bn & 1) * 4 + hd;
        const int bh2 = b * HH + h;
        __syncthreads();   // all warps done reading z[hd]; reuse for staging

        __half* SH = (__half*)(smem + hd * FZ_HEAD);
        if (sel == 0) {
            __half* SL = (__half*)(smem + hd * FZ_HEAD + FZ_LO);
#pragma unroll
            for (int im = 0; im < 4; im++) {
                const int s0 = swm * 64 + im * 16 + g;
#pragma unroll
                for (int jn = 0; jn < 4; jn++) {
                    const int r = swn * 16 + jn * 4 + t4;
                    float h0 = inv * sk[im][jn][0] * sk[im][jn][1];
                    float h1 = inv * sk[im][jn][2] * sk[im][jn][3];
                    float p0 = h0 * h0, p1 = h1 * h1;
                    __half x0 = __float2half_rn(p0);
                    __half x1 = __float2half_rn(p1);
                    SH[s0 * 72 + r] = x0;
                    SH[(s0 + 8) * 72 + r] = x1;
                    SL[s0 * 72 + r] = __float2half_rn(p0 - __half2float(x0));
                    SL[(s0 + 8) * 72 + r] = __float2half_rn(p1 - __half2float(x1));
                }
            }
            __syncthreads();
            const int row = tid >> 1, hf = tid & 1;
            size_t gbase = ((size_t)bh2 * SS + sbase + row) * RR + hf * 32;
            const uint4* srcH = (const uint4*)(smem + hd * FZ_HEAD + row * 144 + hf * 64);
            const uint4* srcL = (const uint4*)(smem + hd * FZ_HEAD + FZ_LO + row * 144 + hf * 64);
#pragma unroll
            for (int i = 0; i < 4; i++) ((uint4*)(pqh + gbase))[i] = srcH[i];
#pragma unroll
            for (int i = 0; i < 4; i++) ((uint4*)(pql + gbase))[i] = srcL[i];
        } else {
            __half* SL = (__half*)(smem + hd * FZ_HEAD + 17408);
#pragma unroll
            for (int im = 0; im < 4; im++) {
                const int s0 = swm * 64 + im * 16 + g;
#pragma unroll
                for (int jn = 0; jn < 4; jn++) {
                    const int r = swn * 16 + jn * 4 + t4;
                    float h0 = inv * sk[im][jn][0] * sk[im][jn][1];
                    float h1 = inv * sk[im][jn][2] * sk[im][jn][3];
                    float p0 = h0 * h0, p1 = h1 * h1;
                    __half x0 = __float2half_rn(p0);
                    __half x1 = __float2half_rn(p1);
                    SH[r * 136 + s0] = x0;
                    SH[r * 136 + s0 + 8] = x1;
                    SL[r * 136 + s0] = __float2half_rn(p0 - __half2float(x0));
                    SL[r * 136 + s0 + 8] = __float2half_rn(p1 - __half2float(x1));
                }
            }
            __syncthreads();
            const int r = tid >> 2, q4 = tid & 3;
            size_t gbase = ((size_t)bh2 * RR + r) * SS + sbase + q4 * 32;
            const uint4* srcH = (const uint4*)(smem + hd * FZ_HEAD + r * 272 + q4 * 64);
            const uint4* srcL = (const uint4*)(smem + hd * FZ_HEAD + 17408 + r * 272 + q4 * 64);
#pragma unroll
            for (int i = 0; i < 4; i++) ((uint4*)(pkth + gbase))[i] = srcH[i];
#pragma unroll
            for (int i = 0; i < 4; i++) ((uint4*)(pktl + gbase))[i] = srcL[i];
        }
    }
}

// ============================================================
// TC kvsum (3-pass fp16): kvT[d][r] = sum_s v[s,d]*phik[s,r]
// ============================================================
__global__ __launch_bounds__(256) void kvsum_tc(
    const __half* __restrict__ pkth, const __half* __restrict__ pktl,
    const __half* __restrict__ vh, const __half* __restrict__ vl,
    float* __restrict__ kvtp, float* __restrict__ ksp)
{
    __shared__ __align__(16) char sm[4 * 64 * 144];
    const uint32_t sb = smem_to_u32(sm);
    const uint32_t VHI = 0, VLO = 9216, PKH = 18432, PKL = 27648;

    const int tid = threadIdx.x;
    const int wid = tid >> 5, lane = tid & 31;
    const int chunk = blockIdx.x, bh = blockIdx.y;
    const int b = bh >> 3, h = bh & 7;
    const int warp_m = wid & 1, warp_n = wid >> 1;
    const int mat = lane >> 3, mr = lane & 7;
    const int g = lane >> 2, t = lane & 3;

    float acc[2][2][4];
#pragma unroll
    for (int i = 0; i < 2; i++)
#pragma unroll
        for (int j = 0; j < 2; j++)
#pragma unroll
            for (int e = 0; e < 4; e++) acc[i][j][e] = 0.f;
    float kacc = 0.f;

    const int lr = tid >> 2, lq = tid & 3;
    const int kr = tid & 63, kg = tid >> 6;

    for (int step = 0; step < 8; step++) {
        const int s0 = chunk * 512 + step * 64;
        {
            const size_t vo = (size_t)(b * SS + s0 + lr) * DD + h * HDIM + lq * 16;
            *(uint4*)(sm + VHI + lr * 144 + lq * 32) = *(const uint4*)(vh + vo);
            *(uint4*)(sm + VHI + lr * 144 + lq * 32 + 16) = *(const uint4*)(vh + vo + 8);
            *(uint4*)(sm + VLO + lr * 144 + lq * 32) = *(const uint4*)(vl + vo);
            *(uint4*)(sm + VLO + lr * 144 + lq * 32 + 16) = *(const uint4*)(vl + vo + 8);
            const size_t po = ((size_t)bh * RR + lr) * SS + s0 + lq * 16;
            *(uint4*)(sm + PKH + lr * 144 + lq * 32) = *(const uint4*)(pkth + po);
            *(uint4*)(sm + PKH + lr * 144 + lq * 32 + 16) = *(const uint4*)(pkth + po + 8);
            *(uint4*)(sm + PKL + lr * 144 + lq * 32) = *(const uint4*)(pktl + po);
            *(uint4*)(sm + PKL + lr * 144 + lq * 32 + 16) = *(const uint4*)(pktl + po + 8);
        }
        __syncthreads();

#pragma unroll
        for (int c = 0; c < 16; c++) {
            int sc = kg * 16 + c;
            kacc += __half2float(*(__half*)(sm + PKH + kr * 144 + sc * 2))
                  + __half2float(*(__half*)(sm + PKL + kr * 144 + sc * 2));
        }

#pragma unroll
        for (int kk = 0; kk < 4; kk++) {
            uint32_t ah[2][4], al[2][4];
#pragma unroll
            for (int im = 0; im < 2; im++) {
                const int d0 = warp_m * 32 + im * 16 + (mat & 1) * 8;
                const int srow = kk * 16 + ((mat >> 1) & 1) * 8 + mr;
                ldsm4t(ah[im][0], ah[im][1], ah[im][2], ah[im][3],
                       sb + VHI + srow * 144 + d0 * 2);
                ldsm4t(al[im][0], al[im][1], al[im][2], al[im][3],
                       sb + VLO + srow * 144 + d0 * 2);
            }
            const int rrow = warp_n * 16 + (mat & 1) * 8 + mr;
            const int chb = kk * 2 + (mat >> 1);
            uint32_t h0, h1, h2, h3, l0, l1, l2, l3;
            ldsm4(h0, h1, h2, h3, sb + PKH + rrow * 144 + chb * 16);
            ldsm4(l0, l1, l2, l3, sb + PKL + rrow * 144 + chb * 16);
            uint32_t bh0[2] = {h0, h2}, bh1[2] = {h1, h3};
            uint32_t bl0[2] = {l0, l2}, bl1[2] = {l1, l3};
#pragma unroll
            for (int im = 0; im < 2; im++) {
                mma16816(acc[im][0], ah[im], bh0);
                mma16816(acc[im][0], ah[im], bl0);
                mma16816(acc[im][0], al[im], bh0);
                mma16816(acc[im][1], ah[im], bh1);
                mma16816(acc[im][1], ah[im], bl1);
                mma16816(acc[im][1], al[im], bh1);
            }
        }
        __syncthreads();
    }

    float* outp = kvtp + ((size_t)bh * NCHUNK + chunk) * (HDIM * RR);
#pragma unroll
    for (int im = 0; im < 2; im++) {
        const int d = warp_m * 32 + im * 16 + g;
#pragma unroll
        for (int nb = 0; nb < 2; nb++) {
            const int r = warp_n * 16 + nb * 8 + t * 2;
            *(float2*)&outp[d * RR + r] =
                make_float2(acc[im][nb][0], acc[im][nb][1]);
            *(float2*)&outp[(d + 8) * RR + r] =
                make_float2(acc[im][nb][2], acc[im][nb][3]);
        }
    }
    __syncthreads();
    float* red = (float*)sm;
    red[kg * 64 + kr] = kacc;
    __syncthreads();
    if (tid < 64)
        ksp[((size_t)bh * NCHUNK + chunk) * RR + tid] =
            red[tid] + red[64 + tid] + red[128 + tid] + red[192 + tid];
}

__global__ void reduce2(const float* __restrict__ kvtp,
                        const float* __restrict__ ksp,
                        __half* __restrict__ kvth, __half* __restrict__ kvtl,
                        float* __restrict__ ks)
{
    const int idx = blockIdx.x * 256 + threadIdx.x;
    const int total = BH * HDIM * RR;
    if (idx < total) {
        int bh = idx >> 12, e = idx & 4095;
        float s = 0.f;
#pragma unroll
        for (int c = 0; c < NCHUNK; c++)
            s += kvtp[((size_t)bh * NCHUNK + c) * 4096 + e];
        __half hi = __float2half_rn(s);
        kvth[idx] = hi;
        kvtl[idx] = __float2half_rn(s - __half2float(hi));
    } else if (idx < total + BH * RR) {
        int j = idx - total;
        int bh = j >> 6, r = j & 63;
        float s = 0.f;
#pragma unroll
        for (int c = 0; c < NCHUNK; c++)
            s += ksp[((size_t)bh * NCHUNK + c) * RR + r];
        ks[j] = s;
    }
}

// ============================================================
// TC attn (3-pass fp16): out = (phiq @ kvT) / (phiq.ks + eps), fp16 out
// ============================================================
#define AT_PQH 0
#define AT_PQL (128 * 144)
#define AT_KVH (2 * 128 * 144)
#define AT_KVL (AT_KVH + 64 * 144)
#define AT_KS  (AT_KVL + 64 * 144)
#define AT_DEN (AT_KS + 256)
#define AT_SMEM (AT_DEN + 512 + 256)

__global__ __launch_bounds__(256) void attn_tc(
    const __half* __restrict__ pqh, const __half* __restrict__ pql,
    const __half* __restrict__ kvth, const __half* __restrict__ kvtl,
    const float* __restrict__ ks,
    __half* __restrict__ ahi)
{
    extern __shared__ char sm[];
    const uint32_t sb = smem_to_u32(sm);
    const int tid = threadIdx.x;
    const int wid = tid >> 5, lane = tid & 31;
    const int stile = blockIdx.x, bh = blockIdx.y;
    const int b = bh >> 3, h = bh & 7;
    const int sbase = stile * 128;
    const int warp_m = wid >> 1, warp_n = wid & 1;

    {
        const int row = tid >> 1, half = tid & 1;
        size_t gbase = ((size_t)bh * SS + sbase + row) * RR + half * 32;
        uint4* dstH = (uint4*)(sm + AT_PQH + row * 144 + half * 64);
        uint4* dstL = (uint4*)(sm + AT_PQL + row * 144 + half * 64);
#pragma unroll
        for (int i = 0; i < 4; i++) dstH[i] = ((const uint4*)(pqh + gbase))[i];
#pragma unroll
        for (int i = 0; i < 4; i++) dstL[i] = ((const uint4*)(pql + gbase))[i];
    }
    {
        const int row = tid >> 2, q4 = tid & 3;
        size_t gbase = (size_t)bh * (HDIM * RR) + row * RR + q4 * 16;
        *(uint4*)(sm + AT_KVH + row * 144 + q4 * 32) = *(const uint4*)(kvth + gbase);
        *(uint4*)(sm + AT_KVH + row * 144 + q4 * 32 + 16) = *(const uint4*)(kvth + gbase + 8);
        *(uint4*)(sm + AT_KVL + row * 144 + q4 * 32) = *(const uint4*)(kvtl + gbase);
        *(uint4*)(sm + AT_KVL + row * 144 + q4 * 32 + 16) = *(const uint4*)(kvtl + gbase + 8);
    }
    if (tid < 64) ((float*)(sm + AT_KS))[tid] = ks[bh * RR + tid];
    __syncthreads();

    if (tid < 128) {
        float d = 1e-6f;
        const float* kss = (const float*)(sm + AT_KS);
#pragma unroll 16
        for (int r = 0; r < 64; r++) {
            float p = __half2float(*(__half*)(sm + AT_PQH + tid * 144 + r * 2))
                    + __half2float(*(__half*)(sm + AT_PQL + tid * 144 + r * 2));
            d += p * kss[r];
        }
        ((float*)(sm + AT_DEN))[tid] = 1.0f / d;
    }
    __syncthreads();

    float acc[2][4][4];
#pragma unroll
    for (int i = 0; i < 2; i++)
#pragma unroll
        for (int j = 0; j < 4; j++)
#pragma unroll
            for (int e = 0; e < 4; e++) acc[i][j][e] = 0.f;

    const int mat = lane >> 3, mr = lane & 7;
    const int a_row_b = warp_m * 32 + (mat & 1) * 8 + mr;
    const int b_row_b = warp_n * 32 + (mat & 1) * 8 + mr;
    const int mchunk = mat >> 1;

#pragma unroll
    for (int kk = 0; kk < 4; kk++) {
        const int ch = kk * 2 + mchunk;
        uint32_t ah[2][4], al[2][4];
#pragma unroll
        for (int im = 0; im < 2; im++) {
            const int row = a_row_b + im * 16;
            ldsm4(ah[im][0], ah[im][1], ah[im][2], ah[im][3],
                  sb + AT_PQH + row * 144 + ch * 16);
            ldsm4(al[im][0], al[im][1], al[im][2], al[im][3],
                  sb + AT_PQL + row * 144 + ch * 16);
        }
#pragma unroll
        for (int nt = 0; nt < 2; nt++) {
            const int row = b_row_b + nt * 16;
            uint32_t h0, h1, h2, h3, l0, l1, l2, l3;
            ldsm4(h0, h1, h2, h3, sb + AT_KVH + row * 144 + ch * 16);
            ldsm4(l0, l1, l2, l3, sb + AT_KVL + row * 144 + ch * 16);
            uint32_t bh0[2] = {h0, h2}, bh1[2] = {h1, h3};
            uint32_t bl0[2] = {l0, l2}, bl1[2] = {l1, l3};
#pragma unroll
            for (int im = 0; im < 2; im++) {
                mma16816(acc[im][nt * 2], ah[im], bh0);
                mma16816(acc[im][nt * 2], ah[im], bl0);
                mma16816(acc[im][nt * 2], al[im], bh0);
                mma16816(acc[im][nt * 2 + 1], ah[im], bh1);
                mma16816(acc[im][nt * 2 + 1], ah[im], bl1);
                mma16816(acc[im][nt * 2 + 1], al[im], bh1);
            }
        }
    }

    const int g = lane >> 2, t = lane & 3;
    const float* rden = (const float*)(sm + AT_DEN);
#pragma unroll
    for (int im = 0; im < 2; im++) {
        const int s0 = warp_m * 32 + im * 16 + g;
        const float rd0 = rden[s0], rd1 = rden[s0 + 8];
        const size_t row0 = ((size_t)b * SS + sbase + s0) * DD + h * HDIM;
        const size_t row1 = row0 + 8 * DD;
#pragma unroll
        for (int j8 = 0; j8 < 4; j8++) {
            const int d = warp_n * 32 + j8 * 8 + t * 2;
            *(uint32_t*)(ahi + row0 + d) =
                pack2h(acc[im][j8][0] * rd0, acc[im][j8][1] * rd0);
            *(uint32_t*)(ahi + row1 + d) =
                pack2h(acc[im][j8][2] * rd1, acc[im][j8][3] * rd1);
        }
    }
}

// ============================================================
// launch
// ============================================================
extern "C" void kernel_launch(void* const* d_in, const int* in_sizes, int n_in,
                              void* d_out, int out_size)
{
    const float* x       = (const float*)d_in[0];
    const float* Wq      = (const float*)d_in[1];
    const float* bq      = (const float*)d_in[2];
    const float* Wk      = (const float*)d_in[3];
    const float* bk      = (const float*)d_in[4];
    const float* Wv      = (const float*)d_in[5];
    const float* bv      = (const float*)d_in[6];
    const float* Wp      = (const float*)d_in[7];
    const float* bp      = (const float*)d_in[8];
    const float* gamma_q = (const float*)d_in[9];
    const float* beta_q  = (const float*)d_in[10];
    const float* gamma_k = (const float*)d_in[11];
    const float* beta_k  = (const float*)d_in[12];
    const float* qG1     = (const float*)d_in[13];
    const float* qG2     = (const float*)d_in[14];
    const float* kG1     = (const float*)d_in[15];
    const float* kG2     = (const float*)d_in[16];
    float* out = (float*)d_out;

    float *p_bqkv, *p_kvtp, *p_ksp, *p_ks;
    __half *p_xhi, *p_xlo, *p_vh, *p_vl, *p_ahi, *p_wth;
    __half *p_pqh, *p_pql, *p_pkth, *p_pktl, *p_kvth, *p_kvtl;
    cudaGetSymbolAddress((void**)&p_xhi, g_xhi);
    cudaGetSymbolAddress((void**)&p_xlo, g_xlo);
    cudaGetSymbolAddress((void**)&p_vh, g_vh);
    cudaGetSymbolAddress((void**)&p_vl, g_vl);
    cudaGetSymbolAddress((void**)&p_ahi, g_ahi);
    cudaGetSymbolAddress((void**)&p_wth, g_wth);
    cudaGetSymbolAddress((void**)&p_bqkv, g_biasqkv);
    cudaGetSymbolAddress((void**)&p_pqh, g_pqh);
    cudaGetSymbolAddress((void**)&p_pql, g_pql);
    cudaGetSymbolAddress((void**)&p_pkth, g_pkth);
    cudaGetSymbolAddress((void**)&p_pktl, g_pktl);
    cudaGetSymbolAddress((void**)&p_kvtp, g_kvtp);
    cudaGetSymbolAddress((void**)&p_ksp, g_ksp);
    cudaGetSymbolAddress((void**)&p_kvth, g_kvth);
    cudaGetSymbolAddress((void**)&p_kvtl, g_kvtl);
    cudaGetSymbolAddress((void**)&p_ks, g_ks);

    cudaFuncSetAttribute(mma_gemm, cudaFuncAttributeMaxDynamicSharedMemorySize,
                         GEMM_SMEM);
    cudaFuncSetAttribute(attn_tc, cudaFuncAttributeMaxDynamicSharedMemorySize,
                         AT_SMEM);

    // ---- prep ----
    split_fp32<<<BSROWS * DD / 4 / 256, 256>>>(x, p_xhi, p_xlo);
    concat_bias<<<6, 256>>>(bq, bk, bv, gamma_q, beta_q, gamma_k, beta_k,
                            p_bqkv);
    g_prep<<<2, 256>>>(qG1, qG2, kG1, kG2);
    transpose_h2<<<dim3(16, 16, 2), 256>>>(Wq, Wk, gamma_q, gamma_k,
                                           p_wth, 0, 512);
    transpose_h2<<<dim3(16, 16, 2), 256>>>(Wv, Wp, nullptr, nullptr,
                                           p_wth, 1024, 1536);

    // ---- fused QKV GEMM + sketch (2-pass A-split) ----
    dim3 gq(6, BSROWS / 128);
    mma_gemm<<<gq, 256, GEMM_SMEM>>>(p_xhi, p_xlo, p_wth, p_bqkv,
                                     p_pqh, p_pql, p_pkth, p_pktl,
                                     p_vh, p_vl, nullptr);

    // ---- TC kvsum + reduce ----
    kvsum_tc<<<dim3(NCHUNK, BH), 256>>>(p_pkth, p_pktl, p_vh, p_vl,
                                        p_kvtp, p_ksp);
    int red_total = BH * HDIM * RR + BH * RR;
    reduce2<<<(red_total + 255) / 256, 256>>>(p_kvtp, p_ksp,
                                              p_kvth, p_kvtl, p_ks);

    // ---- TC attention output (fp16 out) ----
    attn_tc<<<dim3(SS / 128, BH), 256, AT_SMEM>>>(p_pqh, p_pql,
                                                  p_kvth, p_kvtl, p_ks,
                                                  p_ahi);

    // ---- output projection (1-pass fp16, fp32 out) ----
    dim3 go(2, BSROWS / 128);
    mma_gemm<<<go, 256, GEMM_SMEM>>>(p_ahi, nullptr, p_wth + 1536 * DD, bp,
                                     nullptr, nullptr, nullptr, nullptr,
                                     nullptr, nullptr, out);
}

// round 11
// speedup vs baseline: 1.9205x; 1.0833x over previous
#include <cuda_runtime.h>
#include <cuda_fp16.h>
#include <cstdint>

// Problem constants
#define BB 4
#define SS 8192
#define DD 512
#define HH 8
#define HDIM 64
#define RR 64
#define BSROWS (BB * SS)      // 32768
#define BH (BB * HH)          // 32
#define NCHUNK 16

// -------- scratch (static device globals; no allocation) --------
__device__ __half g_xhi[BSROWS * DD];
__device__ __half g_xlo[BSROWS * DD];
__device__ __half g_vh[BSROWS * DD];
__device__ __half g_vl[BSROWS * DD];
__device__ __half g_ahi[BSROWS * DD];
__device__ __half g_wth[4 * DD * DD];     // fp16 transposed weights
__device__ float g_biasqkv[3 * DD];
__device__ __half g_gint_hi[2][128 * 64];
__device__ __half g_gint_lo[2][128 * 64];
__device__ __half g_pqh[BH * SS * RR];    // phiq [bh][s][r], fp16 hi only
__device__ __half g_pkth[BH * RR * SS];   // phikT [bh][r][s], fp16 hi only
__device__ float g_kvtp[BH * NCHUNK * HDIM * RR];
__device__ float g_ksp[BH * NCHUNK * RR];
__device__ __half g_kvth[BH * HDIM * RR];
__device__ __half g_kvtl[BH * HDIM * RR];
__device__ float g_ks[BH * RR];

// ============================================================
// helpers
// ============================================================
__device__ __forceinline__ uint32_t smem_to_u32(const void* p) {
    uint32_t a;
    asm("{ .reg .u64 t; cvta.to.shared.u64 t, %1; cvt.u32.u64 %0, t; }"
        : "=r"(a) : "l"(p));
    return a;
}
__device__ __forceinline__ void ldsm4(uint32_t& r0, uint32_t& r1,
                                      uint32_t& r2, uint32_t& r3,
                                      uint32_t addr) {
    asm volatile("ldmatrix.sync.aligned.m8n8.x4.shared.b16 {%0,%1,%2,%3}, [%4];"
                 : "=r"(r0), "=r"(r1), "=r"(r2), "=r"(r3) : "r"(addr));
}
__device__ __forceinline__ void ldsm4t(uint32_t& r0, uint32_t& r1,
                                       uint32_t& r2, uint32_t& r3,
                                       uint32_t addr) {
    asm volatile("ldmatrix.sync.aligned.m8n8.x4.trans.shared.b16 {%0,%1,%2,%3}, [%4];"
                 : "=r"(r0), "=r"(r1), "=r"(r2), "=r"(r3) : "r"(addr));
}
__device__ __forceinline__ void mma16816(float* d, const uint32_t* a,
                                         const uint32_t* b) {
    asm volatile(
        "mma.sync.aligned.m16n8k16.row.col.f32.f16.f16.f32 "
        "{%0,%1,%2,%3}, {%4,%5,%6,%7}, {%8,%9}, {%0,%1,%2,%3};"
        : "+f"(d[0]), "+f"(d[1]), "+f"(d[2]), "+f"(d[3])
        : "r"(a[0]), "r"(a[1]), "r"(a[2]), "r"(a[3]), "r"(b[0]), "r"(b[1]));
}
#define CP_ASYNC16(dst, src) \
    asm volatile("cp.async.cg.shared.global [%0], [%1], 16;" :: "r"(dst), "l"(src))
#define CP_COMMIT() asm volatile("cp.async.commit_group;" ::: "memory")
#define CP_WAIT(n)  asm volatile("cp.async.wait_group %0;" :: "n"(n) : "memory")

__device__ __forceinline__ void split4h(float4 v, uint2& hi, uint2& lo) {
    __half h0 = __float2half_rn(v.x), h1 = __float2half_rn(v.y);
    __half h2 = __float2half_rn(v.z), h3 = __float2half_rn(v.w);
    float r0 = v.x - __half2float(h0), r1 = v.y - __half2float(h1);
    float r2 = v.z - __half2float(h2), r3 = v.w - __half2float(h3);
    __half l0 = __float2half_rn(r0), l1 = __float2half_rn(r1);
    __half l2 = __float2half_rn(r2), l3 = __float2half_rn(r3);
    hi.x = ((uint32_t)__half_as_ushort(h1) << 16) | __half_as_ushort(h0);
    hi.y = ((uint32_t)__half_as_ushort(h3) << 16) | __half_as_ushort(h2);
    lo.x = ((uint32_t)__half_as_ushort(l1) << 16) | __half_as_ushort(l0);
    lo.y = ((uint32_t)__half_as_ushort(l3) << 16) | __half_as_ushort(l2);
}
__device__ __forceinline__ void split2h(float a, float b, uint32_t& hp, uint32_t& lp) {
    __half h0 = __float2half_rn(a), h1 = __float2half_rn(b);
    float l0 = a - __half2float(h0), l1 = b - __half2float(h1);
    __half e0 = __float2half_rn(l0), e1 = __float2half_rn(l1);
    hp = ((uint32_t)__half_as_ushort(h1) << 16) | __half_as_ushort(h0);
    lp = ((uint32_t)__half_as_ushort(e1) << 16) | __half_as_ushort(e0);
}
__device__ __forceinline__ uint32_t pack2h(float a, float b) {
    __half h0 = __float2half_rn(a), h1 = __float2half_rn(b);
    return ((uint32_t)__half_as_ushort(h1) << 16) | __half_as_ushort(h0);
}

// ============================================================
// prep kernels
// ============================================================
__global__ __launch_bounds__(256) void split_fp32(
    const float* __restrict__ X, __half* __restrict__ Xh,
    __half* __restrict__ Xl)
{
    int i = blockIdx.x * 256 + threadIdx.x;
    float4 v = ((const float4*)X)[i];
    uint2 hi, lo;
    split4h(v, hi, lo);
    ((uint2*)Xh)[i] = hi;
    ((uint2*)Xl)[i] = lo;
}

// all four weight transposes in one launch (z selects)
__global__ __launch_bounds__(256) void transpose_h4(
    const float* __restrict__ Wq, const float* __restrict__ Wk,
    const float* __restrict__ Wv, const float* __restrict__ Wp,
    const float* __restrict__ gq, const float* __restrict__ gk,
    __half* __restrict__ Th)
{
    __shared__ float t[32][33];
    const int z = blockIdx.z;
    const float* W = z == 0 ? Wq : (z == 1 ? Wk : (z == 2 ? Wv : Wp));
    const float scale = z == 0 ? gq[0] : (z == 1 ? gk[0] : 1.0f);
    const int rowoff = z * DD;
    int bx = blockIdx.x * 32, by = blockIdx.y * 32;
    int x = threadIdx.x & 31, y = threadIdx.x >> 5;
    for (int i = y; i < 32; i += 8) t[i][x] = W[(size_t)(by + i) * DD + bx + x];
    __syncthreads();
    for (int i = y; i < 32; i += 8)
        Th[(size_t)(rowoff + bx + i) * DD + by + x] = __float2half_rn(t[x][i] * scale);
}

__global__ void concat_bias(const float* bq, const float* bk, const float* bv,
                            const float* gq, const float* betq,
                            const float* gk, const float* betk,
                            float* bout)
{
    int i = blockIdx.x * 256 + threadIdx.x;
    if (i < DD) bout[i] = gq[0] * bq[i] + betq[0];
    else if (i < 2 * DD) bout[i] = gk[0] * bk[i - DD] + betk[0];
    else if (i < 3 * DD) bout[i] = bv[i - 2 * DD];
}

__global__ __launch_bounds__(256) void g_prep(
    const float* __restrict__ qG1, const float* __restrict__ qG2,
    const float* __restrict__ kG1, const float* __restrict__ kG2)
{
    const int set = blockIdx.x;
    const float* G1 = set ? kG1 : qG1;
    const float* G2 = set ? kG2 : qG2;
    __half* Oh = g_gint_hi[set];
    __half* Ol = g_gint_lo[set];
    for (int it = 0; it < 32; it++) {
        int idx = it * 256 + threadIdx.x;
        int n = idx >> 6, k = idx & 63;
        float v = ((n & 1) ? G2 : G1)[k * 64 + (n >> 1)];
        __half h = __float2half_rn(v);
        Oh[idx] = h;
        Ol[idx] = __float2half_rn(v - __half2float(h));
    }
}

// ============================================================
// fp16 split GEMM + fused sketch epilogue.
// CTA tile 128x256, 8 warps (2m x 4n), warp tile 64x64.
// A-lo pass used only when Alo!=null AND bn<4 (q,k); v (bn>=4) is 1-pass.
// ofp32 set -> proj mode (fp32 out, 1-pass).
// QKV mode: sel = bn>>1: 0 -> q (fused sketch -> phiq hi),
//   1 -> k (fused sketch -> phikT hi), 2 -> v (fp16 hi/lo out).
// ============================================================
#define BKC 32
#define NKCH (DD / BKC)          // 16
#define ROWB 80
#define TILE_A (128 * ROWB)      // 10240
#define TILE_B (256 * ROWB)      // 20480
#define ST_AHI 0
#define ST_ALO TILE_A
#define ST_BH (2 * TILE_A)
#define STAGEB (2 * TILE_A + TILE_B)   // 40960
#define PIPE 4
#define OFF80(row, ch) ((uint32_t)((row) * ROWB + ((ch) << 4)))
// fused sketch regions (reuse smem after mainloop)
#define FZ_HEAD 36864            // per-head z region: hi 18432 + lo 18432
#define FZ_LO 18432
#define FG_OFF (4 * FZ_HEAD)     // 147456
#define FG_LO 18432
#define GEMM_SMEM (FG_OFF + 2 * FG_LO)   // 184320
#define SOFF144(row, ch) ((uint32_t)((row) * 144 + ((ch) << 4)))

__global__ __launch_bounds__(256, 1) void mma_gemm(
    const __half* __restrict__ Ahi, const __half* __restrict__ Alo,
    const __half* __restrict__ Bh, const float* __restrict__ bias,
    __half* __restrict__ pqh, __half* __restrict__ pkth,
    __half* __restrict__ vh, __half* __restrict__ vl,
    float* __restrict__ ofp32)
{
    extern __shared__ char smem[];
    const uint32_t sb = smem_to_u32(smem);

    const int tid = threadIdx.x;
    const int wid = tid >> 5, lane = tid & 31;
    const int bn = blockIdx.x, bm = blockIdx.y;
    const int warp_m = wid & 1, warp_n = wid >> 1;
    const bool useAlo = (Alo != nullptr) && (bn < 4);

    const __half* Ahi_b = Ahi + (size_t)bm * 128 * DD;
    const __half* Alo_b = useAlo ? Alo + (size_t)bm * 128 * DD : Ahi_b;
    const __half* Bh_b = Bh + (size_t)bn * 256 * DD;

    const int lrow = tid >> 2;
    const int lch = tid & 3;

    auto load_chunk = [&](int c, int s) {
        const uint32_t stg = sb + s * STAGEB;
        const int k0 = c * BKC;
#pragma unroll
        for (int sw = 0; sw < 2; sw++) {
            const int row = sw * 64 + lrow;
            const size_t go = (size_t)row * DD + k0 + lch * 8;
            const uint32_t so = OFF80(row, lch);
            CP_ASYNC16(stg + ST_AHI + so, Ahi_b + go);
            if (useAlo) CP_ASYNC16(stg + ST_ALO + so, Alo_b + go);
        }
#pragma unroll
        for (int sw = 0; sw < 4; sw++) {
            const int row = sw * 64 + lrow;
            const size_t go = (size_t)row * DD + k0 + lch * 8;
            CP_ASYNC16(stg + ST_BH + OFF80(row, lch), Bh_b + go);
        }
    };

    float acc[4][8][4];
#pragma unroll
    for (int i = 0; i < 4; i++)
#pragma unroll
        for (int j = 0; j < 8; j++)
#pragma unroll
            for (int e = 0; e < 4; e++) acc[i][j][e] = 0.f;

    const int mat = lane >> 3, mr = lane & 7;
    const int a_row_b = warp_m * 64 + (mat & 1) * 8 + mr;
    const int b_row_b = warp_n * 64 + (mat & 1) * 8 + mr;
    const int mchunk = mat >> 1;

    load_chunk(0, 0); CP_COMMIT();
    load_chunk(1, 1); CP_COMMIT();
    load_chunk(2, 2); CP_COMMIT();

    for (int c = 0; c < NKCH; c++) {
        CP_WAIT(2);
        __syncthreads();
        if (c + 3 < NKCH) load_chunk(c + 3, (c + 3) % PIPE);
        CP_COMMIT();

        const uint32_t stg = sb + (c % PIPE) * STAGEB;
#pragma unroll
        for (int kk = 0; kk < 2; kk++) {
            const int ch = kk * 2 + mchunk;
            uint32_t ahi[4][4], alo[4][4];
#pragma unroll
            for (int im = 0; im < 4; im++) {
                const int row = a_row_b + im * 16;
                ldsm4(ahi[im][0], ahi[im][1], ahi[im][2], ahi[im][3],
                      stg + ST_AHI + OFF80(row, ch));
                if (useAlo)
                    ldsm4(alo[im][0], alo[im][1], alo[im][2], alo[im][3],
                          stg + ST_ALO + OFF80(row, ch));
            }
#pragma unroll
            for (int j16 = 0; j16 < 4; j16++) {
                const int row = b_row_b + j16 * 16;
                uint32_t h0, h1, h2, h3;
                ldsm4(h0, h1, h2, h3, stg + ST_BH + OFF80(row, ch));
                uint32_t bh0[2] = {h0, h2}, bh1[2] = {h1, h3};
#pragma unroll
                for (int im = 0; im < 4; im++) {
                    mma16816(acc[im][j16 * 2], ahi[im], bh0);
                    mma16816(acc[im][j16 * 2 + 1], ahi[im], bh1);
                    if (useAlo) {
                        mma16816(acc[im][j16 * 2], alo[im], bh0);
                        mma16816(acc[im][j16 * 2 + 1], alo[im], bh1);
                    }
                }
            }
        }
    }

    const int erow = lane >> 2, ecol = (lane & 3) * 2;

    if (ofp32) {
        // ---- projection epilogue: fp32 out ----
        const int colbase = bn * 256;
#pragma unroll
        for (int im = 0; im < 4; im++) {
            const size_t row0 = (size_t)bm * 128 + warp_m * 64 + im * 16 + erow;
#pragma unroll
            for (int t = 0; t < 8; t++) {
                const int cofs = warp_n * 64 + t * 8 + ecol;
                float2 b2 = *(const float2*)&bias[colbase + cofs];
                float2 q0 = make_float2(acc[im][t][0] + b2.x, acc[im][t][1] + b2.y);
                float2 q1 = make_float2(acc[im][t][2] + b2.x, acc[im][t][3] + b2.y);
                *(float2*)&ofp32[row0 * DD + colbase + cofs] = q0;
                *(float2*)&ofp32[(row0 + 8) * DD + colbase + cofs] = q1;
            }
        }
        return;
    }

    const int sel = bn >> 1;
    if (sel == 2) {
        // ---- v epilogue: fp16 hi/lo ----
        const int colbase = (bn & 1) * 256;
#pragma unroll
        for (int im = 0; im < 4; im++) {
            const size_t row0 = (size_t)bm * 128 + warp_m * 64 + im * 16 + erow;
#pragma unroll
            for (int t = 0; t < 8; t++) {
                const int cofs = warp_n * 64 + t * 8 + ecol;
                float2 b2 = *(const float2*)&bias[bn * 256 + cofs];
                uint32_t hp, lp;
                split2h(acc[im][t][0] + b2.x, acc[im][t][1] + b2.y, hp, lp);
                *(uint32_t*)(vh + row0 * DD + colbase + cofs) = hp;
                *(uint32_t*)(vl + row0 * DD + colbase + cofs) = lp;
                split2h(acc[im][t][2] + b2.x, acc[im][t][3] + b2.y, hp, lp);
                *(uint32_t*)(vh + (row0 + 8) * DD + colbase + cofs) = hp;
                *(uint32_t*)(vl + (row0 + 8) * DD + colbase + cofs) = lp;
            }
        }
        return;
    }

    // ================= fused sketch epilogue (sel 0 = q, 1 = k) ==========
    CP_WAIT(0);
    __syncthreads();   // mainloop smem no longer needed

    // stage z = acc + bias as fp16 hi/lo, per head (4 heads per CTA tile)
#pragma unroll
    for (int im = 0; im < 4; im++) {
        const int row = warp_m * 64 + im * 16 + erow;
#pragma unroll
        for (int t = 0; t < 8; t++) {
            const int cofs = warp_n * 64 + t * 8 + ecol;
            const int head = cofs >> 6, c = cofs & 63;
            float2 b2 = *(const float2*)&bias[bn * 256 + cofs];
            uint32_t hp, lp;
            split2h(acc[im][t][0] + b2.x, acc[im][t][1] + b2.y, hp, lp);
            *(uint32_t*)(smem + head * FZ_HEAD + row * 144 + c * 2) = hp;
            *(uint32_t*)(smem + head * FZ_HEAD + FZ_LO + row * 144 + c * 2) = lp;
            split2h(acc[im][t][2] + b2.x, acc[im][t][3] + b2.y, hp, lp);
            *(uint32_t*)(smem + head * FZ_HEAD + (row + 8) * 144 + c * 2) = hp;
            *(uint32_t*)(smem + head * FZ_HEAD + FZ_LO + (row + 8) * 144 + c * 2) = lp;
        }
    }
    // load G-int (hi/lo) for this set
    {
        const __half* Gh = &g_gint_hi[sel][0];
        const __half* Gl = &g_gint_lo[sel][0];
#pragma unroll
        for (int it = 0; it < 4; it++) {
            const int cidx = it * 256 + tid;
            const int row = cidx >> 3, ch = cidx & 7;
            *(uint4*)(smem + FG_OFF + SOFF144(row, ch)) =
                *(const uint4*)((const char*)Gh + row * 128 + ch * 16);
            *(uint4*)(smem + FG_OFF + FG_LO + SOFF144(row, ch)) =
                *(const uint4*)((const char*)Gl + row * 128 + ch * 16);
        }
    }
    __syncthreads();

    // sketch warp mapping
    const int swm = wid & 1, swn = wid >> 1;
    const int a_row_s = swm * 64 + (mat & 1) * 8 + mr;
    const int b_row_s = swn * 32 + (mat & 1) * 8 + mr;
    const int b = bm >> 6;
    const int sbase = (bm & 63) * 128;
    const int g = lane >> 2, t4 = lane & 3;
    const float inv = 0.125f;

    for (int hd = 0; hd < 4; hd++) {
        const uint32_t zb = sb + hd * FZ_HEAD;

        float sk[4][4][4];
#pragma unroll
        for (int i = 0; i < 4; i++)
#pragma unroll
            for (int j = 0; j < 4; j++)
#pragma unroll
                for (int e = 0; e < 4; e++) sk[i][j][e] = 0.f;

#pragma unroll
        for (int kk = 0; kk < 4; kk++) {
            const int ch = kk * 2 + mchunk;
            uint32_t zhi[4][4], zlo[4][4];
#pragma unroll
            for (int im = 0; im < 4; im++) {
                const int row = a_row_s + im * 16;
                ldsm4(zhi[im][0], zhi[im][1], zhi[im][2], zhi[im][3],
                      zb + SOFF144(row, ch));
                ldsm4(zlo[im][0], zlo[im][1], zlo[im][2], zlo[im][3],
                      zb + FZ_LO + SOFF144(row, ch));
            }
#pragma unroll
            for (int j16 = 0; j16 < 2; j16++) {
                const int row = b_row_s + j16 * 16;
                uint32_t h0, h1, h2, h3, l0, l1, l2, l3;
                ldsm4(h0, h1, h2, h3, sb + FG_OFF + SOFF144(row, ch));
                ldsm4(l0, l1, l2, l3, sb + FG_OFF + FG_LO + SOFF144(row, ch));
                uint32_t gh0[2] = {h0, h2}, gh1[2] = {h1, h3};
                uint32_t gl0[2] = {l0, l2}, gl1[2] = {l1, l3};
#pragma unroll
                for (int im = 0; im < 4; im++) {
                    mma16816(sk[im][j16 * 2], zhi[im], gh0);
                    mma16816(sk[im][j16 * 2], zhi[im], gl0);
                    mma16816(sk[im][j16 * 2], zlo[im], gh0);
                    mma16816(sk[im][j16 * 2 + 1], zhi[im], gh1);
                    mma16816(sk[im][j16 * 2 + 1], zhi[im], gl1);
                    mma16816(sk[im][j16 * 2 + 1], zlo[im], gh1);
                }
            }
        }

        const int h = (bn & 1) * 4 + hd;
        const int bh2 = b * HH + h;
        __syncthreads();   // all warps done reading z[hd]; reuse for staging

        __half* SH = (__half*)(smem + hd * FZ_HEAD);
        if (sel == 0) {
            // stage phiq hi [128][72]
#pragma unroll
            for (int im = 0; im < 4; im++) {
                const int s0 = swm * 64 + im * 16 + g;
#pragma unroll
                for (int jn = 0; jn < 4; jn++) {
                    const int r = swn * 16 + jn * 4 + t4;
                    float h0 = inv * sk[im][jn][0] * sk[im][jn][1];
                    float h1 = inv * sk[im][jn][2] * sk[im][jn][3];
                    SH[s0 * 72 + r] = __float2half_rn(h0 * h0);
                    SH[(s0 + 8) * 72 + r] = __float2half_rn(h1 * h1);
                }
            }
            __syncthreads();
            const int row = tid >> 1, hf = tid & 1;
            size_t gbase = ((size_t)bh2 * SS + sbase + row) * RR + hf * 32;
            const uint4* srcH = (const uint4*)(smem + hd * FZ_HEAD + row * 144 + hf * 64);
#pragma unroll
            for (int i = 0; i < 4; i++) ((uint4*)(pqh + gbase))[i] = srcH[i];
        } else {
            // stage phikT hi [64 r][136 s]
#pragma unroll
            for (int im = 0; im < 4; im++) {
                const int s0 = swm * 64 + im * 16 + g;
#pragma unroll
                for (int jn = 0; jn < 4; jn++) {
                    const int r = swn * 16 + jn * 4 + t4;
                    float h0 = inv * sk[im][jn][0] * sk[im][jn][1];
                    float h1 = inv * sk[im][jn][2] * sk[im][jn][3];
                    SH[r * 136 + s0] = __float2half_rn(h0 * h0);
                    SH[r * 136 + s0 + 8] = __float2half_rn(h1 * h1);
                }
            }
            __syncthreads();
            const int r = tid >> 2, q4 = tid & 3;
            size_t gbase = ((size_t)bh2 * RR + r) * SS + sbase + q4 * 32;
            const uint4* srcH = (const uint4*)(smem + hd * FZ_HEAD + r * 272 + q4 * 64);
#pragma unroll
            for (int i = 0; i < 4; i++) ((uint4*)(pkth + gbase))[i] = srcH[i];
        }
    }
}

// ============================================================
// TC kvsum (2-pass: v hi/lo x phik hi): kvT[d][r] = sum_s v[s,d]*phik[s,r]
// ============================================================
__global__ __launch_bounds__(256) void kvsum_tc(
    const __half* __restrict__ pkth,
    const __half* __restrict__ vh, const __half* __restrict__ vl,
    float* __restrict__ kvtp, float* __restrict__ ksp)
{
    __shared__ __align__(16) char sm[3 * 64 * 144];   // 27648
    const uint32_t sb = smem_to_u32(sm);
    const uint32_t VHI = 0, VLO = 9216, PKH = 18432;

    const int tid = threadIdx.x;
    const int wid = tid >> 5, lane = tid & 31;
    const int chunk = blockIdx.x, bh = blockIdx.y;
    const int b = bh >> 3, h = bh & 7;
    const int warp_m = wid & 1, warp_n = wid >> 1;
    const int mat = lane >> 3, mr = lane & 7;
    const int g = lane >> 2, t = lane & 3;

    float acc[2][2][4];
#pragma unroll
    for (int i = 0; i < 2; i++)
#pragma unroll
        for (int j = 0; j < 2; j++)
#pragma unroll
            for (int e = 0; e < 4; e++) acc[i][j][e] = 0.f;
    float kacc = 0.f;

    const int lr = tid >> 2, lq = tid & 3;
    const int kr = tid & 63, kg = tid >> 6;

    for (int step = 0; step < 8; step++) {
        const int s0 = chunk * 512 + step * 64;
        {
            const size_t vo = (size_t)(b * SS + s0 + lr) * DD + h * HDIM + lq * 16;
            *(uint4*)(sm + VHI + lr * 144 + lq * 32) = *(const uint4*)(vh + vo);
            *(uint4*)(sm + VHI + lr * 144 + lq * 32 + 16) = *(const uint4*)(vh + vo + 8);
            *(uint4*)(sm + VLO + lr * 144 + lq * 32) = *(const uint4*)(vl + vo);
            *(uint4*)(sm + VLO + lr * 144 + lq * 32 + 16) = *(const uint4*)(vl + vo + 8);
            const size_t po = ((size_t)bh * RR + lr) * SS + s0 + lq * 16;
            *(uint4*)(sm + PKH + lr * 144 + lq * 32) = *(const uint4*)(pkth + po);
            *(uint4*)(sm + PKH + lr * 144 + lq * 32 + 16) = *(const uint4*)(pkth + po + 8);
        }
        __syncthreads();

#pragma unroll
        for (int c = 0; c < 16; c++) {
            int sc = kg * 16 + c;
            kacc += __half2float(*(__half*)(sm + PKH + kr * 144 + sc * 2));
        }

#pragma unroll
        for (int kk = 0; kk < 4; kk++) {
            uint32_t ah[2][4], al[2][4];
#pragma unroll
            for (int im = 0; im < 2; im++) {
                const int d0 = warp_m * 32 + im * 16 + (mat & 1) * 8;
                const int srow = kk * 16 + ((mat >> 1) & 1) * 8 + mr;
                ldsm4t(ah[im][0], ah[im][1], ah[im][2], ah[im][3],
                       sb + VHI + srow * 144 + d0 * 2);
                ldsm4t(al[im][0], al[im][1], al[im][2], al[im][3],
                       sb + VLO + srow * 144 + d0 * 2);
            }
            const int rrow = warp_n * 16 + (mat & 1) * 8 + mr;
            const int chb = kk * 2 + (mat >> 1);
            uint32_t h0, h1, h2, h3;
            ldsm4(h0, h1, h2, h3, sb + PKH + rrow * 144 + chb * 16);
            uint32_t bh0[2] = {h0, h2}, bh1[2] = {h1, h3};
#pragma unroll
            for (int im = 0; im < 2; im++) {
                mma16816(acc[im][0], ah[im], bh0);
                mma16816(acc[im][0], al[im], bh0);
                mma16816(acc[im][1], ah[im], bh1);
                mma16816(acc[im][1], al[im], bh1);
            }
        }
        __syncthreads();
    }

    float* outp = kvtp + ((size_t)bh * NCHUNK + chunk) * (HDIM * RR);
#pragma unroll
    for (int im = 0; im < 2; im++) {
        const int d = warp_m * 32 + im * 16 + g;
#pragma unroll
        for (int nb = 0; nb < 2; nb++) {
            const int r = warp_n * 16 + nb * 8 + t * 2;
            *(float2*)&outp[d * RR + r] =
                make_float2(acc[im][nb][0], acc[im][nb][1]);
            *(float2*)&outp[(d + 8) * RR + r] =
                make_float2(acc[im][nb][2], acc[im][nb][3]);
        }
    }
    __syncthreads();
    float* red = (float*)sm;
    red[kg * 64 + kr] = kacc;
    __syncthreads();
    if (tid < 64)
        ksp[((size_t)bh * NCHUNK + chunk) * RR + tid] =
            red[tid] + red[64 + tid] + red[128 + tid] + red[192 + tid];
}

__global__ void reduce2(const float* __restrict__ kvtp,
                        const float* __restrict__ ksp,
                        __half* __restrict__ kvth, __half* __restrict__ kvtl,
                        float* __restrict__ ks)
{
    const int idx = blockIdx.x * 256 + threadIdx.x;
    const int total = BH * HDIM * RR;
    if (idx < total) {
        int bh = idx >> 12, e = idx & 4095;
        float s = 0.f;
#pragma unroll
        for (int c = 0; c < NCHUNK; c++)
            s += kvtp[((size_t)bh * NCHUNK + c) * 4096 + e];
        __half hi = __float2half_rn(s);
        kvth[idx] = hi;
        kvtl[idx] = __float2half_rn(s - __half2float(hi));
    } else if (idx < total + BH * RR) {
        int j = idx - total;
        int bh = j >> 6, r = j & 63;
        float s = 0.f;
#pragma unroll
        for (int c = 0; c < NCHUNK; c++)
            s += ksp[((size_t)bh * NCHUNK + c) * RR + r];
        ks[j] = s;
    }
}

// ============================================================
// TC attn (2-pass: phiq hi x kv hi/lo): out = (phiq @ kvT) / den, fp16 out
// ============================================================
#define AT_PQH 0
#define AT_KVH (128 * 144)
#define AT_KVL (AT_KVH + 64 * 144)
#define AT_KS  (AT_KVL + 64 * 144)
#define AT_DEN (AT_KS + 256)
#define AT_SMEM (AT_DEN + 512 + 256)

__global__ __launch_bounds__(256) void attn_tc(
    const __half* __restrict__ pqh,
    const __half* __restrict__ kvth, const __half* __restrict__ kvtl,
    const float* __restrict__ ks,
    __half* __restrict__ ahi)
{
    extern __shared__ char sm[];
    const uint32_t sb = smem_to_u32(sm);
    const int tid = threadIdx.x;
    const int wid = tid >> 5, lane = tid & 31;
    const int stile = blockIdx.x, bh = blockIdx.y;
    const int b = bh >> 3, h = bh & 7;
    const int sbase = stile * 128;
    const int warp_m = wid >> 1, warp_n = wid & 1;

    {
        const int row = tid >> 1, half = tid & 1;
        size_t gbase = ((size_t)bh * SS + sbase + row) * RR + half * 32;
        uint4* dstH = (uint4*)(sm + AT_PQH + row * 144 + half * 64);
#pragma unroll
        for (int i = 0; i < 4; i++) dstH[i] = ((const uint4*)(pqh + gbase))[i];
    }
    {
        const int row = tid >> 2, q4 = tid & 3;
        size_t gbase = (size_t)bh * (HDIM * RR) + row * RR + q4 * 16;
        *(uint4*)(sm + AT_KVH + row * 144 + q4 * 32) = *(const uint4*)(kvth + gbase);
        *(uint4*)(sm + AT_KVH + row * 144 + q4 * 32 + 16) = *(const uint4*)(kvth + gbase + 8);
        *(uint4*)(sm + AT_KVL + row * 144 + q4 * 32) = *(const uint4*)(kvtl + gbase);
        *(uint4*)(sm + AT_KVL + row * 144 + q4 * 32 + 16) = *(const uint4*)(kvtl + gbase + 8);
    }
    if (tid < 64) ((float*)(sm + AT_KS))[tid] = ks[bh * RR + tid];
    __syncthreads();

    if (tid < 128) {
        float d = 1e-6f;
        const float* kss = (const float*)(sm + AT_KS);
#pragma unroll 16
        for (int r = 0; r < 64; r++) {
            float p = __half2float(*(__half*)(sm + AT_PQH + tid * 144 + r * 2));
            d += p * kss[r];
        }
        ((float*)(sm + AT_DEN))[tid] = 1.0f / d;
    }
    __syncthreads();

    float acc[2][4][4];
#pragma unroll
    for (int i = 0; i < 2; i++)
#pragma unroll
        for (int j = 0; j < 4; j++)
#pragma unroll
            for (int e = 0; e < 4; e++) acc[i][j][e] = 0.f;

    const int mat = lane >> 3, mr = lane & 7;
    const int a_row_b = warp_m * 32 + (mat & 1) * 8 + mr;
    const int b_row_b = warp_n * 32 + (mat & 1) * 8 + mr;
    const int mchunk = mat >> 1;

#pragma unroll
    for (int kk = 0; kk < 4; kk++) {
        const int ch = kk * 2 + mchunk;
        uint32_t ah[2][4];
#pragma unroll
        for (int im = 0; im < 2; im++) {
            const int row = a_row_b + im * 16;
            ldsm4(ah[im][0], ah[im][1], ah[im][2], ah[im][3],
                  sb + AT_PQH + row * 144 + ch * 16);
        }
#pragma unroll
        for (int nt = 0; nt < 2; nt++) {
            const int row = b_row_b + nt * 16;
            uint32_t h0, h1, h2, h3, l0, l1, l2, l3;
            ldsm4(h0, h1, h2, h3, sb + AT_KVH + row * 144 + ch * 16);
            ldsm4(l0, l1, l2, l3, sb + AT_KVL + row * 144 + ch * 16);
            uint32_t bh0[2] = {h0, h2}, bh1[2] = {h1, h3};
            uint32_t bl0[2] = {l0, l2}, bl1[2] = {l1, l3};
#pragma unroll
            for (int im = 0; im < 2; im++) {
                mma16816(acc[im][nt * 2], ah[im], bh0);
                mma16816(acc[im][nt * 2], ah[im], bl0);
                mma16816(acc[im][nt * 2 + 1], ah[im], bh1);
                mma16816(acc[im][nt * 2 + 1], ah[im], bl1);
            }
        }
    }

    const int g = lane >> 2, t = lane & 3;
    const float* rden = (const float*)(sm + AT_DEN);
#pragma unroll
    for (int im = 0; im < 2; im++) {
        const int s0 = warp_m * 32 + im * 16 + g;
        const float rd0 = rden[s0], rd1 = rden[s0 + 8];
        const size_t row0 = ((size_t)b * SS + sbase + s0) * DD + h * HDIM;
        const size_t row1 = row0 + 8 * DD;
#pragma unroll
        for (int j8 = 0; j8 < 4; j8++) {
            const int d = warp_n * 32 + j8 * 8 + t * 2;
            *(uint32_t*)(ahi + row0 + d) =
                pack2h(acc[im][j8][0] * rd0, acc[im][j8][1] * rd0);
            *(uint32_t*)(ahi + row1 + d) =
                pack2h(acc[im][j8][2] * rd1, acc[im][j8][3] * rd1);
        }
    }
}

// ============================================================
// launch
// ============================================================
extern "C" void kernel_launch(void* const* d_in, const int* in_sizes, int n_in,
                              void* d_out, int out_size)
{
    const float* x       = (const float*)d_in[0];
    const float* Wq      = (const float*)d_in[1];
    const float* bq      = (const float*)d_in[2];
    const float* Wk      = (const float*)d_in[3];
    const float* bk      = (const float*)d_in[4];
    const float* Wv      = (const float*)d_in[5];
    const float* bv      = (const float*)d_in[6];
    const float* Wp      = (const float*)d_in[7];
    const float* bp      = (const float*)d_in[8];
    const float* gamma_q = (const float*)d_in[9];
    const float* beta_q  = (const float*)d_in[10];
    const float* gamma_k = (const float*)d_in[11];
    const float* beta_k  = (const float*)d_in[12];
    const float* qG1     = (const float*)d_in[13];
    const float* qG2     = (const float*)d_in[14];
    const float* kG1     = (const float*)d_in[15];
    const float* kG2     = (const float*)d_in[16];
    float* out = (float*)d_out;

    float *p_bqkv, *p_kvtp, *p_ksp, *p_ks;
    __half *p_xhi, *p_xlo, *p_vh, *p_vl, *p_ahi, *p_wth;
    __half *p_pqh, *p_pkth, *p_kvth, *p_kvtl;
    cudaGetSymbolAddress((void**)&p_xhi, g_xhi);
    cudaGetSymbolAddress((void**)&p_xlo, g_xlo);
    cudaGetSymbolAddress((void**)&p_vh, g_vh);
    cudaGetSymbolAddress((void**)&p_vl, g_vl);
    cudaGetSymbolAddress((void**)&p_ahi, g_ahi);
    cudaGetSymbolAddress((void**)&p_wth, g_wth);
    cudaGetSymbolAddress((void**)&p_bqkv, g_biasqkv);
    cudaGetSymbolAddress((void**)&p_pqh, g_pqh);
    cudaGetSymbolAddress((void**)&p_pkth, g_pkth);
    cudaGetSymbolAddress((void**)&p_kvtp, g_kvtp);
    cudaGetSymbolAddress((void**)&p_ksp, g_ksp);
    cudaGetSymbolAddress((void**)&p_kvth, g_kvth);
    cudaGetSymbolAddress((void**)&p_kvtl, g_kvtl);
    cudaGetSymbolAddress((void**)&p_ks, g_ks);

    cudaFuncSetAttribute(mma_gemm, cudaFuncAttributeMaxDynamicSharedMemorySize,
                         GEMM_SMEM);
    cudaFuncSetAttribute(attn_tc, cudaFuncAttributeMaxDynamicSharedMemorySize,
                         AT_SMEM);

    // ---- prep (4 launches; mma_gemm is launch #5) ----
    split_fp32<<<BSROWS * DD / 4 / 256, 256>>>(x, p_xhi, p_xlo);               // 1
    concat_bias<<<6, 256>>>(bq, bk, bv, gamma_q, beta_q, gamma_k, beta_k,
                            p_bqkv);                                           // 2
    g_prep<<<2, 256>>>(qG1, qG2, kG1, kG2);                                    // 3
    transpose_h4<<<dim3(16, 16, 4), 256>>>(Wq, Wk, Wv, Wp,
                                           gamma_q, gamma_k, p_wth);           // 4

    // ---- fused QKV GEMM + sketch (q,k 2-pass; v 1-pass) ----
    dim3 gq(6, BSROWS / 128);
    mma_gemm<<<gq, 256, GEMM_SMEM>>>(p_xhi, p_xlo, p_wth, p_bqkv,
                                     p_pqh, p_pkth, p_vh, p_vl, nullptr);      // 5

    // ---- TC kvsum + reduce ----
    kvsum_tc<<<dim3(NCHUNK, BH), 256>>>(p_pkth, p_vh, p_vl, p_kvtp, p_ksp);
    int red_total = BH * HDIM * RR + BH * RR;
    reduce2<<<(red_total + 255) / 256, 256>>>(p_kvtp, p_ksp,
                                              p_kvth, p_kvtl, p_ks);

    // ---- TC attention output (fp16 out) ----
    attn_tc<<<dim3(SS / 128, BH), 256, AT_SMEM>>>(p_pqh, p_kvth, p_kvtl,
                                                  p_ks, p_ahi);

    // ---- output projection (1-pass fp16, fp32 out) ----
    dim3 go(2, BSROWS / 128);
    mma_gemm<<<go, 256, GEMM_SMEM>>>(p_ahi, nullptr, p_wth + 1536 * DD, bp,
                                     nullptr, nullptr, nullptr, nullptr, out);
}

// round 12
// speedup vs baseline: 1.9701x; 1.0258x over previous
#include <cuda_runtime.h>
#include <cuda_fp16.h>
#include <cstdint>

// Problem constants
#define BB 4
#define SS 8192
#define DD 512
#define HH 8
#define HDIM 64
#define RR 64
#define BSROWS (BB * SS)      // 32768
#define BH (BB * HH)          // 32
#define NCHUNK 16

// -------- scratch (static device globals; no allocation) --------
__device__ __half g_xhi[BSROWS * DD];
__device__ __half g_xlo[BSROWS * DD];
__device__ __half g_vh[BSROWS * DD];
__device__ __half g_ahi[BSROWS * DD];
__device__ __half g_wth[4 * DD * DD];     // fp16 transposed weights
__device__ float g_biasqkv[3 * DD];
__device__ __half g_gint_hi[2][128 * 64];
__device__ __half g_gint_lo[2][128 * 64];
__device__ __half g_pqh[BH * SS * RR];    // phiq [bh][s][r], fp16 hi only
__device__ __half g_pkth[BH * RR * SS];   // phikT [bh][r][s], fp16 hi only
__device__ float g_kvtp[BH * NCHUNK * HDIM * RR];
__device__ float g_ksp[BH * NCHUNK * RR];
__device__ __half g_kvth[BH * HDIM * RR];
__device__ float g_ks[BH * RR];

// ============================================================
// helpers
// ============================================================
__device__ __forceinline__ uint32_t smem_to_u32(const void* p) {
    uint32_t a;
    asm("{ .reg .u64 t; cvta.to.shared.u64 t, %1; cvt.u32.u64 %0, t; }"
        : "=r"(a) : "l"(p));
    return a;
}
__device__ __forceinline__ void ldsm4(uint32_t& r0, uint32_t& r1,
                                      uint32_t& r2, uint32_t& r3,
                                      uint32_t addr) {
    asm volatile("ldmatrix.sync.aligned.m8n8.x4.shared.b16 {%0,%1,%2,%3}, [%4];"
                 : "=r"(r0), "=r"(r1), "=r"(r2), "=r"(r3) : "r"(addr));
}
__device__ __forceinline__ void ldsm4t(uint32_t& r0, uint32_t& r1,
                                       uint32_t& r2, uint32_t& r3,
                                       uint32_t addr) {
    asm volatile("ldmatrix.sync.aligned.m8n8.x4.trans.shared.b16 {%0,%1,%2,%3}, [%4];"
                 : "=r"(r0), "=r"(r1), "=r"(r2), "=r"(r3) : "r"(addr));
}
__device__ __forceinline__ void mma16816(float* d, const uint32_t* a,
                                         const uint32_t* b) {
    asm volatile(
        "mma.sync.aligned.m16n8k16.row.col.f32.f16.f16.f32 "
        "{%0,%1,%2,%3}, {%4,%5,%6,%7}, {%8,%9}, {%0,%1,%2,%3};"
        : "+f"(d[0]), "+f"(d[1]), "+f"(d[2]), "+f"(d[3])
        : "r"(a[0]), "r"(a[1]), "r"(a[2]), "r"(a[3]), "r"(b[0]), "r"(b[1]));
}
#define CP_ASYNC16(dst, src) \
    asm volatile("cp.async.cg.shared.global [%0], [%1], 16;" :: "r"(dst), "l"(src))
#define CP_COMMIT() asm volatile("cp.async.commit_group;" ::: "memory")
#define CP_WAIT(n)  asm volatile("cp.async.wait_group %0;" :: "n"(n) : "memory")

__device__ __forceinline__ void split4h(float4 v, uint2& hi, uint2& lo) {
    __half h0 = __float2half_rn(v.x), h1 = __float2half_rn(v.y);
    __half h2 = __float2half_rn(v.z), h3 = __float2half_rn(v.w);
    float r0 = v.x - __half2float(h0), r1 = v.y - __half2float(h1);
    float r2 = v.z - __half2float(h2), r3 = v.w - __half2float(h3);
    __half l0 = __float2half_rn(r0), l1 = __float2half_rn(r1);
    __half l2 = __float2half_rn(r2), l3 = __float2half_rn(r3);
    hi.x = ((uint32_t)__half_as_ushort(h1) << 16) | __half_as_ushort(h0);
    hi.y = ((uint32_t)__half_as_ushort(h3) << 16) | __half_as_ushort(h2);
    lo.x = ((uint32_t)__half_as_ushort(l1) << 16) | __half_as_ushort(l0);
    lo.y = ((uint32_t)__half_as_ushort(l3) << 16) | __half_as_ushort(l2);
}
__device__ __forceinline__ void split2h(float a, float b, uint32_t& hp, uint32_t& lp) {
    __half h0 = __float2half_rn(a), h1 = __float2half_rn(b);
    float l0 = a - __half2float(h0), l1 = b - __half2float(h1);
    __half e0 = __float2half_rn(l0), e1 = __float2half_rn(l1);
    hp = ((uint32_t)__half_as_ushort(h1) << 16) | __half_as_ushort(h0);
    lp = ((uint32_t)__half_as_ushort(e1) << 16) | __half_as_ushort(e0);
}
__device__ __forceinline__ uint32_t pack2h(float a, float b) {
    __half h0 = __float2half_rn(a), h1 = __float2half_rn(b);
    return ((uint32_t)__half_as_ushort(h1) << 16) | __half_as_ushort(h0);
}

// ============================================================
// prep kernels
// ============================================================
__global__ __launch_bounds__(256) void split_fp32(
    const float* __restrict__ X, __half* __restrict__ Xh,
    __half* __restrict__ Xl)
{
    int i = blockIdx.x * 256 + threadIdx.x;
    float4 v = ((const float4*)X)[i];
    uint2 hi, lo;
    split4h(v, hi, lo);
    ((uint2*)Xh)[i] = hi;
    ((uint2*)Xl)[i] = lo;
}

__global__ __launch_bounds__(256) void transpose_h4(
    const float* __restrict__ Wq, const float* __restrict__ Wk,
    const float* __restrict__ Wv, const float* __restrict__ Wp,
    const float* __restrict__ gq, const float* __restrict__ gk,
    __half* __restrict__ Th)
{
    __shared__ float t[32][33];
    const int z = blockIdx.z;
    const float* W = z == 0 ? Wq : (z == 1 ? Wk : (z == 2 ? Wv : Wp));
    const float scale = z == 0 ? gq[0] : (z == 1 ? gk[0] : 1.0f);
    const int rowoff = z * DD;
    int bx = blockIdx.x * 32, by = blockIdx.y * 32;
    int x = threadIdx.x & 31, y = threadIdx.x >> 5;
    for (int i = y; i < 32; i += 8) t[i][x] = W[(size_t)(by + i) * DD + bx + x];
    __syncthreads();
    for (int i = y; i < 32; i += 8)
        Th[(size_t)(rowoff + bx + i) * DD + by + x] = __float2half_rn(t[x][i] * scale);
}

__global__ void concat_bias(const float* bq, const float* bk, const float* bv,
                            const float* gq, const float* betq,
                            const float* gk, const float* betk,
                            float* bout)
{
    int i = blockIdx.x * 256 + threadIdx.x;
    if (i < DD) bout[i] = gq[0] * bq[i] + betq[0];
    else if (i < 2 * DD) bout[i] = gk[0] * bk[i - DD] + betk[0];
    else if (i < 3 * DD) bout[i] = bv[i - 2 * DD];
}

__global__ __launch_bounds__(256) void g_prep(
    const float* __restrict__ qG1, const float* __restrict__ qG2,
    const float* __restrict__ kG1, const float* __restrict__ kG2)
{
    const int set = blockIdx.x;
    const float* G1 = set ? kG1 : qG1;
    const float* G2 = set ? kG2 : qG2;
    __half* Oh = g_gint_hi[set];
    __half* Ol = g_gint_lo[set];
    for (int it = 0; it < 32; it++) {
        int idx = it * 256 + threadIdx.x;
        int n = idx >> 6, k = idx & 63;
        float v = ((n & 1) ? G2 : G1)[k * 64 + (n >> 1)];
        __half h = __float2half_rn(v);
        Oh[idx] = h;
        Ol[idx] = __float2half_rn(v - __half2float(h));
    }
}

// ============================================================
// fp16 split GEMM + fused sketch epilogue.
// CTA tile 128x256, 8 warps (2m x 4n), warp tile 64x64.
// A-lo pass used only when Alo!=null AND bn<4 (q,k); v (bn>=4) is 1-pass.
// ofp32 set -> proj mode (fp32 out, 1-pass).
// QKV mode: sel = bn>>1: 0 -> q (fused sketch -> phiq hi),
//   1 -> k (fused sketch -> phikT hi), 2 -> v (fp16 hi out).
// ============================================================
#define BKC 32
#define NKCH (DD / BKC)          // 16
#define ROWB 80
#define TILE_A (128 * ROWB)      // 10240
#define TILE_B (256 * ROWB)      // 20480
#define ST_AHI 0
#define ST_ALO TILE_A
#define ST_BH (2 * TILE_A)
#define STAGEB (2 * TILE_A + TILE_B)   // 40960
#define PIPE 4
#define OFF80(row, ch) ((uint32_t)((row) * ROWB + ((ch) << 4)))
// fused sketch regions (reuse smem after mainloop)
#define FZ_HEAD 36864            // per-head z region: hi 18432 + lo 18432
#define FZ_LO 18432
#define FG_OFF (4 * FZ_HEAD)     // 147456
#define FG_LO 18432
#define GEMM_SMEM (FG_OFF + 2 * FG_LO)   // 184320
#define SOFF144(row, ch) ((uint32_t)((row) * 144 + ((ch) << 4)))

__global__ __launch_bounds__(256, 1) void mma_gemm(
    const __half* __restrict__ Ahi, const __half* __restrict__ Alo,
    const __half* __restrict__ Bh, const float* __restrict__ bias,
    __half* __restrict__ pqh, __half* __restrict__ pkth,
    __half* __restrict__ vh, float* __restrict__ ofp32)
{
    extern __shared__ char smem[];
    const uint32_t sb = smem_to_u32(smem);

    const int tid = threadIdx.x;
    const int wid = tid >> 5, lane = tid & 31;
    const int bn = blockIdx.x, bm = blockIdx.y;
    const int warp_m = wid & 1, warp_n = wid >> 1;
    const bool useAlo = (Alo != nullptr) && (bn < 4);

    const __half* Ahi_b = Ahi + (size_t)bm * 128 * DD;
    const __half* Alo_b = useAlo ? Alo + (size_t)bm * 128 * DD : Ahi_b;
    const __half* Bh_b = Bh + (size_t)bn * 256 * DD;

    const int lrow = tid >> 2;
    const int lch = tid & 3;

    auto load_chunk = [&](int c, int s) {
        const uint32_t stg = sb + s * STAGEB;
        const int k0 = c * BKC;
#pragma unroll
        for (int sw = 0; sw < 2; sw++) {
            const int row = sw * 64 + lrow;
            const size_t go = (size_t)row * DD + k0 + lch * 8;
            const uint32_t so = OFF80(row, lch);
            CP_ASYNC16(stg + ST_AHI + so, Ahi_b + go);
            if (useAlo) CP_ASYNC16(stg + ST_ALO + so, Alo_b + go);
        }
#pragma unroll
        for (int sw = 0; sw < 4; sw++) {
            const int row = sw * 64 + lrow;
            const size_t go = (size_t)row * DD + k0 + lch * 8;
            CP_ASYNC16(stg + ST_BH + OFF80(row, lch), Bh_b + go);
        }
    };

    float acc[4][8][4];
#pragma unroll
    for (int i = 0; i < 4; i++)
#pragma unroll
        for (int j = 0; j < 8; j++)
#pragma unroll
            for (int e = 0; e < 4; e++) acc[i][j][e] = 0.f;

    const int mat = lane >> 3, mr = lane & 7;
    const int a_row_b = warp_m * 64 + (mat & 1) * 8 + mr;
    const int b_row_b = warp_n * 64 + (mat & 1) * 8 + mr;
    const int mchunk = mat >> 1;

    load_chunk(0, 0); CP_COMMIT();
    load_chunk(1, 1); CP_COMMIT();
    load_chunk(2, 2); CP_COMMIT();

    for (int c = 0; c < NKCH; c++) {
        CP_WAIT(2);
        __syncthreads();
        if (c + 3 < NKCH) load_chunk(c + 3, (c + 3) % PIPE);
        CP_COMMIT();

        const uint32_t stg = sb + (c % PIPE) * STAGEB;
#pragma unroll
        for (int kk = 0; kk < 2; kk++) {
            const int ch = kk * 2 + mchunk;
            uint32_t ahi[4][4], alo[4][4];
#pragma unroll
            for (int im = 0; im < 4; im++) {
                const int row = a_row_b + im * 16;
                ldsm4(ahi[im][0], ahi[im][1], ahi[im][2], ahi[im][3],
                      stg + ST_AHI + OFF80(row, ch));
                if (useAlo)
                    ldsm4(alo[im][0], alo[im][1], alo[im][2], alo[im][3],
                          stg + ST_ALO + OFF80(row, ch));
            }
#pragma unroll
            for (int j16 = 0; j16 < 4; j16++) {
                const int row = b_row_b + j16 * 16;
                uint32_t h0, h1, h2, h3;
                ldsm4(h0, h1, h2, h3, stg + ST_BH + OFF80(row, ch));
                uint32_t bh0[2] = {h0, h2}, bh1[2] = {h1, h3};
#pragma unroll
                for (int im = 0; im < 4; im++) {
                    mma16816(acc[im][j16 * 2], ahi[im], bh0);
                    mma16816(acc[im][j16 * 2 + 1], ahi[im], bh1);
                    if (useAlo) {
                        mma16816(acc[im][j16 * 2], alo[im], bh0);
                        mma16816(acc[im][j16 * 2 + 1], alo[im], bh1);
                    }
                }
            }
        }
    }

    const int erow = lane >> 2, ecol = (lane & 3) * 2;

    if (ofp32) {
        // ---- projection epilogue: fp32 out ----
        const int colbase = bn * 256;
#pragma unroll
        for (int im = 0; im < 4; im++) {
            const size_t row0 = (size_t)bm * 128 + warp_m * 64 + im * 16 + erow;
#pragma unroll
            for (int t = 0; t < 8; t++) {
                const int cofs = warp_n * 64 + t * 8 + ecol;
                float2 b2 = *(const float2*)&bias[colbase + cofs];
                float2 q0 = make_float2(acc[im][t][0] + b2.x, acc[im][t][1] + b2.y);
                float2 q1 = make_float2(acc[im][t][2] + b2.x, acc[im][t][3] + b2.y);
                *(float2*)&ofp32[row0 * DD + colbase + cofs] = q0;
                *(float2*)&ofp32[(row0 + 8) * DD + colbase + cofs] = q1;
            }
        }
        return;
    }

    const int sel = bn >> 1;
    if (sel == 2) {
        // ---- v epilogue: fp16 hi only ----
        const int colbase = (bn & 1) * 256;
#pragma unroll
        for (int im = 0; im < 4; im++) {
            const size_t row0 = (size_t)bm * 128 + warp_m * 64 + im * 16 + erow;
#pragma unroll
            for (int t = 0; t < 8; t++) {
                const int cofs = warp_n * 64 + t * 8 + ecol;
                float2 b2 = *(const float2*)&bias[bn * 256 + cofs];
                *(uint32_t*)(vh + row0 * DD + colbase + cofs) =
                    pack2h(acc[im][t][0] + b2.x, acc[im][t][1] + b2.y);
                *(uint32_t*)(vh + (row0 + 8) * DD + colbase + cofs) =
                    pack2h(acc[im][t][2] + b2.x, acc[im][t][3] + b2.y);
            }
        }
        return;
    }

    // ================= fused sketch epilogue (sel 0 = q, 1 = k) ==========
    CP_WAIT(0);
    __syncthreads();   // mainloop smem no longer needed

    // stage z = acc + bias as fp16 hi/lo, per head (4 heads per CTA tile)
#pragma unroll
    for (int im = 0; im < 4; im++) {
        const int row = warp_m * 64 + im * 16 + erow;
#pragma unroll
        for (int t = 0; t < 8; t++) {
            const int cofs = warp_n * 64 + t * 8 + ecol;
            const int head = cofs >> 6, c = cofs & 63;
            float2 b2 = *(const float2*)&bias[bn * 256 + cofs];
            uint32_t hp, lp;
            split2h(acc[im][t][0] + b2.x, acc[im][t][1] + b2.y, hp, lp);
            *(uint32_t*)(smem + head * FZ_HEAD + row * 144 + c * 2) = hp;
            *(uint32_t*)(smem + head * FZ_HEAD + FZ_LO + row * 144 + c * 2) = lp;
            split2h(acc[im][t][2] + b2.x, acc[im][t][3] + b2.y, hp, lp);
            *(uint32_t*)(smem + head * FZ_HEAD + (row + 8) * 144 + c * 2) = hp;
            *(uint32_t*)(smem + head * FZ_HEAD + FZ_LO + (row + 8) * 144 + c * 2) = lp;
        }
    }
    // load G-int (hi/lo) for this set
    {
        const __half* Gh = &g_gint_hi[sel][0];
        const __half* Gl = &g_gint_lo[sel][0];
#pragma unroll
        for (int it = 0; it < 4; it++) {
            const int cidx = it * 256 + tid;
            const int row = cidx >> 3, ch = cidx & 7;
            *(uint4*)(smem + FG_OFF + SOFF144(row, ch)) =
                *(const uint4*)((const char*)Gh + row * 128 + ch * 16);
            *(uint4*)(smem + FG_OFF + FG_LO + SOFF144(row, ch)) =
                *(const uint4*)((const char*)Gl + row * 128 + ch * 16);
        }
    }
    __syncthreads();

    // sketch warp mapping
    const int swm = wid & 1, swn = wid >> 1;
    const int a_row_s = swm * 64 + (mat & 1) * 8 + mr;
    const int b_row_s = swn * 32 + (mat & 1) * 8 + mr;
    const int b = bm >> 6;
    const int sbase = (bm & 63) * 128;
    const int g = lane >> 2, t4 = lane & 3;
    const float inv = 0.125f;

    for (int hd = 0; hd < 4; hd++) {
        const uint32_t zb = sb + hd * FZ_HEAD;

        float sk[4][4][4];
#pragma unroll
        for (int i = 0; i < 4; i++)
#pragma unroll
            for (int j = 0; j < 4; j++)
#pragma unroll
                for (int e = 0; e < 4; e++) sk[i][j][e] = 0.f;

#pragma unroll
        for (int kk = 0; kk < 4; kk++) {
            const int ch = kk * 2 + mchunk;
            uint32_t zhi[4][4], zlo[4][4];
#pragma unroll
            for (int im = 0; im < 4; im++) {
                const int row = a_row_s + im * 16;
                ldsm4(zhi[im][0], zhi[im][1], zhi[im][2], zhi[im][3],
                      zb + SOFF144(row, ch));
                ldsm4(zlo[im][0], zlo[im][1], zlo[im][2], zlo[im][3],
                      zb + FZ_LO + SOFF144(row, ch));
            }
#pragma unroll
            for (int j16 = 0; j16 < 2; j16++) {
                const int row = b_row_s + j16 * 16;
                uint32_t h0, h1, h2, h3, l0, l1, l2, l3;
                ldsm4(h0, h1, h2, h3, sb + FG_OFF + SOFF144(row, ch));
                ldsm4(l0, l1, l2, l3, sb + FG_OFF + FG_LO + SOFF144(row, ch));
                uint32_t gh0[2] = {h0, h2}, gh1[2] = {h1, h3};
                uint32_t gl0[2] = {l0, l2}, gl1[2] = {l1, l3};
#pragma unroll
                for (int im = 0; im < 4; im++) {
                    mma16816(sk[im][j16 * 2], zhi[im], gh0);
                    mma16816(sk[im][j16 * 2], zhi[im], gl0);
                    mma16816(sk[im][j16 * 2], zlo[im], gh0);
                    mma16816(sk[im][j16 * 2 + 1], zhi[im], gh1);
                    mma16816(sk[im][j16 * 2 + 1], zhi[im], gl1);
                    mma16816(sk[im][j16 * 2 + 1], zlo[im], gh1);
                }
            }
        }

        const int h = (bn & 1) * 4 + hd;
        const int bh2 = b * HH + h;
        __syncthreads();   // all warps done reading z[hd]; reuse for staging

        __half* SH = (__half*)(smem + hd * FZ_HEAD);
        if (sel == 0) {
            // stage phiq hi [128][72]
#pragma unroll
            for (int im = 0; im < 4; im++) {
                const int s0 = swm * 64 + im * 16 + g;
#pragma unroll
                for (int jn = 0; jn < 4; jn++) {
                    const int r = swn * 16 + jn * 4 + t4;
                    float h0 = inv * sk[im][jn][0] * sk[im][jn][1];
                    float h1 = inv * sk[im][jn][2] * sk[im][jn][3];
                    SH[s0 * 72 + r] = __float2half_rn(h0 * h0);
                    SH[(s0 + 8) * 72 + r] = __float2half_rn(h1 * h1);
                }
            }
            __syncthreads();
            const int row = tid >> 1, hf = tid & 1;
            size_t gbase = ((size_t)bh2 * SS + sbase + row) * RR + hf * 32;
            const uint4* srcH = (const uint4*)(smem + hd * FZ_HEAD + row * 144 + hf * 64);
#pragma unroll
            for (int i = 0; i < 4; i++) ((uint4*)(pqh + gbase))[i] = srcH[i];
        } else {
            // stage phikT hi [64 r][136 s]
#pragma unroll
            for (int im = 0; im < 4; im++) {
                const int s0 = swm * 64 + im * 16 + g;
#pragma unroll
                for (int jn = 0; jn < 4; jn++) {
                    const int r = swn * 16 + jn * 4 + t4;
                    float h0 = inv * sk[im][jn][0] * sk[im][jn][1];
                    float h1 = inv * sk[im][jn][2] * sk[im][jn][3];
                    SH[r * 136 + s0] = __float2half_rn(h0 * h0);
                    SH[r * 136 + s0 + 8] = __float2half_rn(h1 * h1);
                }
            }
            __syncthreads();
            const int r = tid >> 2, q4 = tid & 3;
            size_t gbase = ((size_t)bh2 * RR + r) * SS + sbase + q4 * 32;
            const uint4* srcH = (const uint4*)(smem + hd * FZ_HEAD + r * 272 + q4 * 64);
#pragma unroll
            for (int i = 0; i < 4; i++) ((uint4*)(pkth + gbase))[i] = srcH[i];
        }
    }
}

// ============================================================
// TC kvsum (1-pass: v hi x phik hi): kvT[d][r] = sum_s v[s,d]*phik[s,r]
// ============================================================
__global__ __launch_bounds__(256) void kvsum_tc(
    const __half* __restrict__ pkth, const __half* __restrict__ vh,
    float* __restrict__ kvtp, float* __restrict__ ksp)
{
    __shared__ __align__(16) char sm[2 * 64 * 144];   // 18432
    const uint32_t sb = smem_to_u32(sm);
    const uint32_t VHI = 0, PKH = 9216;

    const int tid = threadIdx.x;
    const int wid = tid >> 5, lane = tid & 31;
    const int chunk = blockIdx.x, bh = blockIdx.y;
    const int b = bh >> 3, h = bh & 7;
    const int warp_m = wid & 1, warp_n = wid >> 1;
    const int mat = lane >> 3, mr = lane & 7;
    const int g = lane >> 2, t = lane & 3;

    float acc[2][2][4];
#pragma unroll
    for (int i = 0; i < 2; i++)
#pragma unroll
        for (int j = 0; j < 2; j++)
#pragma unroll
            for (int e = 0; e < 4; e++) acc[i][j][e] = 0.f;
    float kacc = 0.f;

    const int lr = tid >> 2, lq = tid & 3;
    const int kr = tid & 63, kg = tid >> 6;

    for (int step = 0; step < 8; step++) {
        const int s0 = chunk * 512 + step * 64;
        {
            const size_t vo = (size_t)(b * SS + s0 + lr) * DD + h * HDIM + lq * 16;
            *(uint4*)(sm + VHI + lr * 144 + lq * 32) = *(const uint4*)(vh + vo);
            *(uint4*)(sm + VHI + lr * 144 + lq * 32 + 16) = *(const uint4*)(vh + vo + 8);
            const size_t po = ((size_t)bh * RR + lr) * SS + s0 + lq * 16;
            *(uint4*)(sm + PKH + lr * 144 + lq * 32) = *(const uint4*)(pkth + po);
            *(uint4*)(sm + PKH + lr * 144 + lq * 32 + 16) = *(const uint4*)(pkth + po + 8);
        }
        __syncthreads();

#pragma unroll
        for (int c = 0; c < 16; c++) {
            int sc = kg * 16 + c;
            kacc += __half2float(*(__half*)(sm + PKH + kr * 144 + sc * 2));
        }

#pragma unroll
        for (int kk = 0; kk < 4; kk++) {
            uint32_t ah[2][4];
#pragma unroll
            for (int im = 0; im < 2; im++) {
                const int d0 = warp_m * 32 + im * 16 + (mat & 1) * 8;
                const int srow = kk * 16 + ((mat >> 1) & 1) * 8 + mr;
                ldsm4t(ah[im][0], ah[im][1], ah[im][2], ah[im][3],
                       sb + VHI + srow * 144 + d0 * 2);
            }
            const int rrow = warp_n * 16 + (mat & 1) * 8 + mr;
            const int chb = kk * 2 + (mat >> 1);
            uint32_t h0, h1, h2, h3;
            ldsm4(h0, h1, h2, h3, sb + PKH + rrow * 144 + chb * 16);
            uint32_t bh0[2] = {h0, h2}, bh1[2] = {h1, h3};
#pragma unroll
            for (int im = 0; im < 2; im++) {
                mma16816(acc[im][0], ah[im], bh0);
                mma16816(acc[im][1], ah[im], bh1);
            }
        }
        __syncthreads();
    }

    float* outp = kvtp + ((size_t)bh * NCHUNK + chunk) * (HDIM * RR);
#pragma unroll
    for (int im = 0; im < 2; im++) {
        const int d = warp_m * 32 + im * 16 + g;
#pragma unroll
        for (int nb = 0; nb < 2; nb++) {
            const int r = warp_n * 16 + nb * 8 + t * 2;
            *(float2*)&outp[d * RR + r] =
                make_float2(acc[im][nb][0], acc[im][nb][1]);
            *(float2*)&outp[(d + 8) * RR + r] =
                make_float2(acc[im][nb][2], acc[im][nb][3]);
        }
    }
    __syncthreads();
    float* red = (float*)sm;
    red[kg * 64 + kr] = kacc;
    __syncthreads();
    if (tid < 64)
        ksp[((size_t)bh * NCHUNK + chunk) * RR + tid] =
            red[tid] + red[64 + tid] + red[128 + tid] + red[192 + tid];
}

__global__ void reduce2(const float* __restrict__ kvtp,
                        const float* __restrict__ ksp,
                        __half* __restrict__ kvth, float* __restrict__ ks)
{
    const int idx = blockIdx.x * 256 + threadIdx.x;
    const int total = BH * HDIM * RR;
    if (idx < total) {
        int bh = idx >> 12, e = idx & 4095;
        float s = 0.f;
#pragma unroll
        for (int c = 0; c < NCHUNK; c++)
            s += kvtp[((size_t)bh * NCHUNK + c) * 4096 + e];
        kvth[idx] = __float2half_rn(s);
    } else if (idx < total + BH * RR) {
        int j = idx - total;
        int bh = j >> 6, r = j & 63;
        float s = 0.f;
#pragma unroll
        for (int c = 0; c < NCHUNK; c++)
            s += ksp[((size_t)bh * NCHUNK + c) * RR + r];
        ks[j] = s;
    }
}

// ============================================================
// TC attn (1-pass: phiq hi x kv hi): out = (phiq @ kvT) / den, fp16 out
// ============================================================
#define AT_PQH 0
#define AT_KVH (128 * 144)
#define AT_KS  (AT_KVH + 64 * 144)
#define AT_DEN (AT_KS + 256)
#define AT_SMEM (AT_DEN + 512 + 256)

__global__ __launch_bounds__(256) void attn_tc(
    const __half* __restrict__ pqh, const __half* __restrict__ kvth,
    const float* __restrict__ ks,
    __half* __restrict__ ahi)
{
    extern __shared__ char sm[];
    const uint32_t sb = smem_to_u32(sm);
    const int tid = threadIdx.x;
    const int wid = tid >> 5, lane = tid & 31;
    const int stile = blockIdx.x, bh = blockIdx.y;
    const int b = bh >> 3, h = bh & 7;
    const int sbase = stile * 128;
    const int warp_m = wid >> 1, warp_n = wid & 1;

    {
        const int row = tid >> 1, half = tid & 1;
        size_t gbase = ((size_t)bh * SS + sbase + row) * RR + half * 32;
        uint4* dstH = (uint4*)(sm + AT_PQH + row * 144 + half * 64);
#pragma unroll
        for (int i = 0; i < 4; i++) dstH[i] = ((const uint4*)(pqh + gbase))[i];
    }
    {
        const int row = tid >> 2, q4 = tid & 3;
        size_t gbase = (size_t)bh * (HDIM * RR) + row * RR + q4 * 16;
        *(uint4*)(sm + AT_KVH + row * 144 + q4 * 32) = *(const uint4*)(kvth + gbase);
        *(uint4*)(sm + AT_KVH + row * 144 + q4 * 32 + 16) = *(const uint4*)(kvth + gbase + 8);
    }
    if (tid < 64) ((float*)(sm + AT_KS))[tid] = ks[bh * RR + tid];
    __syncthreads();

    if (tid < 128) {
        float d = 1e-6f;
        const float* kss = (const float*)(sm + AT_KS);
#pragma unroll 16
        for (int r = 0; r < 64; r++) {
            float p = __half2float(*(__half*)(sm + AT_PQH + tid * 144 + r * 2));
            d += p * kss[r];
        }
        ((float*)(sm + AT_DEN))[tid] = 1.0f / d;
    }
    __syncthreads();

    float acc[2][4][4];
#pragma unroll
    for (int i = 0; i < 2; i++)
#pragma unroll
        for (int j = 0; j < 4; j++)
#pragma unroll
            for (int e = 0; e < 4; e++) acc[i][j][e] = 0.f;

    const int mat = lane >> 3, mr = lane & 7;
    const int a_row_b = warp_m * 32 + (mat & 1) * 8 + mr;
    const int b_row_b = warp_n * 32 + (mat & 1) * 8 + mr;
    const int mchunk = mat >> 1;

#pragma unroll
    for (int kk = 0; kk < 4; kk++) {
        const int ch = kk * 2 + mchunk;
        uint32_t ah[2][4];
#pragma unroll
        for (int im = 0; im < 2; im++) {
            const int row = a_row_b + im * 16;
            ldsm4(ah[im][0], ah[im][1], ah[im][2], ah[im][3],
                  sb + AT_PQH + row * 144 + ch * 16);
        }
#pragma unroll
        for (int nt = 0; nt < 2; nt++) {
            const int row = b_row_b + nt * 16;
            uint32_t h0, h1, h2, h3;
            ldsm4(h0, h1, h2, h3, sb + AT_KVH + row * 144 + ch * 16);
            uint32_t bh0[2] = {h0, h2}, bh1[2] = {h1, h3};
#pragma unroll
            for (int im = 0; im < 2; im++) {
                mma16816(acc[im][nt * 2], ah[im], bh0);
                mma16816(acc[im][nt * 2 + 1], ah[im], bh1);
            }
        }
    }

    const int g = lane >> 2, t = lane & 3;
    const float* rden = (const float*)(sm + AT_DEN);
#pragma unroll
    for (int im = 0; im < 2; im++) {
        const int s0 = warp_m * 32 + im * 16 + g;
        const float rd0 = rden[s0], rd1 = rden[s0 + 8];
        const size_t row0 = ((size_t)b * SS + sbase + s0) * DD + h * HDIM;
        const size_t row1 = row0 + 8 * DD;
#pragma unroll
        for (int j8 = 0; j8 < 4; j8++) {
            const int d = warp_n * 32 + j8 * 8 + t * 2;
            *(uint32_t*)(ahi + row0 + d) =
                pack2h(acc[im][j8][0] * rd0, acc[im][j8][1] * rd0);
            *(uint32_t*)(ahi + row1 + d) =
                pack2h(acc[im][j8][2] * rd1, acc[im][j8][3] * rd1);
        }
    }
}

// ============================================================
// launch
// ============================================================
extern "C" void kernel_launch(void* const* d_in, const int* in_sizes, int n_in,
                              void* d_out, int out_size)
{
    const float* x       = (const float*)d_in[0];
    const float* Wq      = (const float*)d_in[1];
    const float* bq      = (const float*)d_in[2];
    const float* Wk      = (const float*)d_in[3];
    const float* bk      = (const float*)d_in[4];
    const float* Wv      = (const float*)d_in[5];
    const float* bv      = (const float*)d_in[6];
    const float* Wp      = (const float*)d_in[7];
    const float* bp      = (const float*)d_in[8];
    const float* gamma_q = (const float*)d_in[9];
    const float* beta_q  = (const float*)d_in[10];
    const float* gamma_k = (const float*)d_in[11];
    const float* beta_k  = (const float*)d_in[12];
    const float* qG1     = (const float*)d_in[13];
    const float* qG2     = (const float*)d_in[14];
    const float* kG1     = (const float*)d_in[15];
    const float* kG2     = (const float*)d_in[16];
    float* out = (float*)d_out;

    float *p_bqkv, *p_kvtp, *p_ksp, *p_ks;
    __half *p_xhi, *p_xlo, *p_vh, *p_ahi, *p_wth;
    __half *p_pqh, *p_pkth, *p_kvth;
    cudaGetSymbolAddress((void**)&p_xhi, g_xhi);
    cudaGetSymbolAddress((void**)&p_xlo, g_xlo);
    cudaGetSymbolAddress((void**)&p_vh, g_vh);
    cudaGetSymbolAddress((void**)&p_ahi, g_ahi);
    cudaGetSymbolAddress((void**)&p_wth, g_wth);
    cudaGetSymbolAddress((void**)&p_bqkv, g_biasqkv);
    cudaGetSymbolAddress((void**)&p_pqh, g_pqh);
    cudaGetSymbolAddress((void**)&p_pkth, g_pkth);
    cudaGetSymbolAddress((void**)&p_kvtp, g_kvtp);
    cudaGetSymbolAddress((void**)&p_ksp, g_ksp);
    cudaGetSymbolAddress((void**)&p_kvth, g_kvth);
    cudaGetSymbolAddress((void**)&p_ks, g_ks);

    cudaFuncSetAttribute(mma_gemm, cudaFuncAttributeMaxDynamicSharedMemorySize,
                         GEMM_SMEM);
    cudaFuncSetAttribute(attn_tc, cudaFuncAttributeMaxDynamicSharedMemorySize,
                         AT_SMEM);

    // ---- prep (4 launches; mma_gemm is launch #5) ----
    split_fp32<<<BSROWS * DD / 4 / 256, 256>>>(x, p_xhi, p_xlo);               // 1
    concat_bias<<<6, 256>>>(bq, bk, bv, gamma_q, beta_q, gamma_k, beta_k,
                            p_bqkv);                                           // 2
    g_prep<<<2, 256>>>(qG1, qG2, kG1, kG2);                                    // 3
    transpose_h4<<<dim3(16, 16, 4), 256>>>(Wq, Wk, Wv, Wp,
                                           gamma_q, gamma_k, p_wth);           // 4

    // ---- fused QKV GEMM + sketch (q,k 2-pass; v 1-pass) ----
    dim3 gq(6, BSROWS / 128);
    mma_gemm<<<gq, 256, GEMM_SMEM>>>(p_xhi, p_xlo, p_wth, p_bqkv,
                                     p_pqh, p_pkth, p_vh, nullptr);            // 5

    // ---- TC kvsum + reduce ----
    kvsum_tc<<<dim3(NCHUNK, BH), 256>>>(p_pkth, p_vh, p_kvtp, p_ksp);
    int red_total = BH * HDIM * RR + BH * RR;
    reduce2<<<(red_total + 255) / 256, 256>>>(p_kvtp, p_ksp, p_kvth, p_ks);

    // ---- TC attention output (fp16 out) ----
    attn_tc<<<dim3(SS / 128, BH), 256, AT_SMEM>>>(p_pqh, p_kvth, p_ks, p_ahi);

    // ---- output projection (1-pass fp16, fp32 out) ----
    dim3 go(2, BSROWS / 128);
    mma_gemm<<<go, 256, GEMM_SMEM>>>(p_ahi, nullptr, p_wth + 1536 * DD, bp,
                                     nullptr, nullptr, nullptr, out);
}

// round 13
// speedup vs baseline: 1.9773x; 1.0036x over previous
#include <cuda_runtime.h>
#include <cuda_fp16.h>
#include <cstdint>

// Problem constants
#define BB 4
#define SS 8192
#define DD 512
#define HH 8
#define HDIM 64
#define RR 64
#define BSROWS (BB * SS)      // 32768
#define BH (BB * HH)          // 32
#define NCHUNK 16

// -------- scratch (static device globals; no allocation) --------
__device__ __half g_xhi[BSROWS * DD];
__device__ __half g_xlo[BSROWS * DD];
__device__ __half g_vh[BSROWS * DD];
__device__ __half g_ahi[BSROWS * DD];
__device__ __half g_wth[4 * DD * DD];     // fp16 transposed weights
__device__ float g_biasqkv[3 * DD];
__device__ __half g_gint_hi[2][128 * 64];
__device__ __half g_gint_lo[2][128 * 64];
__device__ __half g_pqh[BH * SS * RR];    // phiq [bh][s][r], fp16 hi only
__device__ __half g_pkth[BH * RR * SS];   // phikT [bh][r][s], fp16 hi only
__device__ float g_kvtp[BH * NCHUNK * HDIM * RR];
__device__ float g_ksp[BH * NCHUNK * RR];
__device__ __half g_kvth[BH * HDIM * RR];
__device__ float g_ks[BH * RR];

// ============================================================
// helpers
// ============================================================
__device__ __forceinline__ uint32_t smem_to_u32(const void* p) {
    uint32_t a;
    asm("{ .reg .u64 t; cvta.to.shared.u64 t, %1; cvt.u32.u64 %0, t; }"
        : "=r"(a) : "l"(p));
    return a;
}
__device__ __forceinline__ void ldsm4(uint32_t& r0, uint32_t& r1,
                                      uint32_t& r2, uint32_t& r3,
                                      uint32_t addr) {
    asm volatile("ldmatrix.sync.aligned.m8n8.x4.shared.b16 {%0,%1,%2,%3}, [%4];"
                 : "=r"(r0), "=r"(r1), "=r"(r2), "=r"(r3) : "r"(addr));
}
__device__ __forceinline__ void ldsm4t(uint32_t& r0, uint32_t& r1,
                                       uint32_t& r2, uint32_t& r3,
                                       uint32_t addr) {
    asm volatile("ldmatrix.sync.aligned.m8n8.x4.trans.shared.b16 {%0,%1,%2,%3}, [%4];"
                 : "=r"(r0), "=r"(r1), "=r"(r2), "=r"(r3) : "r"(addr));
}
__device__ __forceinline__ void mma16816(float* d, const uint32_t* a,
                                         const uint32_t* b) {
    asm volatile(
        "mma.sync.aligned.m16n8k16.row.col.f32.f16.f16.f32 "
        "{%0,%1,%2,%3}, {%4,%5,%6,%7}, {%8,%9}, {%0,%1,%2,%3};"
        : "+f"(d[0]), "+f"(d[1]), "+f"(d[2]), "+f"(d[3])
        : "r"(a[0]), "r"(a[1]), "r"(a[2]), "r"(a[3]), "r"(b[0]), "r"(b[1]));
}
#define CP_ASYNC16(dst, src) \
    asm volatile("cp.async.cg.shared.global [%0], [%1], 16;" :: "r"(dst), "l"(src))
#define CP_COMMIT() asm volatile("cp.async.commit_group;" ::: "memory")
#define CP_WAIT(n)  asm volatile("cp.async.wait_group %0;" :: "n"(n) : "memory")

__device__ __forceinline__ void split4h(float4 v, uint2& hi, uint2& lo) {
    __half h0 = __float2half_rn(v.x), h1 = __float2half_rn(v.y);
    __half h2 = __float2half_rn(v.z), h3 = __float2half_rn(v.w);
    float r0 = v.x - __half2float(h0), r1 = v.y - __half2float(h1);
    float r2 = v.z - __half2float(h2), r3 = v.w - __half2float(h3);
    __half l0 = __float2half_rn(r0), l1 = __float2half_rn(r1);
    __half l2 = __float2half_rn(r2), l3 = __float2half_rn(r3);
    hi.x = ((uint32_t)__half_as_ushort(h1) << 16) | __half_as_ushort(h0);
    hi.y = ((uint32_t)__half_as_ushort(h3) << 16) | __half_as_ushort(h2);
    lo.x = ((uint32_t)__half_as_ushort(l1) << 16) | __half_as_ushort(l0);
    lo.y = ((uint32_t)__half_as_ushort(l3) << 16) | __half_as_ushort(l2);
}
__device__ __forceinline__ void split2h(float a, float b, uint32_t& hp, uint32_t& lp) {
    __half h0 = __float2half_rn(a), h1 = __float2half_rn(b);
    float l0 = a - __half2float(h0), l1 = b - __half2float(h1);
    __half e0 = __float2half_rn(l0), e1 = __float2half_rn(l1);
    hp = ((uint32_t)__half_as_ushort(h1) << 16) | __half_as_ushort(h0);
    lp = ((uint32_t)__half_as_ushort(e1) << 16) | __half_as_ushort(e0);
}
__device__ __forceinline__ uint32_t pack2h(float a, float b) {
    __half h0 = __float2half_rn(a), h1 = __float2half_rn(b);
    return ((uint32_t)__half_as_ushort(h1) << 16) | __half_as_ushort(h0);
}

// ============================================================
// prep kernels
// ============================================================
__global__ __launch_bounds__(256) void split_fp32(
    const float* __restrict__ X, __half* __restrict__ Xh,
    __half* __restrict__ Xl)
{
    int i = blockIdx.x * 256 + threadIdx.x;
    float4 v = ((const float4*)X)[i];
    uint2 hi, lo;
    split4h(v, hi, lo);
    ((uint2*)Xh)[i] = hi;
    ((uint2*)Xl)[i] = lo;
}

__global__ __launch_bounds__(256) void transpose_h4(
    const float* __restrict__ Wq, const float* __restrict__ Wk,
    const float* __restrict__ Wv, const float* __restrict__ Wp,
    const float* __restrict__ gq, const float* __restrict__ gk,
    __half* __restrict__ Th)
{
    __shared__ float t[32][33];
    const int z = blockIdx.z;
    const float* W = z == 0 ? Wq : (z == 1 ? Wk : (z == 2 ? Wv : Wp));
    const float scale = z == 0 ? gq[0] : (z == 1 ? gk[0] : 1.0f);
    const int rowoff = z * DD;
    int bx = blockIdx.x * 32, by = blockIdx.y * 32;
    int x = threadIdx.x & 31, y = threadIdx.x >> 5;
    for (int i = y; i < 32; i += 8) t[i][x] = W[(size_t)(by + i) * DD + bx + x];
    __syncthreads();
    for (int i = y; i < 32; i += 8)
        Th[(size_t)(rowoff + bx + i) * DD + by + x] = __float2half_rn(t[x][i] * scale);
}

// g_prep (blocks 0,1) + concat_bias (blocks 2..7) in one launch
__global__ __launch_bounds__(256) void misc_prep(
    const float* __restrict__ qG1, const float* __restrict__ qG2,
    const float* __restrict__ kG1, const float* __restrict__ kG2,
    const float* bq, const float* bk, const float* bv,
    const float* gq, const float* betq,
    const float* gk, const float* betk,
    float* bout)
{
    const int blk = blockIdx.x;
    if (blk < 2) {
        const int set = blk;
        const float* G1 = set ? kG1 : qG1;
        const float* G2 = set ? kG2 : qG2;
        __half* Oh = g_gint_hi[set];
        __half* Ol = g_gint_lo[set];
        for (int it = 0; it < 32; it++) {
            int idx = it * 256 + threadIdx.x;
            int n = idx >> 6, k = idx & 63;
            float v = ((n & 1) ? G2 : G1)[k * 64 + (n >> 1)];
            __half h = __float2half_rn(v);
            Oh[idx] = h;
            Ol[idx] = __float2half_rn(v - __half2float(h));
        }
    } else {
        int i = (blk - 2) * 256 + threadIdx.x;
        if (i < DD) bout[i] = gq[0] * bq[i] + betq[0];
        else if (i < 2 * DD) bout[i] = gk[0] * bk[i - DD] + betk[0];
        else if (i < 3 * DD) bout[i] = bv[i - 2 * DD];
    }
}

// ============================================================
// fp16 split GEMM + fused sketch epilogue (unchanged from R12)
// ============================================================
#define BKC 32
#define NKCH (DD / BKC)          // 16
#define ROWB 80
#define TILE_A (128 * ROWB)      // 10240
#define TILE_B (256 * ROWB)      // 20480
#define ST_AHI 0
#define ST_ALO TILE_A
#define ST_BH (2 * TILE_A)
#define STAGEB (2 * TILE_A + TILE_B)   // 40960
#define PIPE 4
#define OFF80(row, ch) ((uint32_t)((row) * ROWB + ((ch) << 4)))
#define FZ_HEAD 36864
#define FZ_LO 18432
#define FG_OFF (4 * FZ_HEAD)
#define FG_LO 18432
#define GEMM_SMEM (FG_OFF + 2 * FG_LO)   // 184320
#define SOFF144(row, ch) ((uint32_t)((row) * 144 + ((ch) << 4)))

__global__ __launch_bounds__(256, 1) void mma_gemm(
    const __half* __restrict__ Ahi, const __half* __restrict__ Alo,
    const __half* __restrict__ Bh, const float* __restrict__ bias,
    __half* __restrict__ pqh, __half* __restrict__ pkth,
    __half* __restrict__ vh, float* __restrict__ ofp32)
{
    extern __shared__ char smem[];
    const uint32_t sb = smem_to_u32(smem);

    const int tid = threadIdx.x;
    const int wid = tid >> 5, lane = tid & 31;
    const int bn = blockIdx.x, bm = blockIdx.y;
    const int warp_m = wid & 1, warp_n = wid >> 1;
    const bool useAlo = (Alo != nullptr) && (bn < 4);

    const __half* Ahi_b = Ahi + (size_t)bm * 128 * DD;
    const __half* Alo_b = useAlo ? Alo + (size_t)bm * 128 * DD : Ahi_b;
    const __half* Bh_b = Bh + (size_t)bn * 256 * DD;

    const int lrow = tid >> 2;
    const int lch = tid & 3;

    auto load_chunk = [&](int c, int s) {
        const uint32_t stg = sb + s * STAGEB;
        const int k0 = c * BKC;
#pragma unroll
        for (int sw = 0; sw < 2; sw++) {
            const int row = sw * 64 + lrow;
            const size_t go = (size_t)row * DD + k0 + lch * 8;
            const uint32_t so = OFF80(row, lch);
            CP_ASYNC16(stg + ST_AHI + so, Ahi_b + go);
            if (useAlo) CP_ASYNC16(stg + ST_ALO + so, Alo_b + go);
        }
#pragma unroll
        for (int sw = 0; sw < 4; sw++) {
            const int row = sw * 64 + lrow;
            const size_t go = (size_t)row * DD + k0 + lch * 8;
            CP_ASYNC16(stg + ST_BH + OFF80(row, lch), Bh_b + go);
        }
    };

    float acc[4][8][4];
#pragma unroll
    for (int i = 0; i < 4; i++)
#pragma unroll
        for (int j = 0; j < 8; j++)
#pragma unroll
            for (int e = 0; e < 4; e++) acc[i][j][e] = 0.f;

    const int mat = lane >> 3, mr = lane & 7;
    const int a_row_b = warp_m * 64 + (mat & 1) * 8 + mr;
    const int b_row_b = warp_n * 64 + (mat & 1) * 8 + mr;
    const int mchunk = mat >> 1;

    load_chunk(0, 0); CP_COMMIT();
    load_chunk(1, 1); CP_COMMIT();
    load_chunk(2, 2); CP_COMMIT();

    for (int c = 0; c < NKCH; c++) {
        CP_WAIT(2);
        __syncthreads();
        if (c + 3 < NKCH) load_chunk(c + 3, (c + 3) % PIPE);
        CP_COMMIT();

        const uint32_t stg = sb + (c % PIPE) * STAGEB;
#pragma unroll
        for (int kk = 0; kk < 2; kk++) {
            const int ch = kk * 2 + mchunk;
            uint32_t ahi[4][4], alo[4][4];
#pragma unroll
            for (int im = 0; im < 4; im++) {
                const int row = a_row_b + im * 16;
                ldsm4(ahi[im][0], ahi[im][1], ahi[im][2], ahi[im][3],
                      stg + ST_AHI + OFF80(row, ch));
                if (useAlo)
                    ldsm4(alo[im][0], alo[im][1], alo[im][2], alo[im][3],
                          stg + ST_ALO + OFF80(row, ch));
            }
#pragma unroll
            for (int j16 = 0; j16 < 4; j16++) {
                const int row = b_row_b + j16 * 16;
                uint32_t h0, h1, h2, h3;
                ldsm4(h0, h1, h2, h3, stg + ST_BH + OFF80(row, ch));
                uint32_t bh0[2] = {h0, h2}, bh1[2] = {h1, h3};
#pragma unroll
                for (int im = 0; im < 4; im++) {
                    mma16816(acc[im][j16 * 2], ahi[im], bh0);
                    mma16816(acc[im][j16 * 2 + 1], ahi[im], bh1);
                    if (useAlo) {
                        mma16816(acc[im][j16 * 2], alo[im], bh0);
                        mma16816(acc[im][j16 * 2 + 1], alo[im], bh1);
                    }
                }
            }
        }
    }

    const int erow = lane >> 2, ecol = (lane & 3) * 2;

    if (ofp32) {
        const int colbase = bn * 256;
#pragma unroll
        for (int im = 0; im < 4; im++) {
            const size_t row0 = (size_t)bm * 128 + warp_m * 64 + im * 16 + erow;
#pragma unroll
            for (int t = 0; t < 8; t++) {
                const int cofs = warp_n * 64 + t * 8 + ecol;
                float2 b2 = *(const float2*)&bias[colbase + cofs];
                float2 q0 = make_float2(acc[im][t][0] + b2.x, acc[im][t][1] + b2.y);
                float2 q1 = make_float2(acc[im][t][2] + b2.x, acc[im][t][3] + b2.y);
                *(float2*)&ofp32[row0 * DD + colbase + cofs] = q0;
                *(float2*)&ofp32[(row0 + 8) * DD + colbase + cofs] = q1;
            }
        }
        return;
    }

    const int sel = bn >> 1;
    if (sel == 2) {
        const int colbase = (bn & 1) * 256;
#pragma unroll
        for (int im = 0; im < 4; im++) {
            const size_t row0 = (size_t)bm * 128 + warp_m * 64 + im * 16 + erow;
#pragma unroll
            for (int t = 0; t < 8; t++) {
                const int cofs = warp_n * 64 + t * 8 + ecol;
                float2 b2 = *(const float2*)&bias[bn * 256 + cofs];
                *(uint32_t*)(vh + row0 * DD + colbase + cofs) =
                    pack2h(acc[im][t][0] + b2.x, acc[im][t][1] + b2.y);
                *(uint32_t*)(vh + (row0 + 8) * DD + colbase + cofs) =
                    pack2h(acc[im][t][2] + b2.x, acc[im][t][3] + b2.y);
            }
        }
        return;
    }

    // ---- fused sketch epilogue (sel 0 = q, 1 = k) ----
    CP_WAIT(0);
    __syncthreads();

#pragma unroll
    for (int im = 0; im < 4; im++) {
        const int row = warp_m * 64 + im * 16 + erow;
#pragma unroll
        for (int t = 0; t < 8; t++) {
            const int cofs = warp_n * 64 + t * 8 + ecol;
            const int head = cofs >> 6, c = cofs & 63;
            float2 b2 = *(const float2*)&bias[bn * 256 + cofs];
            uint32_t hp, lp;
            split2h(acc[im][t][0] + b2.x, acc[im][t][1] + b2.y, hp, lp);
            *(uint32_t*)(smem + head * FZ_HEAD + row * 144 + c * 2) = hp;
            *(uint32_t*)(smem + head * FZ_HEAD + FZ_LO + row * 144 + c * 2) = lp;
            split2h(acc[im][t][2] + b2.x, acc[im][t][3] + b2.y, hp, lp);
            *(uint32_t*)(smem + head * FZ_HEAD + (row + 8) * 144 + c * 2) = hp;
            *(uint32_t*)(smem + head * FZ_HEAD + FZ_LO + (row + 8) * 144 + c * 2) = lp;
        }
    }
    {
        const __half* Gh = &g_gint_hi[sel][0];
        const __half* Gl = &g_gint_lo[sel][0];
#pragma unroll
        for (int it = 0; it < 4; it++) {
            const int cidx = it * 256 + tid;
            const int row = cidx >> 3, ch = cidx & 7;
            *(uint4*)(smem + FG_OFF + SOFF144(row, ch)) =
                *(const uint4*)((const char*)Gh + row * 128 + ch * 16);
            *(uint4*)(smem + FG_OFF + FG_LO + SOFF144(row, ch)) =
                *(const uint4*)((const char*)Gl + row * 128 + ch * 16);
        }
    }
    __syncthreads();

    const int swm = wid & 1, swn = wid >> 1;
    const int a_row_s = swm * 64 + (mat & 1) * 8 + mr;
    const int b_row_s = swn * 32 + (mat & 1) * 8 + mr;
    const int b = bm >> 6;
    const int sbase = (bm & 63) * 128;
    const int g = lane >> 2, t4 = lane & 3;
    const float inv = 0.125f;

    for (int hd = 0; hd < 4; hd++) {
        const uint32_t zb = sb + hd * FZ_HEAD;

        float sk[4][4][4];
#pragma unroll
        for (int i = 0; i < 4; i++)
#pragma unroll
            for (int j = 0; j < 4; j++)
#pragma unroll
                for (int e = 0; e < 4; e++) sk[i][j][e] = 0.f;

#pragma unroll
        for (int kk = 0; kk < 4; kk++) {
            const int ch = kk * 2 + mchunk;
            uint32_t zhi[4][4], zlo[4][4];
#pragma unroll
            for (int im = 0; im < 4; im++) {
                const int row = a_row_s + im * 16;
                ldsm4(zhi[im][0], zhi[im][1], zhi[im][2], zhi[im][3],
                      zb + SOFF144(row, ch));
                ldsm4(zlo[im][0], zlo[im][1], zlo[im][2], zlo[im][3],
                      zb + FZ_LO + SOFF144(row, ch));
            }
#pragma unroll
            for (int j16 = 0; j16 < 2; j16++) {
                const int row = b_row_s + j16 * 16;
                uint32_t h0, h1, h2, h3, l0, l1, l2, l3;
                ldsm4(h0, h1, h2, h3, sb + FG_OFF + SOFF144(row, ch));
                ldsm4(l0, l1, l2, l3, sb + FG_OFF + FG_LO + SOFF144(row, ch));
                uint32_t gh0[2] = {h0, h2}, gh1[2] = {h1, h3};
                uint32_t gl0[2] = {l0, l2}, gl1[2] = {l1, l3};
#pragma unroll
                for (int im = 0; im < 4; im++) {
                    mma16816(sk[im][j16 * 2], zhi[im], gh0);
                    mma16816(sk[im][j16 * 2], zhi[im], gl0);
                    mma16816(sk[im][j16 * 2], zlo[im], gh0);
                    mma16816(sk[im][j16 * 2 + 1], zhi[im], gh1);
                    mma16816(sk[im][j16 * 2 + 1], zhi[im], gl1);
                    mma16816(sk[im][j16 * 2 + 1], zlo[im], gh1);
                }
            }
        }

        const int h = (bn & 1) * 4 + hd;
        const int bh2 = b * HH + h;
        __syncthreads();

        __half* SH = (__half*)(smem + hd * FZ_HEAD);
        if (sel == 0) {
#pragma unroll
            for (int im = 0; im < 4; im++) {
                const int s0 = swm * 64 + im * 16 + g;
#pragma unroll
                for (int jn = 0; jn < 4; jn++) {
                    const int r = swn * 16 + jn * 4 + t4;
                    float h0 = inv * sk[im][jn][0] * sk[im][jn][1];
                    float h1 = inv * sk[im][jn][2] * sk[im][jn][3];
                    SH[s0 * 72 + r] = __float2half_rn(h0 * h0);
                    SH[(s0 + 8) * 72 + r] = __float2half_rn(h1 * h1);
                }
            }
            __syncthreads();
            const int row = tid >> 1, hf = tid & 1;
            size_t gbase = ((size_t)bh2 * SS + sbase + row) * RR + hf * 32;
            const uint4* srcH = (const uint4*)(smem + hd * FZ_HEAD + row * 144 + hf * 64);
#pragma unroll
            for (int i = 0; i < 4; i++) ((uint4*)(pqh + gbase))[i] = srcH[i];
        } else {
#pragma unroll
            for (int im = 0; im < 4; im++) {
                const int s0 = swm * 64 + im * 16 + g;
#pragma unroll
                for (int jn = 0; jn < 4; jn++) {
                    const int r = swn * 16 + jn * 4 + t4;
                    float h0 = inv * sk[im][jn][0] * sk[im][jn][1];
                    float h1 = inv * sk[im][jn][2] * sk[im][jn][3];
                    SH[r * 136 + s0] = __float2half_rn(h0 * h0);
                    SH[r * 136 + s0 + 8] = __float2half_rn(h1 * h1);
                }
            }
            __syncthreads();
            const int r = tid >> 2, q4 = tid & 3;
            size_t gbase = ((size_t)bh2 * RR + r) * SS + sbase + q4 * 32;
            const uint4* srcH = (const uint4*)(smem + hd * FZ_HEAD + r * 272 + q4 * 64);
#pragma unroll
            for (int i = 0; i < 4; i++) ((uint4*)(pkth + gbase))[i] = srcH[i];
        }
    }
}

// ============================================================
// TC kvsum (1-pass, cp.async double-buffered steps)
// ============================================================
#define KV_STG 18432
#define KV_VHI 0
#define KV_PKH 9216

__global__ __launch_bounds__(256) void kvsum_tc(
    const __half* __restrict__ pkth, const __half* __restrict__ vh,
    float* __restrict__ kvtp, float* __restrict__ ksp)
{
    __shared__ __align__(16) char sm[2 * KV_STG];   // 36864
    const uint32_t sb = smem_to_u32(sm);

    const int tid = threadIdx.x;
    const int wid = tid >> 5, lane = tid & 31;
    const int chunk = blockIdx.x, bh = blockIdx.y;
    const int b = bh >> 3, h = bh & 7;
    const int warp_m = wid & 1, warp_n = wid >> 1;
    const int mat = lane >> 3, mr = lane & 7;
    const int g = lane >> 2, t = lane & 3;

    float acc[2][2][4];
#pragma unroll
    for (int i = 0; i < 2; i++)
#pragma unroll
        for (int j = 0; j < 2; j++)
#pragma unroll
            for (int e = 0; e < 4; e++) acc[i][j][e] = 0.f;
    float kacc = 0.f;

    const int lr = tid >> 2, lq = tid & 3;
    const int kr = tid & 63, kg = tid >> 6;

    auto load_step = [&](int step, int s) {
        const uint32_t stg = sb + s * KV_STG;
        const int s0 = chunk * 512 + step * 64;
        const size_t vo = (size_t)(b * SS + s0 + lr) * DD + h * HDIM + lq * 16;
        CP_ASYNC16(stg + KV_VHI + lr * 144 + lq * 32, vh + vo);
        CP_ASYNC16(stg + KV_VHI + lr * 144 + lq * 32 + 16, vh + vo + 8);
        const size_t po = ((size_t)bh * RR + lr) * SS + s0 + lq * 16;
        CP_ASYNC16(stg + KV_PKH + lr * 144 + lq * 32, pkth + po);
        CP_ASYNC16(stg + KV_PKH + lr * 144 + lq * 32 + 16, pkth + po + 8);
    };

    load_step(0, 0);
    CP_COMMIT();

    for (int step = 0; step < 8; step++) {
        if (step + 1 < 8) load_step(step + 1, (step + 1) & 1);
        CP_COMMIT();
        CP_WAIT(1);
        __syncthreads();

        const uint32_t stg = sb + (step & 1) * KV_STG;

#pragma unroll
        for (int c = 0; c < 16; c++) {
            int sc = kg * 16 + c;
            kacc += __half2float(*(__half*)((char*)sm + (step & 1) * KV_STG +
                                            KV_PKH + kr * 144 + sc * 2));
        }

#pragma unroll
        for (int kk = 0; kk < 4; kk++) {
            uint32_t ah[2][4];
#pragma unroll
            for (int im = 0; im < 2; im++) {
                const int d0 = warp_m * 32 + im * 16 + (mat & 1) * 8;
                const int srow = kk * 16 + ((mat >> 1) & 1) * 8 + mr;
                ldsm4t(ah[im][0], ah[im][1], ah[im][2], ah[im][3],
                       stg + KV_VHI + srow * 144 + d0 * 2);
            }
            const int rrow = warp_n * 16 + (mat & 1) * 8 + mr;
            const int chb = kk * 2 + (mat >> 1);
            uint32_t h0, h1, h2, h3;
            ldsm4(h0, h1, h2, h3, stg + KV_PKH + rrow * 144 + chb * 16);
            uint32_t bh0[2] = {h0, h2}, bh1[2] = {h1, h3};
#pragma unroll
            for (int im = 0; im < 2; im++) {
                mma16816(acc[im][0], ah[im], bh0);
                mma16816(acc[im][1], ah[im], bh1);
            }
        }
        __syncthreads();
    }

    float* outp = kvtp + ((size_t)bh * NCHUNK + chunk) * (HDIM * RR);
#pragma unroll
    for (int im = 0; im < 2; im++) {
        const int d = warp_m * 32 + im * 16 + g;
#pragma unroll
        for (int nb = 0; nb < 2; nb++) {
            const int r = warp_n * 16 + nb * 8 + t * 2;
            *(float2*)&outp[d * RR + r] =
                make_float2(acc[im][nb][0], acc[im][nb][1]);
            *(float2*)&outp[(d + 8) * RR + r] =
                make_float2(acc[im][nb][2], acc[im][nb][3]);
        }
    }
    __syncthreads();
    float* red = (float*)sm;
    red[kg * 64 + kr] = kacc;
    __syncthreads();
    if (tid < 64)
        ksp[((size_t)bh * NCHUNK + chunk) * RR + tid] =
            red[tid] + red[64 + tid] + red[128 + tid] + red[192 + tid];
}

__global__ void reduce2(const float* __restrict__ kvtp,
                        const float* __restrict__ ksp,
                        __half* __restrict__ kvth, float* __restrict__ ks)
{
    const int idx = blockIdx.x * 256 + threadIdx.x;
    const int total = BH * HDIM * RR;
    if (idx < total) {
        int bh = idx >> 12, e = idx & 4095;
        float s = 0.f;
#pragma unroll
        for (int c = 0; c < NCHUNK; c++)
            s += kvtp[((size_t)bh * NCHUNK + c) * 4096 + e];
        kvth[idx] = __float2half_rn(s);
    } else if (idx < total + BH * RR) {
        int j = idx - total;
        int bh = j >> 6, r = j & 63;
        float s = 0.f;
#pragma unroll
        for (int c = 0; c < NCHUNK; c++)
            s += ksp[((size_t)bh * NCHUNK + c) * RR + r];
        ks[j] = s;
    }
}

// ============================================================
// TC attn: 256 s-rows per CTA, one kv load, two MMA halves.
// ============================================================
#define AT_PQH 0
#define AT_KVH (256 * 144)                 // 36864
#define AT_KS  (AT_KVH + 64 * 144)         // + 9216
#define AT_DEN (AT_KS + 256)
#define AT_SMEM (AT_DEN + 1024)            // 47360

__global__ __launch_bounds__(256) void attn_tc(
    const __half* __restrict__ pqh, const __half* __restrict__ kvth,
    const float* __restrict__ ks,
    __half* __restrict__ ahi)
{
    __shared__ __align__(16) char sm[AT_SMEM];
    const uint32_t sb = smem_to_u32(sm);
    const int tid = threadIdx.x;
    const int wid = tid >> 5, lane = tid & 31;
    const int stile = blockIdx.x, bh = blockIdx.y;
    const int b = bh >> 3, h = bh & 7;
    const int sbase = stile * 256;
    const int warp_m = wid >> 1, warp_n = wid & 1;

    // load phiq [256][64] (each thread: one row, 8x16B)
    {
        const int row = tid;
        size_t gbase = ((size_t)bh * SS + sbase + row) * RR;
        uint4* dst = (uint4*)(sm + AT_PQH + row * 144);
#pragma unroll
        for (int i = 0; i < 8; i++) dst[i] = ((const uint4*)(pqh + gbase))[i];
    }
    // load kvT [64][64]
    {
        const int row = tid >> 2, q4 = tid & 3;
        size_t gbase = (size_t)bh * (HDIM * RR) + row * RR + q4 * 16;
        *(uint4*)(sm + AT_KVH + row * 144 + q4 * 32) = *(const uint4*)(kvth + gbase);
        *(uint4*)(sm + AT_KVH + row * 144 + q4 * 32 + 16) = *(const uint4*)(kvth + gbase + 8);
    }
    if (tid < 64) ((float*)(sm + AT_KS))[tid] = ks[bh * RR + tid];
    __syncthreads();

    // den reciprocal: each thread one row
    {
        float d = 1e-6f;
        const float* kss = (const float*)(sm + AT_KS);
#pragma unroll 16
        for (int r = 0; r < 64; r++) {
            float p = __half2float(*(__half*)(sm + AT_PQH + tid * 144 + r * 2));
            d += p * kss[r];
        }
        ((float*)(sm + AT_DEN))[tid] = 1.0f / d;
    }
    __syncthreads();

    const int mat = lane >> 3, mr = lane & 7;
    const int b_row_b = warp_n * 32 + (mat & 1) * 8 + mr;
    const int mchunk = mat >> 1;
    const int g = lane >> 2, t = lane & 3;
    const float* rden = (const float*)(sm + AT_DEN);

#pragma unroll
    for (int half = 0; half < 2; half++) {
        const int hbase = half * 128;
        const int a_row_b = hbase + warp_m * 32 + (mat & 1) * 8 + mr;

        float acc[2][4][4];
#pragma unroll
        for (int i = 0; i < 2; i++)
#pragma unroll
            for (int j = 0; j < 4; j++)
#pragma unroll
                for (int e = 0; e < 4; e++) acc[i][j][e] = 0.f;

#pragma unroll
        for (int kk = 0; kk < 4; kk++) {
            const int ch = kk * 2 + mchunk;
            uint32_t ah[2][4];
#pragma unroll
            for (int im = 0; im < 2; im++) {
                const int row = a_row_b + im * 16;
                ldsm4(ah[im][0], ah[im][1], ah[im][2], ah[im][3],
                      sb + AT_PQH + row * 144 + ch * 16);
            }
#pragma unroll
            for (int nt = 0; nt < 2; nt++) {
                const int row = b_row_b + nt * 16;
                uint32_t h0, h1, h2, h3;
                ldsm4(h0, h1, h2, h3, sb + AT_KVH + row * 144 + ch * 16);
                uint32_t bh0[2] = {h0, h2}, bh1[2] = {h1, h3};
#pragma unroll
                for (int im = 0; im < 2; im++) {
                    mma16816(acc[im][nt * 2], ah[im], bh0);
                    mma16816(acc[im][nt * 2 + 1], ah[im], bh1);
                }
            }
        }

#pragma unroll
        for (int im = 0; im < 2; im++) {
            const int s0 = hbase + warp_m * 32 + im * 16 + g;
            const float rd0 = rden[s0], rd1 = rden[s0 + 8];
            const size_t row0 = ((size_t)b * SS + sbase + s0) * DD + h * HDIM;
            const size_t row1 = row0 + 8 * DD;
#pragma unroll
            for (int j8 = 0; j8 < 4; j8++) {
                const int d = warp_n * 32 + j8 * 8 + t * 2;
                *(uint32_t*)(ahi + row0 + d) =
                    pack2h(acc[im][j8][0] * rd0, acc[im][j8][1] * rd0);
                *(uint32_t*)(ahi + row1 + d) =
                    pack2h(acc[im][j8][2] * rd1, acc[im][j8][3] * rd1);
            }
        }
    }
}

// ============================================================
// launch
// ============================================================
extern "C" void kernel_launch(void* const* d_in, const int* in_sizes, int n_in,
                              void* d_out, int out_size)
{
    const float* x       = (const float*)d_in[0];
    const float* Wq      = (const float*)d_in[1];
    const float* bq      = (const float*)d_in[2];
    const float* Wk      = (const float*)d_in[3];
    const float* bk      = (const float*)d_in[4];
    const float* Wv      = (const float*)d_in[5];
    const float* bv      = (const float*)d_in[6];
    const float* Wp      = (const float*)d_in[7];
    const float* bp      = (const float*)d_in[8];
    const float* gamma_q = (const float*)d_in[9];
    const float* beta_q  = (const float*)d_in[10];
    const float* gamma_k = (const float*)d_in[11];
    const float* beta_k  = (const float*)d_in[12];
    const float* qG1     = (const float*)d_in[13];
    const float* qG2     = (const float*)d_in[14];
    const float* kG1     = (const float*)d_in[15];
    const float* kG2     = (const float*)d_in[16];
    float* out = (float*)d_out;

    float *p_bqkv, *p_kvtp, *p_ksp, *p_ks;
    __half *p_xhi, *p_xlo, *p_vh, *p_ahi, *p_wth;
    __half *p_pqh, *p_pkth, *p_kvth;
    cudaGetSymbolAddress((void**)&p_xhi, g_xhi);
    cudaGetSymbolAddress((void**)&p_xlo, g_xlo);
    cudaGetSymbolAddress((void**)&p_vh, g_vh);
    cudaGetSymbolAddress((void**)&p_ahi, g_ahi);
    cudaGetSymbolAddress((void**)&p_wth, g_wth);
    cudaGetSymbolAddress((void**)&p_bqkv, g_biasqkv);
    cudaGetSymbolAddress((void**)&p_pqh, g_pqh);
    cudaGetSymbolAddress((void**)&p_pkth, g_pkth);
    cudaGetSymbolAddress((void**)&p_kvtp, g_kvtp);
    cudaGetSymbolAddress((void**)&p_ksp, g_ksp);
    cudaGetSymbolAddress((void**)&p_kvth, g_kvth);
    cudaGetSymbolAddress((void**)&p_ks, g_ks);

    cudaFuncSetAttribute(mma_gemm, cudaFuncAttributeMaxDynamicSharedMemorySize,
                         GEMM_SMEM);

    // ---- prep (3 launches) ----
    split_fp32<<<BSROWS * DD / 4 / 256, 256>>>(x, p_xhi, p_xlo);               // 1
    misc_prep<<<8, 256>>>(qG1, qG2, kG1, kG2, bq, bk, bv,
                          gamma_q, beta_q, gamma_k, beta_k, p_bqkv);           // 2
    transpose_h4<<<dim3(16, 16, 4), 256>>>(Wq, Wk, Wv, Wp,
                                           gamma_q, gamma_k, p_wth);           // 3

    // ---- fused QKV GEMM + sketch (q,k 2-pass; v 1-pass) ----
    dim3 gq(6, BSROWS / 128);
    mma_gemm<<<gq, 256, GEMM_SMEM>>>(p_xhi, p_xlo, p_wth, p_bqkv,
                                     p_pqh, p_pkth, p_vh, nullptr);            // 4

    // ---- TC kvsum (pipelined) + reduce ----
    kvsum_tc<<<dim3(NCHUNK, BH), 256>>>(p_pkth, p_vh, p_kvtp, p_ksp);          // 5
    int red_total = BH * HDIM * RR + BH * RR;
    reduce2<<<(red_total + 255) / 256, 256>>>(p_kvtp, p_ksp, p_kvth, p_ks);

    // ---- TC attention output (256 rows/CTA, fp16 out) ----
    attn_tc<<<dim3(SS / 256, BH), 256>>>(p_pqh, p_kvth, p_ks, p_ahi);

    // ---- output projection (1-pass fp16, fp32 out) ----
    dim3 go(2, BSROWS / 128);
    mma_gemm<<<go, 256, GEMM_SMEM>>>(p_ahi, nullptr, p_wth + 1536 * DD, bp,
                                     nullptr, nullptr, nullptr, out);
}

// round 14
// speedup vs baseline: 2.0400x; 1.0317x over previous
#include <cuda_runtime.h>
#include <cuda_fp16.h>
#include <cstdint>

// Problem constants
#define BB 4
#define SS 8192
#define DD 512
#define HH 8
#define HDIM 64
#define RR 64
#define BSROWS (BB * SS)      // 32768
#define BH (BB * HH)          // 32
#define NCHUNK 16

// -------- scratch (static device globals; no allocation) --------
__device__ __half g_xhi[BSROWS * DD];
__device__ __half g_xlo[BSROWS * DD];
__device__ __half g_vh[BSROWS * DD];
__device__ __half g_ahi[BSROWS * DD];
__device__ __half g_wth[4 * DD * DD];     // fp16 transposed weights
__device__ float g_biasqkv[3 * DD];
__device__ __half g_gint_hi[2][128 * 64];
__device__ __half g_gint_lo[2][128 * 64];
__device__ __half g_pqh[BH * SS * RR];    // phiq [bh][s][r], fp16 hi only
__device__ __half g_pkth[BH * RR * SS];   // phikT [bh][r][s], fp16 hi only
__device__ float g_kvtp[BH * NCHUNK * HDIM * RR];
__device__ float g_ksp[BH * NCHUNK * RR];
__device__ __half g_kvth[BH * HDIM * RR];
__device__ float g_ks[BH * RR];

// ============================================================
// helpers
// ============================================================
__device__ __forceinline__ uint32_t smem_to_u32(const void* p) {
    uint32_t a;
    asm("{ .reg .u64 t; cvta.to.shared.u64 t, %1; cvt.u32.u64 %0, t; }"
        : "=r"(a) : "l"(p));
    return a;
}
__device__ __forceinline__ void ldsm4(uint32_t& r0, uint32_t& r1,
                                      uint32_t& r2, uint32_t& r3,
                                      uint32_t addr) {
    asm volatile("ldmatrix.sync.aligned.m8n8.x4.shared.b16 {%0,%1,%2,%3}, [%4];"
                 : "=r"(r0), "=r"(r1), "=r"(r2), "=r"(r3) : "r"(addr));
}
__device__ __forceinline__ void ldsm4t(uint32_t& r0, uint32_t& r1,
                                       uint32_t& r2, uint32_t& r3,
                                       uint32_t addr) {
    asm volatile("ldmatrix.sync.aligned.m8n8.x4.trans.shared.b16 {%0,%1,%2,%3}, [%4];"
                 : "=r"(r0), "=r"(r1), "=r"(r2), "=r"(r3) : "r"(addr));
}
__device__ __forceinline__ void mma16816(float* d, const uint32_t* a,
                                         const uint32_t* b) {
    asm volatile(
        "mma.sync.aligned.m16n8k16.row.col.f32.f16.f16.f32 "
        "{%0,%1,%2,%3}, {%4,%5,%6,%7}, {%8,%9}, {%0,%1,%2,%3};"
        : "+f"(d[0]), "+f"(d[1]), "+f"(d[2]), "+f"(d[3])
        : "r"(a[0]), "r"(a[1]), "r"(a[2]), "r"(a[3]), "r"(b[0]), "r"(b[1]));
}
#define CP_ASYNC16(dst, src) \
    asm volatile("cp.async.cg.shared.global [%0], [%1], 16;" :: "r"(dst), "l"(src))
#define CP_COMMIT() asm volatile("cp.async.commit_group;" ::: "memory")
#define CP_WAIT(n)  asm volatile("cp.async.wait_group %0;" :: "n"(n) : "memory")

__device__ __forceinline__ void split4h(float4 v, uint2& hi, uint2& lo) {
    __half h0 = __float2half_rn(v.x), h1 = __float2half_rn(v.y);
    __half h2 = __float2half_rn(v.z), h3 = __float2half_rn(v.w);
    float r0 = v.x - __half2float(h0), r1 = v.y - __half2float(h1);
    float r2 = v.z - __half2float(h2), r3 = v.w - __half2float(h3);
    __half l0 = __float2half_rn(r0), l1 = __float2half_rn(r1);
    __half l2 = __float2half_rn(r2), l3 = __float2half_rn(r3);
    hi.x = ((uint32_t)__half_as_ushort(h1) << 16) | __half_as_ushort(h0);
    hi.y = ((uint32_t)__half_as_ushort(h3) << 16) | __half_as_ushort(h2);
    lo.x = ((uint32_t)__half_as_ushort(l1) << 16) | __half_as_ushort(l0);
    lo.y = ((uint32_t)__half_as_ushort(l3) << 16) | __half_as_ushort(l2);
}
__device__ __forceinline__ void split2h(float a, float b, uint32_t& hp, uint32_t& lp) {
    __half h0 = __float2half_rn(a), h1 = __float2half_rn(b);
    float l0 = a - __half2float(h0), l1 = b - __half2float(h1);
    __half e0 = __float2half_rn(l0), e1 = __float2half_rn(l1);
    hp = ((uint32_t)__half_as_ushort(h1) << 16) | __half_as_ushort(h0);
    lp = ((uint32_t)__half_as_ushort(e1) << 16) | __half_as_ushort(e0);
}
__device__ __forceinline__ uint32_t pack2h(float a, float b) {
    __half h0 = __float2half_rn(a), h1 = __float2half_rn(b);
    return ((uint32_t)__half_as_ushort(h1) << 16) | __half_as_ushort(h0);
}

// ============================================================
// prep kernels
// ============================================================
__global__ __launch_bounds__(256) void split_fp32(
    const float* __restrict__ X, __half* __restrict__ Xh,
    __half* __restrict__ Xl)
{
    int i = blockIdx.x * 256 + threadIdx.x;
    float4 v = ((const float4*)X)[i];
    uint2 hi, lo;
    split4h(v, hi, lo);
    ((uint2*)Xh)[i] = hi;
    ((uint2*)Xl)[i] = lo;
}

__global__ __launch_bounds__(256) void transpose_h4(
    const float* __restrict__ Wq, const float* __restrict__ Wk,
    const float* __restrict__ Wv, const float* __restrict__ Wp,
    const float* __restrict__ gq, const float* __restrict__ gk,
    __half* __restrict__ Th)
{
    __shared__ float t[32][33];
    const int z = blockIdx.z;
    const float* W = z == 0 ? Wq : (z == 1 ? Wk : (z == 2 ? Wv : Wp));
    const float scale = z == 0 ? gq[0] : (z == 1 ? gk[0] : 1.0f);
    const int rowoff = z * DD;
    int bx = blockIdx.x * 32, by = blockIdx.y * 32;
    int x = threadIdx.x & 31, y = threadIdx.x >> 5;
    for (int i = y; i < 32; i += 8) t[i][x] = W[(size_t)(by + i) * DD + bx + x];
    __syncthreads();
    for (int i = y; i < 32; i += 8)
        Th[(size_t)(rowoff + bx + i) * DD + by + x] = __float2half_rn(t[x][i] * scale);
}

__global__ __launch_bounds__(256) void misc_prep(
    const float* __restrict__ qG1, const float* __restrict__ qG2,
    const float* __restrict__ kG1, const float* __restrict__ kG2,
    const float* bq, const float* bk, const float* bv,
    const float* gq, const float* betq,
    const float* gk, const float* betk,
    float* bout)
{
    const int blk = blockIdx.x;
    if (blk < 2) {
        const int set = blk;
        const float* G1 = set ? kG1 : qG1;
        const float* G2 = set ? kG2 : qG2;
        __half* Oh = g_gint_hi[set];
        __half* Ol = g_gint_lo[set];
        for (int it = 0; it < 32; it++) {
            int idx = it * 256 + threadIdx.x;
            int n = idx >> 6, k = idx & 63;
            float v = ((n & 1) ? G2 : G1)[k * 64 + (n >> 1)];
            __half h = __float2half_rn(v);
            Oh[idx] = h;
            Ol[idx] = __float2half_rn(v - __half2float(h));
        }
    } else {
        int i = (blk - 2) * 256 + threadIdx.x;
        if (i < DD) bout[i] = gq[0] * bq[i] + betq[0];
        else if (i < 2 * DD) bout[i] = gk[0] * bk[i - DD] + betk[0];
        else if (i < 3 * DD) bout[i] = bv[i - 2 * DD];
    }
}

// ============================================================
// fp16 split GEMM + fused sketch epilogue.
// 512 threads, 16 warps (4m x 4n), warp tile 32x64, CTA 128x256.
// ============================================================
#define BKC 32
#define NKCH (DD / BKC)          // 16
#define ROWB 80
#define TILE_A (128 * ROWB)      // 10240
#define TILE_B (256 * ROWB)      // 20480
#define ST_AHI 0
#define ST_ALO TILE_A
#define ST_BH (2 * TILE_A)
#define STAGEB (2 * TILE_A + TILE_B)   // 40960
#define PIPE 4
#define OFF80(row, ch) ((uint32_t)((row) * ROWB + ((ch) << 4)))
#define FZ_HEAD 36864
#define FZ_LO 18432
#define FG_OFF (4 * FZ_HEAD)
#define FG_LO 18432
#define GEMM_SMEM (FG_OFF + 2 * FG_LO)   // 184320
#define SOFF144(row, ch) ((uint32_t)((row) * 144 + ((ch) << 4)))

__global__ __launch_bounds__(512, 1) void mma_gemm(
    const __half* __restrict__ Ahi, const __half* __restrict__ Alo,
    const __half* __restrict__ Bh, const float* __restrict__ bias,
    __half* __restrict__ pqh, __half* __restrict__ pkth,
    __half* __restrict__ vh, float* __restrict__ ofp32)
{
    extern __shared__ char smem[];
    const uint32_t sb = smem_to_u32(smem);

    const int tid = threadIdx.x;
    const int wid = tid >> 5, lane = tid & 31;
    const int bn = blockIdx.x, bm = blockIdx.y;
    const int warp_m = wid & 3, warp_n = wid >> 2;
    const bool useAlo = (Alo != nullptr) && (bn < 4);

    const __half* Ahi_b = Ahi + (size_t)bm * 128 * DD;
    const __half* Alo_b = useAlo ? Alo + (size_t)bm * 128 * DD : Ahi_b;
    const __half* Bh_b = Bh + (size_t)bn * 256 * DD;

    const int lrow = tid >> 2;    // 0..127
    const int lch = tid & 3;

    auto load_chunk = [&](int c, int s) {
        const uint32_t stg = sb + s * STAGEB;
        const int k0 = c * BKC;
        {
            const size_t go = (size_t)lrow * DD + k0 + lch * 8;
            const uint32_t so = OFF80(lrow, lch);
            CP_ASYNC16(stg + ST_AHI + so, Ahi_b + go);
            if (useAlo) CP_ASYNC16(stg + ST_ALO + so, Alo_b + go);
        }
#pragma unroll
        for (int sw = 0; sw < 2; sw++) {
            const int row = sw * 128 + lrow;
            const size_t go = (size_t)row * DD + k0 + lch * 8;
            CP_ASYNC16(stg + ST_BH + OFF80(row, lch), Bh_b + go);
        }
    };

    float acc[2][8][4];
#pragma unroll
    for (int i = 0; i < 2; i++)
#pragma unroll
        for (int j = 0; j < 8; j++)
#pragma unroll
            for (int e = 0; e < 4; e++) acc[i][j][e] = 0.f;

    const int mat = lane >> 3, mr = lane & 7;
    const int a_row_b = warp_m * 32 + (mat & 1) * 8 + mr;
    const int b_row_b = warp_n * 64 + (mat & 1) * 8 + mr;
    const int mchunk = mat >> 1;

    load_chunk(0, 0); CP_COMMIT();
    load_chunk(1, 1); CP_COMMIT();
    load_chunk(2, 2); CP_COMMIT();

    for (int c = 0; c < NKCH; c++) {
        CP_WAIT(2);
        __syncthreads();
        if (c + 3 < NKCH) load_chunk(c + 3, (c + 3) % PIPE);
        CP_COMMIT();

        const uint32_t stg = sb + (c % PIPE) * STAGEB;
#pragma unroll
        for (int kk = 0; kk < 2; kk++) {
            const int ch = kk * 2 + mchunk;
            uint32_t ahi[2][4], alo[2][4];
#pragma unroll
            for (int im = 0; im < 2; im++) {
                const int row = a_row_b + im * 16;
                ldsm4(ahi[im][0], ahi[im][1], ahi[im][2], ahi[im][3],
                      stg + ST_AHI + OFF80(row, ch));
                if (useAlo)
                    ldsm4(alo[im][0], alo[im][1], alo[im][2], alo[im][3],
                          stg + ST_ALO + OFF80(row, ch));
            }
#pragma unroll
            for (int j16 = 0; j16 < 4; j16++) {
                const int row = b_row_b + j16 * 16;
                uint32_t h0, h1, h2, h3;
                ldsm4(h0, h1, h2, h3, stg + ST_BH + OFF80(row, ch));
                uint32_t bh0[2] = {h0, h2}, bh1[2] = {h1, h3};
#pragma unroll
                for (int im = 0; im < 2; im++) {
                    mma16816(acc[im][j16 * 2], ahi[im], bh0);
                    mma16816(acc[im][j16 * 2 + 1], ahi[im], bh1);
                    if (useAlo) {
                        mma16816(acc[im][j16 * 2], alo[im], bh0);
                        mma16816(acc[im][j16 * 2 + 1], alo[im], bh1);
                    }
                }
            }
        }
    }

    const int erow = lane >> 2, ecol = (lane & 3) * 2;

    if (ofp32) {
        const int colbase = bn * 256;
#pragma unroll
        for (int im = 0; im < 2; im++) {
            const size_t row0 = (size_t)bm * 128 + warp_m * 32 + im * 16 + erow;
#pragma unroll
            for (int t = 0; t < 8; t++) {
                const int cofs = warp_n * 64 + t * 8 + ecol;
                float2 b2 = *(const float2*)&bias[colbase + cofs];
                float2 q0 = make_float2(acc[im][t][0] + b2.x, acc[im][t][1] + b2.y);
                float2 q1 = make_float2(acc[im][t][2] + b2.x, acc[im][t][3] + b2.y);
                *(float2*)&ofp32[row0 * DD + colbase + cofs] = q0;
                *(float2*)&ofp32[(row0 + 8) * DD + colbase + cofs] = q1;
            }
        }
        return;
    }

    const int sel = bn >> 1;
    if (sel == 2) {
        const int colbase = (bn & 1) * 256;
#pragma unroll
        for (int im = 0; im < 2; im++) {
            const size_t row0 = (size_t)bm * 128 + warp_m * 32 + im * 16 + erow;
#pragma unroll
            for (int t = 0; t < 8; t++) {
                const int cofs = warp_n * 64 + t * 8 + ecol;
                float2 b2 = *(const float2*)&bias[bn * 256 + cofs];
                *(uint32_t*)(vh + row0 * DD + colbase + cofs) =
                    pack2h(acc[im][t][0] + b2.x, acc[im][t][1] + b2.y);
                *(uint32_t*)(vh + (row0 + 8) * DD + colbase + cofs) =
                    pack2h(acc[im][t][2] + b2.x, acc[im][t][3] + b2.y);
            }
        }
        return;
    }

    // ---- fused sketch epilogue (sel 0 = q, 1 = k) ----
    CP_WAIT(0);
    __syncthreads();

    // stage z = acc + bias as fp16 hi/lo, per head (4 heads per CTA tile)
#pragma unroll
    for (int im = 0; im < 2; im++) {
        const int row = warp_m * 32 + im * 16 + erow;
#pragma unroll
        for (int t = 0; t < 8; t++) {
            const int cofs = warp_n * 64 + t * 8 + ecol;
            const int head = cofs >> 6, c = cofs & 63;
            float2 b2 = *(const float2*)&bias[bn * 256 + cofs];
            uint32_t hp, lp;
            split2h(acc[im][t][0] + b2.x, acc[im][t][1] + b2.y, hp, lp);
            *(uint32_t*)(smem + head * FZ_HEAD + row * 144 + c * 2) = hp;
            *(uint32_t*)(smem + head * FZ_HEAD + FZ_LO + row * 144 + c * 2) = lp;
            split2h(acc[im][t][2] + b2.x, acc[im][t][3] + b2.y, hp, lp);
            *(uint32_t*)(smem + head * FZ_HEAD + (row + 8) * 144 + c * 2) = hp;
            *(uint32_t*)(smem + head * FZ_HEAD + FZ_LO + (row + 8) * 144 + c * 2) = lp;
        }
    }
    // load G-int (hi/lo)
    {
        const __half* Gh = &g_gint_hi[sel][0];
        const __half* Gl = &g_gint_lo[sel][0];
#pragma unroll
        for (int it = 0; it < 2; it++) {
            const int cidx = it * 512 + tid;
            const int row = cidx >> 3, ch = cidx & 7;
            *(uint4*)(smem + FG_OFF + SOFF144(row, ch)) =
                *(const uint4*)((const char*)Gh + row * 128 + ch * 16);
            *(uint4*)(smem + FG_OFF + FG_LO + SOFF144(row, ch)) =
                *(const uint4*)((const char*)Gl + row * 128 + ch * 16);
        }
    }
    __syncthreads();

    // sketch warp mapping: 4m x 4n, warp tile 32x32
    const int swm = wid & 3, swn = wid >> 2;
    const int a_row_s = swm * 32 + (mat & 1) * 8 + mr;
    const int b_row_s = swn * 32 + (mat & 1) * 8 + mr;
    const int b = bm >> 6;
    const int sbase = (bm & 63) * 128;
    const int g = lane >> 2, t4 = lane & 3;
    const float inv = 0.125f;

    for (int hd = 0; hd < 4; hd++) {
        const uint32_t zb = sb + hd * FZ_HEAD;

        float sk[2][4][4];
#pragma unroll
        for (int i = 0; i < 2; i++)
#pragma unroll
            for (int j = 0; j < 4; j++)
#pragma unroll
                for (int e = 0; e < 4; e++) sk[i][j][e] = 0.f;

#pragma unroll
        for (int kk = 0; kk < 4; kk++) {
            const int ch = kk * 2 + mchunk;
            uint32_t zhi[2][4], zlo[2][4];
#pragma unroll
            for (int im = 0; im < 2; im++) {
                const int row = a_row_s + im * 16;
                ldsm4(zhi[im][0], zhi[im][1], zhi[im][2], zhi[im][3],
                      zb + SOFF144(row, ch));
                ldsm4(zlo[im][0], zlo[im][1], zlo[im][2], zlo[im][3],
                      zb + FZ_LO + SOFF144(row, ch));
            }
#pragma unroll
            for (int j16 = 0; j16 < 2; j16++) {
                const int row = b_row_s + j16 * 16;
                uint32_t h0, h1, h2, h3, l0, l1, l2, l3;
                ldsm4(h0, h1, h2, h3, sb + FG_OFF + SOFF144(row, ch));
                ldsm4(l0, l1, l2, l3, sb + FG_OFF + FG_LO + SOFF144(row, ch));
                uint32_t gh0[2] = {h0, h2}, gh1[2] = {h1, h3};
                uint32_t gl0[2] = {l0, l2}, gl1[2] = {l1, l3};
#pragma unroll
                for (int im = 0; im < 2; im++) {
                    mma16816(sk[im][j16 * 2], zhi[im], gh0);
                    mma16816(sk[im][j16 * 2], zhi[im], gl0);
                    mma16816(sk[im][j16 * 2], zlo[im], gh0);
                    mma16816(sk[im][j16 * 2 + 1], zhi[im], gh1);
                    mma16816(sk[im][j16 * 2 + 1], zhi[im], gl1);
                    mma16816(sk[im][j16 * 2 + 1], zlo[im], gh1);
                }
            }
        }

        const int h = (bn & 1) * 4 + hd;
        const int bh2 = b * HH + h;
        __syncthreads();   // all warps done reading z[hd]; reuse for staging

        __half* SH = (__half*)(smem + hd * FZ_HEAD);
        if (sel == 0) {
            // stage phiq hi [128][72]
#pragma unroll
            for (int im = 0; im < 2; im++) {
                const int s0 = swm * 32 + im * 16 + g;
#pragma unroll
                for (int jn = 0; jn < 4; jn++) {
                    const int r = swn * 16 + jn * 4 + t4;
                    float h0 = inv * sk[im][jn][0] * sk[im][jn][1];
                    float h1 = inv * sk[im][jn][2] * sk[im][jn][3];
                    SH[s0 * 72 + r] = __float2half_rn(h0 * h0);
                    SH[(s0 + 8) * 72 + r] = __float2half_rn(h1 * h1);
                }
            }
            __syncthreads();
            const int row = tid >> 2, q4 = tid & 3;
            size_t gbase = ((size_t)bh2 * SS + sbase + row) * RR + q4 * 16;
            const uint4* srcH = (const uint4*)(smem + hd * FZ_HEAD + row * 144 + q4 * 32);
            ((uint4*)(pqh + gbase))[0] = srcH[0];
            ((uint4*)(pqh + gbase))[1] = srcH[1];
        } else {
            // stage phikT hi [64 r][136 s]
#pragma unroll
            for (int im = 0; im < 2; im++) {
                const int s0 = swm * 32 + im * 16 + g;
#pragma unroll
                for (int jn = 0; jn < 4; jn++) {
                    const int r = swn * 16 + jn * 4 + t4;
                    float h0 = inv * sk[im][jn][0] * sk[im][jn][1];
                    float h1 = inv * sk[im][jn][2] * sk[im][jn][3];
                    SH[r * 136 + s0] = __float2half_rn(h0 * h0);
                    SH[r * 136 + s0 + 8] = __float2half_rn(h1 * h1);
                }
            }
            __syncthreads();
            const int r = tid >> 3, q8 = tid & 7;
            size_t gbase = ((size_t)bh2 * RR + r) * SS + sbase + q8 * 16;
            const uint4* srcH = (const uint4*)(smem + hd * FZ_HEAD + r * 272 + q8 * 32);
            ((uint4*)(pkth + gbase))[0] = srcH[0];
            ((uint4*)(pkth + gbase))[1] = srcH[1];
        }
    }
}

// ============================================================
// TC kvsum (1-pass, cp.async double-buffered steps)
// ============================================================
#define KV_STG 18432
#define KV_VHI 0
#define KV_PKH 9216

__global__ __launch_bounds__(256) void kvsum_tc(
    const __half* __restrict__ pkth, const __half* __restrict__ vh,
    float* __restrict__ kvtp, float* __restrict__ ksp)
{
    __shared__ __align__(16) char sm[2 * KV_STG];   // 36864
    const uint32_t sb = smem_to_u32(sm);

    const int tid = threadIdx.x;
    const int wid = tid >> 5, lane = tid & 31;
    const int chunk = blockIdx.x, bh = blockIdx.y;
    const int b = bh >> 3, h = bh & 7;
    const int warp_m = wid & 1, warp_n = wid >> 1;
    const int mat = lane >> 3, mr = lane & 7;
    const int g = lane >> 2, t = lane & 3;

    float acc[2][2][4];
#pragma unroll
    for (int i = 0; i < 2; i++)
#pragma unroll
        for (int j = 0; j < 2; j++)
#pragma unroll
            for (int e = 0; e < 4; e++) acc[i][j][e] = 0.f;
    float kacc = 0.f;

    const int lr = tid >> 2, lq = tid & 3;
    const int kr = tid & 63, kg = tid >> 6;

    auto load_step = [&](int step, int s) {
        const uint32_t stg = sb + s * KV_STG;
        const int s0 = chunk * 512 + step * 64;
        const size_t vo = (size_t)(b * SS + s0 + lr) * DD + h * HDIM + lq * 16;
        CP_ASYNC16(stg + KV_VHI + lr * 144 + lq * 32, vh + vo);
        CP_ASYNC16(stg + KV_VHI + lr * 144 + lq * 32 + 16, vh + vo + 8);
        const size_t po = ((size_t)bh * RR + lr) * SS + s0 + lq * 16;
        CP_ASYNC16(stg + KV_PKH + lr * 144 + lq * 32, pkth + po);
        CP_ASYNC16(stg + KV_PKH + lr * 144 + lq * 32 + 16, pkth + po + 8);
    };

    load_step(0, 0);
    CP_COMMIT();

    for (int step = 0; step < 8; step++) {
        if (step + 1 < 8) load_step(step + 1, (step + 1) & 1);
        CP_COMMIT();
        CP_WAIT(1);
        __syncthreads();

        const uint32_t stg = sb + (step & 1) * KV_STG;

#pragma unroll
        for (int c = 0; c < 16; c++) {
            int sc = kg * 16 + c;
            kacc += __half2float(*(__half*)((char*)sm + (step & 1) * KV_STG +
                                            KV_PKH + kr * 144 + sc * 2));
        }

#pragma unroll
        for (int kk = 0; kk < 4; kk++) {
            uint32_t ah[2][4];
#pragma unroll
            for (int im = 0; im < 2; im++) {
                const int d0 = warp_m * 32 + im * 16 + (mat & 1) * 8;
                const int srow = kk * 16 + ((mat >> 1) & 1) * 8 + mr;
                ldsm4t(ah[im][0], ah[im][1], ah[im][2], ah[im][3],
                       stg + KV_VHI + srow * 144 + d0 * 2);
            }
            const int rrow = warp_n * 16 + (mat & 1) * 8 + mr;
            const int chb = kk * 2 + (mat >> 1);
            uint32_t h0, h1, h2, h3;
            ldsm4(h0, h1, h2, h3, stg + KV_PKH + rrow * 144 + chb * 16);
            uint32_t bh0[2] = {h0, h2}, bh1[2] = {h1, h3};
#pragma unroll
            for (int im = 0; im < 2; im++) {
                mma16816(acc[im][0], ah[im], bh0);
                mma16816(acc[im][1], ah[im], bh1);
            }
        }
        __syncthreads();
    }

    float* outp = kvtp + ((size_t)bh * NCHUNK + chunk) * (HDIM * RR);
#pragma unroll
    for (int im = 0; im < 2; im++) {
        const int d = warp_m * 32 + im * 16 + g;
#pragma unroll
        for (int nb = 0; nb < 2; nb++) {
            const int r = warp_n * 16 + nb * 8 + t * 2;
            *(float2*)&outp[d * RR + r] =
                make_float2(acc[im][nb][0], acc[im][nb][1]);
            *(float2*)&outp[(d + 8) * RR + r] =
                make_float2(acc[im][nb][2], acc[im][nb][3]);
        }
    }
    __syncthreads();
    float* red = (float*)sm;
    red[kg * 64 + kr] = kacc;
    __syncthreads();
    if (tid < 64)
        ksp[((size_t)bh * NCHUNK + chunk) * RR + tid] =
            red[tid] + red[64 + tid] + red[128 + tid] + red[192 + tid];
}

__global__ void reduce2(const float* __restrict__ kvtp,
                        const float* __restrict__ ksp,
                        __half* __restrict__ kvth, float* __restrict__ ks)
{
    const int idx = blockIdx.x * 256 + threadIdx.x;
    const int total = BH * HDIM * RR;
    if (idx < total) {
        int bh = idx >> 12, e = idx & 4095;
        float s = 0.f;
#pragma unroll
        for (int c = 0; c < NCHUNK; c++)
            s += kvtp[((size_t)bh * NCHUNK + c) * 4096 + e];
        kvth[idx] = __float2half_rn(s);
    } else if (idx < total + BH * RR) {
        int j = idx - total;
        int bh = j >> 6, r = j & 63;
        float s = 0.f;
#pragma unroll
        for (int c = 0; c < NCHUNK; c++)
            s += ksp[((size_t)bh * NCHUNK + c) * RR + r];
        ks[j] = s;
    }
}

// ============================================================
// TC attn: 256 s-rows per CTA, one kv load, two MMA halves.
// ============================================================
#define AT_PQH 0
#define AT_KVH (256 * 144)                 // 36864
#define AT_KS  (AT_KVH + 64 * 144)         // + 9216
#define AT_DEN (AT_KS + 256)
#define AT_SMEM (AT_DEN + 1024)            // 47360

__global__ __launch_bounds__(256) void attn_tc(
    const __half* __restrict__ pqh, const __half* __restrict__ kvth,
    const float* __restrict__ ks,
    __half* __restrict__ ahi)
{
    __shared__ __align__(16) char sm[AT_SMEM];
    const uint32_t sb = smem_to_u32(sm);
    const int tid = threadIdx.x;
    const int wid = tid >> 5, lane = tid & 31;
    const int stile = blockIdx.x, bh = blockIdx.y;
    const int b = bh >> 3, h = bh & 7;
    const int sbase = stile * 256;
    const int warp_m = wid >> 1, warp_n = wid & 1;

    {
        const int row = tid;
        size_t gbase = ((size_t)bh * SS + sbase + row) * RR;
        uint4* dst = (uint4*)(sm + AT_PQH + row * 144);
#pragma unroll
        for (int i = 0; i < 8; i++) dst[i] = ((const uint4*)(pqh + gbase))[i];
    }
    {
        const int row = tid >> 2, q4 = tid & 3;
        size_t gbase = (size_t)bh * (HDIM * RR) + row * RR + q4 * 16;
        *(uint4*)(sm + AT_KVH + row * 144 + q4 * 32) = *(const uint4*)(kvth + gbase);
        *(uint4*)(sm + AT_KVH + row * 144 + q4 * 32 + 16) = *(const uint4*)(kvth + gbase + 8);
    }
    if (tid < 64) ((float*)(sm + AT_KS))[tid] = ks[bh * RR + tid];
    __syncthreads();

    {
        float d = 1e-6f;
        const float* kss = (const float*)(sm + AT_KS);
#pragma unroll 16
        for (int r = 0; r < 64; r++) {
            float p = __half2float(*(__half*)(sm + AT_PQH + tid * 144 + r * 2));
            d += p * kss[r];
        }
        ((float*)(sm + AT_DEN))[tid] = 1.0f / d;
    }
    __syncthreads();

    const int mat = lane >> 3, mr = lane & 7;
    const int b_row_b = warp_n * 32 + (mat & 1) * 8 + mr;
    const int mchunk = mat >> 1;
    const int g = lane >> 2, t = lane & 3;
    const float* rden = (const float*)(sm + AT_DEN);

#pragma unroll
    for (int half = 0; half < 2; half++) {
        const int hbase = half * 128;
        const int a_row_b = hbase + warp_m * 32 + (mat & 1) * 8 + mr;

        float acc[2][4][4];
#pragma unroll
        for (int i = 0; i < 2; i++)
#pragma unroll
            for (int j = 0; j < 4; j++)
#pragma unroll
                for (int e = 0; e < 4; e++) acc[i][j][e] = 0.f;

#pragma unroll
        for (int kk = 0; kk < 4; kk++) {
            const int ch = kk * 2 + mchunk;
            uint32_t ah[2][4];
#pragma unroll
            for (int im = 0; im < 2; im++) {
                const int row = a_row_b + im * 16;
                ldsm4(ah[im][0], ah[im][1], ah[im][2], ah[im][3],
                      sb + AT_PQH + row * 144 + ch * 16);
            }
#pragma unroll
            for (int nt = 0; nt < 2; nt++) {
                const int row = b_row_b + nt * 16;
                uint32_t h0, h1, h2, h3;
                ldsm4(h0, h1, h2, h3, sb + AT_KVH + row * 144 + ch * 16);
                uint32_t bh0[2] = {h0, h2}, bh1[2] = {h1, h3};
#pragma unroll
                for (int im = 0; im < 2; im++) {
                    mma16816(acc[im][nt * 2], ah[im], bh0);
                    mma16816(acc[im][nt * 2 + 1], ah[im], bh1);
                }
            }
        }

#pragma unroll
        for (int im = 0; im < 2; im++) {
            const int s0 = hbase + warp_m * 32 + im * 16 + g;
            const float rd0 = rden[s0], rd1 = rden[s0 + 8];
            const size_t row0 = ((size_t)b * SS + sbase + s0) * DD + h * HDIM;
            const size_t row1 = row0 + 8 * DD;
#pragma unroll
            for (int j8 = 0; j8 < 4; j8++) {
                const int d = warp_n * 32 + j8 * 8 + t * 2;
                *(uint32_t*)(ahi + row0 + d) =
                    pack2h(acc[im][j8][0] * rd0, acc[im][j8][1] * rd0);
                *(uint32_t*)(ahi + row1 + d) =
                    pack2h(acc[im][j8][2] * rd1, acc[im][j8][3] * rd1);
            }
        }
    }
}

// ============================================================
// launch
// ============================================================
extern "C" void kernel_launch(void* const* d_in, const int* in_sizes, int n_in,
                              void* d_out, int out_size)
{
    const float* x       = (const float*)d_in[0];
    const float* Wq      = (const float*)d_in[1];
    const float* bq      = (const float*)d_in[2];
    const float* Wk      = (const float*)d_in[3];
    const float* bk      = (const float*)d_in[4];
    const float* Wv      = (const float*)d_in[5];
    const float* bv      = (const float*)d_in[6];
    const float* Wp      = (const float*)d_in[7];
    const float* bp      = (const float*)d_in[8];
    const float* gamma_q = (const float*)d_in[9];
    const float* beta_q  = (const float*)d_in[10];
    const float* gamma_k = (const float*)d_in[11];
    const float* beta_k  = (const float*)d_in[12];
    const float* qG1     = (const float*)d_in[13];
    const float* qG2     = (const float*)d_in[14];
    const float* kG1     = (const float*)d_in[15];
    const float* kG2     = (const float*)d_in[16];
    float* out = (float*)d_out;

    float *p_bqkv, *p_kvtp, *p_ksp, *p_ks;
    __half *p_xhi, *p_xlo, *p_vh, *p_ahi, *p_wth;
    __half *p_pqh, *p_pkth, *p_kvth;
    cudaGetSymbolAddress((void**)&p_xhi, g_xhi);
    cudaGetSymbolAddress((void**)&p_xlo, g_xlo);
    cudaGetSymbolAddress((void**)&p_vh, g_vh);
    cudaGetSymbolAddress((void**)&p_ahi, g_ahi);
    cudaGetSymbolAddress((void**)&p_wth, g_wth);
    cudaGetSymbolAddress((void**)&p_bqkv, g_biasqkv);
    cudaGetSymbolAddress((void**)&p_pqh, g_pqh);
    cudaGetSymbolAddress((void**)&p_pkth, g_pkth);
    cudaGetSymbolAddress((void**)&p_kvtp, g_kvtp);
    cudaGetSymbolAddress((void**)&p_ksp, g_ksp);
    cudaGetSymbolAddress((void**)&p_kvth, g_kvth);
    cudaGetSymbolAddress((void**)&p_ks, g_ks);

    cudaFuncSetAttribute(mma_gemm, cudaFuncAttributeMaxDynamicSharedMemorySize,
                         GEMM_SMEM);

    // ---- prep (3 launches) ----
    split_fp32<<<BSROWS * DD / 4 / 256, 256>>>(x, p_xhi, p_xlo);               // 1
    misc_prep<<<8, 256>>>(qG1, qG2, kG1, kG2, bq, bk, bv,
                          gamma_q, beta_q, gamma_k, beta_k, p_bqkv);           // 2
    transpose_h4<<<dim3(16, 16, 4), 256>>>(Wq, Wk, Wv, Wp,
                                           gamma_q, gamma_k, p_wth);           // 3

    // ---- fused QKV GEMM + sketch (512 threads, 16 warps) ----
    dim3 gq(6, BSROWS / 128);
    mma_gemm<<<gq, 512, GEMM_SMEM>>>(p_xhi, p_xlo, p_wth, p_bqkv,
                                     p_pqh, p_pkth, p_vh, nullptr);            // 4

    // ---- TC kvsum (pipelined) + reduce ----
    kvsum_tc<<<dim3(NCHUNK, BH), 256>>>(p_pkth, p_vh, p_kvtp, p_ksp);          // 5
    int red_total = BH * HDIM * RR + BH * RR;
    reduce2<<<(red_total + 255) / 256, 256>>>(p_kvtp, p_ksp, p_kvth, p_ks);

    // ---- TC attention output (256 rows/CTA, fp16 out) ----
    attn_tc<<<dim3(SS / 256, BH), 256>>>(p_pqh, p_kvth, p_ks, p_ahi);

    // ---- output projection (1-pass fp16, fp32 out) ----
    dim3 go(2, BSROWS / 128);
    mma_gemm<<<go, 512, GEMM_SMEM>>>(p_ahi, nullptr, p_wth + 1536 * DD, bp,
                                     nullptr, nullptr, nullptr, out);
}